// round 11
// baseline (speedup 1.0000x reference)
#include <cuda_runtime.h>
#include <cstdint>
#include <math.h>

typedef unsigned int u32;

// Problem constants
#define B_  16
#define N_  1024
#define C_  256
#define NH_ 8
#define DH_ 32
#define M_  (B_*N_)      // 16384 rows
#define HID_ 1024

// Weight segment sizes (floats)
#define WSZ_QKV   (3*C_*C_)
#define WSZ_PROJ  (C_*C_)
#define WSZ_OFF   (64*C_)
#define WSZ_AW    (32*C_)
#define WSZ_VPROJ (C_*C_)
#define WSZ_OPROJ (C_*C_)
#define WSZ_FC1   (HID_*C_)
#define WSZ_FC2   (C_*HID_)
#define WOFF_QKV   0
#define WOFF_PROJ  (WOFF_QKV  + WSZ_QKV)
#define WOFF_OFF   (WOFF_PROJ + WSZ_PROJ)
#define WOFF_AW    (WOFF_OFF  + WSZ_OFF)
#define WOFF_VPROJ (WOFF_AW   + WSZ_AW)
#define WOFF_OPROJ (WOFF_VPROJ+ WSZ_VPROJ)
#define WOFF_FC1   (WOFF_OPROJ+ WSZ_OPROJ)
#define WOFF_FC2   (WOFF_FC1  + WSZ_FC1)
#define WTOT       (WOFF_FC2  + WSZ_FC2)   // 942080

// ---------------------------------------------------------------------------
// Scratch (static __device__ arrays; no allocations allowed)
// ---------------------------------------------------------------------------
__device__ float g_y  [M_*C_];
__device__ float g_qkv[M_*3*C_];
__device__ float g_tmp[M_*C_];
__device__ float g_x2 [M_*C_];
__device__ float g_off[M_*64];
__device__ float g_awl[M_*32];
__device__ float g_vp [M_*C_];
__device__ float g_h1 [M_*HID_];
__device__ float g_w  [WTOT];      // tf32-rounded weights
__device__ float g_val[M_*C_];     // tf32-rounded value input

// ---------------------------------------------------------------------------
// helpers
// ---------------------------------------------------------------------------
__device__ __forceinline__ float tf32r(float x) {
    u32 u;
    asm("cvt.rna.tf32.f32 %0, %1;" : "=r"(u) : "f"(x));
    return __uint_as_float(u);
}

__device__ __forceinline__ float ex2f(float x) {
    float y;
    asm("ex2.approx.f32 %0, %1;" : "=f"(y) : "f"(x));
    return y;
}

__device__ __forceinline__ void mma_tf32(float (&d)[4],
                                         const u32 (&a)[4],
                                         const u32 (&b)[2]) {
    asm volatile(
        "mma.sync.aligned.m16n8k8.row.col.f32.tf32.tf32.f32 "
        "{%0,%1,%2,%3}, {%4,%5,%6,%7}, {%8,%9}, {%0,%1,%2,%3};"
        : "+f"(d[0]), "+f"(d[1]), "+f"(d[2]), "+f"(d[3])
        : "r"(a[0]), "r"(a[1]), "r"(a[2]), "r"(a[3]),
          "r"(b[0]), "r"(b[1]));
}

__device__ __forceinline__ u32 smem_u32(const void* p) {
    return (u32)__cvta_generic_to_shared(p);
}

// ---------------------------------------------------------------------------
// Pre-round all weights into g_w (rna tf32), float4-granular.
// ---------------------------------------------------------------------------
__global__ __launch_bounds__(256) void round_weights(
    const float* __restrict__ qkv_w, const float* __restrict__ proj_w,
    const float* __restrict__ off_w, const float* __restrict__ aw_w,
    const float* __restrict__ vproj_w, const float* __restrict__ oproj_w,
    const float* __restrict__ fc1_w, const float* __restrict__ fc2_w,
    float* __restrict__ dst)
{
    int i4 = blockIdx.x*256 + threadIdx.x;
    if (i4 >= WTOT/4) return;
    int i = i4*4;
    const float* src;
    int off;
    if      (i < WOFF_PROJ)  { src = qkv_w;   off = i - WOFF_QKV;  }
    else if (i < WOFF_OFF)   { src = proj_w;  off = i - WOFF_PROJ; }
    else if (i < WOFF_AW)    { src = off_w;   off = i - WOFF_OFF;  }
    else if (i < WOFF_VPROJ) { src = aw_w;    off = i - WOFF_AW;   }
    else if (i < WOFF_OPROJ) { src = vproj_w; off = i - WOFF_VPROJ;}
    else if (i < WOFF_FC1)   { src = oproj_w; off = i - WOFF_OPROJ;}
    else if (i < WOFF_FC2)   { src = fc1_w;   off = i - WOFF_FC1;  }
    else                     { src = fc2_w;   off = i - WOFF_FC2;  }
    float4 v = *(const float4*)(src + off);
    v.x = tf32r(v.x); v.y = tf32r(v.y); v.z = tf32r(v.z); v.w = tf32r(v.w);
    *(float4*)(dst + i) = v;
}

__global__ __launch_bounds__(256) void round_buf(
    const float* __restrict__ src, float* __restrict__ dst, int n4)
{
    int i4 = blockIdx.x*256 + threadIdx.x;
    if (i4 >= n4) return;
    float4 v = *(const float4*)(src + i4*4);
    v.x = tf32r(v.x); v.y = tf32r(v.y); v.z = tf32r(v.z); v.w = tf32r(v.w);
    *(float4*)(dst + i4*4) = v;
}

// ---------------------------------------------------------------------------
// LayerNorm: one block per row, 256 threads (C=256). Output tf32-rounded.
// ---------------------------------------------------------------------------
__global__ __launch_bounds__(256) void ln_kernel(
    const float* __restrict__ in, const float* __restrict__ w,
    const float* __restrict__ b, float* __restrict__ out)
{
    __shared__ float red[8];
    int row = blockIdx.x;
    int t = threadIdx.x;
    float v = in[(size_t)row*C_ + t];
    float s = v;
    #pragma unroll
    for (int o = 16; o; o >>= 1) s += __shfl_xor_sync(0xffffffffu, s, o);
    if ((t & 31) == 0) red[t >> 5] = s;
    __syncthreads();
    float tot = 0.f;
    #pragma unroll
    for (int i = 0; i < 8; i++) tot += red[i];
    float mean = tot * (1.0f/256.0f);
    __syncthreads();
    float d = v - mean;
    s = d*d;
    #pragma unroll
    for (int o = 16; o; o >>= 1) s += __shfl_xor_sync(0xffffffffu, s, o);
    if ((t & 31) == 0) red[t >> 5] = s;
    __syncthreads();
    tot = 0.f;
    #pragma unroll
    for (int i = 0; i < 8; i++) tot += red[i];
    float rs = rsqrtf(tot*(1.0f/256.0f) + 1e-5f);
    out[(size_t)row*C_ + t] = tf32r(d*rs*w[t] + b[t]);
}

// ---------------------------------------------------------------------------
// tf32 tensor-core GEMM, cp.async 3-stage ring, ONE barrier per K-iteration.
// At iter it: wait tile it; barrier; refill stage (it+2)%3 (last read at
// it-1, safe past the barrier); compute stage it%3.
// ---------------------------------------------------------------------------
#define TSTR 36
#define GTILE (128*TSTR)
#define GSTG 3
#define GSMEM (GSTG*2*GTILE*4)        // 110592 B

template <int PAD, int RND>
__global__ __launch_bounds__(256, 2) void gemm_tc_t(
    const float* __restrict__ X, const float* __restrict__ W,
    const float* __restrict__ bias, const float* __restrict__ res,
    float* __restrict__ Y, int M, int Nout, int K, int act)
{
    extern __shared__ float dsm[];
    int tid  = threadIdx.x;
    int warp = tid >> 5, lane = tid & 31;
    int g = lane >> 2, t = lane & 3;
    int wm0 = (warp >> 2) * 64;
    int wn0 = (warp & 3) * 32;
    int m0 = blockIdx.y * 128, n0 = blockIdx.x * 128;
    u32 sb = smem_u32(dsm);

    auto issue_tile = [&](int s, int k0) {
        #pragma unroll
        for (int i = 0; i < 4; i++) {
            int idx = tid + (i << 8);
            int r  = idx >> 3;
            int c4 = (idx & 7) << 2;
            u32 dX = sb + (u32)((s*2*GTILE) + r*TSTR + c4)*4u;
            const float* gX = X + (size_t)(m0+r)*K + k0 + c4;
            asm volatile("cp.async.ca.shared.global [%0], [%1], 16;"
                         :: "r"(dX), "l"(gX));
            u32 dW = sb + (u32)((s*2*GTILE) + GTILE + r*TSTR + c4)*4u;
            const float* gW = W + (size_t)(n0+r)*K + k0 + c4;
            if (PAD) {
                int vld = (n0 + r < Nout) ? 16 : 0;
                asm volatile("cp.async.ca.shared.global [%0], [%1], 16, %2;"
                             :: "r"(dW), "l"(gW), "r"(vld));
            } else {
                asm volatile("cp.async.ca.shared.global [%0], [%1], 16;"
                             :: "r"(dW), "l"(gW));
            }
        }
    };

    float acc[4][4][4];
    #pragma unroll
    for (int mt = 0; mt < 4; mt++)
        #pragma unroll
        for (int nt = 0; nt < 4; nt++)
            #pragma unroll
            for (int c = 0; c < 4; c++) acc[mt][nt][c] = 0.f;

    issue_tile(0, 0);
    asm volatile("cp.async.commit_group;" ::: "memory");
    issue_tile(1, 32);
    asm volatile("cp.async.commit_group;" ::: "memory");

    int nk = K >> 5;
    int stage = 0;
    for (int it = 0; it < nk; it++) {
        asm volatile("cp.async.wait_group 1;" ::: "memory");
        __syncthreads();

        // refill stage (it+2)%3 == stage read at it-1 (safe past barrier)
        int k2 = (it + 2) << 5;
        if (k2 < K) issue_tile((stage + 2 >= GSTG) ? stage - 1 : stage + 2, k2);
        asm volatile("cp.async.commit_group;" ::: "memory");

        const float* sX = dsm + stage*2*GTILE;
        const float* sW = sX + GTILE;
        #pragma unroll
        for (int ks = 0; ks < 4; ks++) {
            int kc = ks*8 + t;
            u32 a[4][4];
            #pragma unroll
            for (int mt = 0; mt < 4; mt++) {
                int r = wm0 + mt*16 + g;
                a[mt][0] = __float_as_uint(sX[r*TSTR     + kc]);
                a[mt][1] = __float_as_uint(sX[(r+8)*TSTR + kc]);
                a[mt][2] = __float_as_uint(sX[r*TSTR     + kc + 4]);
                a[mt][3] = __float_as_uint(sX[(r+8)*TSTR + kc + 4]);
            }
            u32 bb[4][2];
            #pragma unroll
            for (int nt = 0; nt < 4; nt++) {
                int r = wn0 + nt*8 + g;
                bb[nt][0] = __float_as_uint(sW[r*TSTR + kc]);
                bb[nt][1] = __float_as_uint(sW[r*TSTR + kc + 4]);
            }
            #pragma unroll
            for (int mt = 0; mt < 4; mt++)
                #pragma unroll
                for (int nt = 0; nt < 4; nt++)
                    mma_tf32(acc[mt][nt], a[mt], bb[nt]);
        }
        stage = (stage + 1 == GSTG) ? 0 : stage + 1;
    }

    #pragma unroll
    for (int mt = 0; mt < 4; mt++) {
        #pragma unroll
        for (int nt = 0; nt < 4; nt++) {
            int n = n0 + wn0 + nt*8 + 2*t;
            if (PAD && n >= Nout) continue;
            #pragma unroll
            for (int half = 0; half < 2; half++) {
                int m = m0 + wm0 + mt*16 + g + half*8;
                float v0 = acc[mt][nt][half*2 + 0];
                float v1 = acc[mt][nt][half*2 + 1];
                if (bias) { v0 += bias[n]; v1 += bias[n+1]; }
                if (act)  { v0 *= normcdff(v0); v1 *= normcdff(v1); }
                if (res)  { v0 += res[(size_t)m*Nout + n];
                            v1 += res[(size_t)m*Nout + n + 1]; }
                if (RND)  { v0 = tf32r(v0); v1 = tf32r(v1); }
                *(float2*)(Y + (size_t)m*Nout + n) = make_float2(v0, v1);
            }
        }
    }
}

// ---------------------------------------------------------------------------
// Flash attention v3: double-buffered K/V, ONE barrier per chunk.
// Per chunk: STS(regs->buf c%2) ; LDG prefetch c+1 ; barrier ; compute.
// Softmax in base-2 (log2e folded into Q scale, raw ex2.approx).
// ---------------------------------------------------------------------------
#define FQT  128
#define FKC  64
#define QSTR 36
#define VSTR 68
#define KVBUF (FKC*QSTR + 32*VSTR)                 // 4480 floats
#define FSMEM ((FQT*QSTR + 2*KVBUF)*4)             // 54272 B

__global__ __launch_bounds__(256, 2) void flash_tc(
    const float* __restrict__ qkv, float* __restrict__ out)
{
    extern __shared__ float sm[];
    float* q_s = sm;                    // FQT x 36
    float* kvb = sm + FQT*QSTR;         // 2 x KVBUF

    int tid  = threadIdx.x;
    int warp = tid >> 5, lane = tid & 31;
    int g = lane >> 2, t = lane & 3;
    int b = blockIdx.z, h = blockIdx.y;
    int q0 = blockIdx.x * FQT;
    const float* qb = qkv + (size_t)b*N_*768 + h*32;
    // 32^-0.5 * log2(e) folded into Q
    const float qsc = 0.17677669529663687f * 1.4426950408889634f;

    for (int ii = tid; ii < FQT*8; ii += 256) {
        int r = ii >> 3, c4q = (ii & 7) << 2;
        float4 v = *(const float4*)(qb + (size_t)(q0+r)*768 + c4q);
        q_s[r*QSTR + c4q + 0] = tf32r(v.x*qsc);
        q_s[r*QSTR + c4q + 1] = tf32r(v.y*qsc);
        q_s[r*QSTR + c4q + 2] = tf32r(v.z*qsc);
        q_s[r*QSTR + c4q + 3] = tf32r(v.w*qsc);
    }

    int row0 = warp * 16;
    float oa[4][4];
    #pragma unroll
    for (int nt = 0; nt < 4; nt++)
        #pragma unroll
        for (int c = 0; c < 4; c++) oa[nt][c] = 0.f;
    float mr0 = -1e30f, mr1 = -1e30f, lr0 = 0.f, lr1 = 0.f;

    int src_lo = (lane & ~3) | (t >> 1);
    int src_hi = src_lo | 2;

    int rA = tid >> 3, rB = rA + 32;
    int c4 = (tid & 7) << 2;

    float4 kfA = *(const float4*)(qb + (size_t)rA*768 + 256 + c4);
    float4 kfB = *(const float4*)(qb + (size_t)rB*768 + 256 + c4);
    float4 vfA = *(const float4*)(qb + (size_t)rA*768 + 512 + c4);
    float4 vfB = *(const float4*)(qb + (size_t)rB*768 + 512 + c4);

    for (int ic = 0; ic < N_/FKC; ic++) {
        float* k_s = kvb + (ic & 1)*KVBUF;
        float* v_s = k_s + FKC*QSTR;

        // stage chunk ic (buf (ic&1) was last read at chunk ic-2; the barrier
        // below at chunk ic-1 ordered those reads before this write)
        k_s[rA*QSTR + c4 + 0] = tf32r(kfA.x);
        k_s[rA*QSTR + c4 + 1] = tf32r(kfA.y);
        k_s[rA*QSTR + c4 + 2] = tf32r(kfA.z);
        k_s[rA*QSTR + c4 + 3] = tf32r(kfA.w);
        k_s[rB*QSTR + c4 + 0] = tf32r(kfB.x);
        k_s[rB*QSTR + c4 + 1] = tf32r(kfB.y);
        k_s[rB*QSTR + c4 + 2] = tf32r(kfB.z);
        k_s[rB*QSTR + c4 + 3] = tf32r(kfB.w);
        v_s[(c4+0)*VSTR + rA] = tf32r(vfA.x);
        v_s[(c4+1)*VSTR + rA] = tf32r(vfA.y);
        v_s[(c4+2)*VSTR + rA] = tf32r(vfA.z);
        v_s[(c4+3)*VSTR + rA] = tf32r(vfA.w);
        v_s[(c4+0)*VSTR + rB] = tf32r(vfB.x);
        v_s[(c4+1)*VSTR + rB] = tf32r(vfB.y);
        v_s[(c4+2)*VSTR + rB] = tf32r(vfB.z);
        v_s[(c4+3)*VSTR + rB] = tf32r(vfB.w);

        // prefetch chunk ic+1 (overlaps this chunk's compute)
        int ktn = (ic + 1) * FKC;
        if (ktn < N_) {
            kfA = *(const float4*)(qb + (size_t)(ktn+rA)*768 + 256 + c4);
            kfB = *(const float4*)(qb + (size_t)(ktn+rB)*768 + 256 + c4);
            vfA = *(const float4*)(qb + (size_t)(ktn+rA)*768 + 512 + c4);
            vfB = *(const float4*)(qb + (size_t)(ktn+rB)*768 + 512 + c4);
        }
        __syncthreads();

        // ---- S = Q @ K^T (scaled to log2 units) ----
        float s[8][4];
        #pragma unroll
        for (int nt = 0; nt < 8; nt++)
            #pragma unroll
            for (int c = 0; c < 4; c++) s[nt][c] = 0.f;

        #pragma unroll
        for (int ks = 0; ks < 4; ks++) {
            int kc = ks*8 + t;
            u32 a[4];
            a[0] = __float_as_uint(q_s[(row0+g)*QSTR   + kc]);
            a[1] = __float_as_uint(q_s[(row0+8+g)*QSTR + kc]);
            a[2] = __float_as_uint(q_s[(row0+g)*QSTR   + kc + 4]);
            a[3] = __float_as_uint(q_s[(row0+8+g)*QSTR + kc + 4]);
            u32 bb[8][2];
            #pragma unroll
            for (int nt = 0; nt < 8; nt++) {
                int rr = nt*8 + g;
                bb[nt][0] = __float_as_uint(k_s[rr*QSTR + kc]);
                bb[nt][1] = __float_as_uint(k_s[rr*QSTR + kc + 4]);
            }
            #pragma unroll
            for (int nt = 0; nt < 8; nt++)
                mma_tf32(s[nt], a, bb[nt]);
        }

        // ---- online softmax in base-2 ----
        {
            float m0 = -1e30f, m1 = -1e30f;
            #pragma unroll
            for (int nt = 0; nt < 8; nt++) {
                m0 = fmaxf(m0, fmaxf(s[nt][0], s[nt][1]));
                m1 = fmaxf(m1, fmaxf(s[nt][2], s[nt][3]));
            }
            #pragma unroll
            for (int o = 1; o <= 2; o <<= 1) {
                m0 = fmaxf(m0, __shfl_xor_sync(0xffffffffu, m0, o));
                m1 = fmaxf(m1, __shfl_xor_sync(0xffffffffu, m1, o));
            }
            float mn0 = fmaxf(mr0, m0);
            float mn1 = fmaxf(mr1, m1);
            float sf0 = ex2f(mr0 - mn0);
            float sf1 = ex2f(mr1 - mn1);
            mr0 = mn0; mr1 = mn1;
            float ls0 = 0.f, ls1 = 0.f;
            #pragma unroll
            for (int nt = 0; nt < 8; nt++) {
                float e0 = ex2f(s[nt][0] - mn0);
                float e1 = ex2f(s[nt][1] - mn0);
                float e2 = ex2f(s[nt][2] - mn1);
                float e3 = ex2f(s[nt][3] - mn1);
                ls0 += e0 + e1;  ls1 += e2 + e3;
                s[nt][0] = tf32r(e0);  s[nt][1] = tf32r(e1);
                s[nt][2] = tf32r(e2);  s[nt][3] = tf32r(e3);
            }
            #pragma unroll
            for (int o = 1; o <= 2; o <<= 1) {
                ls0 += __shfl_xor_sync(0xffffffffu, ls0, o);
                ls1 += __shfl_xor_sync(0xffffffffu, ls1, o);
            }
            lr0 = lr0*sf0 + ls0;
            lr1 = lr1*sf1 + ls1;
            #pragma unroll
            for (int nt = 0; nt < 4; nt++) {
                oa[nt][0] *= sf0;  oa[nt][1] *= sf0;
                oa[nt][2] *= sf1;  oa[nt][3] *= sf1;
            }
        }

        // ---- O += P @ V ----
        #pragma unroll
        for (int k8 = 0; k8 < 8; k8++) {
            float y00 = __shfl_sync(0xffffffffu, s[k8][0], src_lo);
            float y01 = __shfl_sync(0xffffffffu, s[k8][1], src_lo);
            float y10 = __shfl_sync(0xffffffffu, s[k8][0], src_hi);
            float y11 = __shfl_sync(0xffffffffu, s[k8][1], src_hi);
            float z00 = __shfl_sync(0xffffffffu, s[k8][2], src_lo);
            float z01 = __shfl_sync(0xffffffffu, s[k8][3], src_lo);
            float z10 = __shfl_sync(0xffffffffu, s[k8][2], src_hi);
            float z11 = __shfl_sync(0xffffffffu, s[k8][3], src_hi);
            u32 a[4];
            a[0] = __float_as_uint((t & 1) ? y01 : y00);
            a[2] = __float_as_uint((t & 1) ? y11 : y10);
            a[1] = __float_as_uint((t & 1) ? z01 : z00);
            a[3] = __float_as_uint((t & 1) ? z11 : z10);
            u32 bb[4][2];
            #pragma unroll
            for (int nt = 0; nt < 4; nt++) {
                int d = nt*8 + g;
                bb[nt][0] = __float_as_uint(v_s[d*VSTR + k8*8 + t]);
                bb[nt][1] = __float_as_uint(v_s[d*VSTR + k8*8 + t + 4]);
            }
            #pragma unroll
            for (int nt = 0; nt < 4; nt++)
                mma_tf32(oa[nt], a, bb[nt]);
        }
    }

    float i0 = 1.f / lr0;
    float i1 = 1.f / lr1;
    int r = q0 + row0 + g;
    #pragma unroll
    for (int nt = 0; nt < 4; nt++) {
        int col = h*32 + nt*8 + 2*t;
        *(float2*)(out + ((size_t)b*N_ + r)*C_ + col) =
            make_float2(tf32r(oa[nt][0]*i0), tf32r(oa[nt][1]*i0));
        *(float2*)(out + ((size_t)b*N_ + r + 8)*C_ + col) =
            make_float2(tf32r(oa[nt][2]*i1), tf32r(oa[nt][3]*i1));
    }
}

// ---------------------------------------------------------------------------
// Deformable gather: one warp per (b, n, head); lane = channel d.
// ---------------------------------------------------------------------------
__global__ __launch_bounds__(128) void deform_kernel(
    const float* __restrict__ ref, const float* __restrict__ off,
    const float* __restrict__ awl, const float* __restrict__ vp,
    float* __restrict__ out)
{
    int u = (blockIdx.x << 2) + (threadIdx.x >> 5);
    int lane = threadIdx.x & 31;
    int h  = u & 7;
    int bn = u >> 3;
    int b  = bn >> 10;

    float rx = ref[(size_t)bn*2 + 0]*32.f - 0.5f;
    float ry = ref[(size_t)bn*2 + 1]*32.f - 0.5f;
    const float* offp = off + (size_t)bn*64 + h*8;
    const float* awp  = awl + (size_t)bn*32 + h*4;

    float a0 = awp[0], a1 = awp[1], a2 = awp[2], a3 = awp[3];
    float mx = fmaxf(fmaxf(a0,a1), fmaxf(a2,a3));
    float e0 = __expf(a0-mx), e1 = __expf(a1-mx), e2 = __expf(a2-mx), e3 = __expf(a3-mx);
    float inv = 1.f/(e0+e1+e2+e3);
    float aw4[4] = {e0*inv, e1*inv, e2*inv, e3*inv};

    const float* vb = vp + (size_t)b*N_*C_ + h*32 + lane;
    float acc = 0.f;
    #pragma unroll
    for (int p = 0; p < 4; p++) {
        float gx = rx + offp[p*2+0];
        float gy = ry + offp[p*2+1];
        float x0f = floorf(gx), y0f = floorf(gy);
        float lx = gx - x0f, ly = gy - y0f;
        int x0 = (int)x0f, y0 = (int)y0f;
        float s = 0.f;
        #pragma unroll
        for (int cy = 0; cy < 2; cy++) {
            int yi = y0 + cy;
            float wy = cy ? ly : (1.f - ly);
            bool vy = (yi >= 0) && (yi < 32);
            int yc = min(max(yi, 0), 31);
            #pragma unroll
            for (int cx = 0; cx < 2; cx++) {
                int xi = x0 + cx;
                float wx = cx ? lx : (1.f - lx);
                bool vx = (xi >= 0) && (xi < 32);
                int xc = min(max(xi, 0), 31);
                float val = (vx && vy) ? vb[(size_t)(yc*32 + xc)*C_] : 0.f;
                s = fmaf(val, wx*wy, s);
            }
        }
        acc = fmaf(aw4[p], s, acc);
    }
    out[(size_t)bn*C_ + h*32 + lane] = tf32r(acc);
}

// ---------------------------------------------------------------------------
// Launch
// ---------------------------------------------------------------------------
extern "C" void kernel_launch(void* const* d_in, const int* in_sizes, int n_in,
                              void* d_out, int out_size)
{
    const float* x       = (const float*)d_in[0];
    const float* ref     = (const float*)d_in[1];
    const float* value   = (const float*)d_in[2];
    const float* ln1w    = (const float*)d_in[3];
    const float* ln1b    = (const float*)d_in[4];
    const float* ln2w    = (const float*)d_in[5];
    const float* ln2b    = (const float*)d_in[6];
    const float* ln3w    = (const float*)d_in[7];
    const float* ln3b    = (const float*)d_in[8];
    const float* qkv_w   = (const float*)d_in[9];
    const float* proj_w  = (const float*)d_in[10];
    const float* proj_b  = (const float*)d_in[11];
    const float* off_w   = (const float*)d_in[12];
    const float* off_b   = (const float*)d_in[13];
    const float* aw_w    = (const float*)d_in[14];
    const float* aw_b    = (const float*)d_in[15];
    const float* vproj_w = (const float*)d_in[16];
    const float* vproj_b = (const float*)d_in[17];
    const float* oproj_w = (const float*)d_in[18];
    const float* oproj_b = (const float*)d_in[19];
    const float* fc1_w   = (const float*)d_in[20];
    const float* fc1_b   = (const float*)d_in[21];
    const float* fc2_w   = (const float*)d_in[22];
    const float* fc2_b   = (const float*)d_in[23];
    float* out = (float*)d_out;

    float *y, *qkvb, *tmp, *x2, *offb, *awb, *vpb, *h1, *wbuf, *valb;
    cudaGetSymbolAddress((void**)&y,    g_y);
    cudaGetSymbolAddress((void**)&qkvb, g_qkv);
    cudaGetSymbolAddress((void**)&tmp,  g_tmp);
    cudaGetSymbolAddress((void**)&x2,   g_x2);
    cudaGetSymbolAddress((void**)&offb, g_off);
    cudaGetSymbolAddress((void**)&awb,  g_awl);
    cudaGetSymbolAddress((void**)&vpb,  g_vp);
    cudaGetSymbolAddress((void**)&h1,   g_h1);
    cudaGetSymbolAddress((void**)&wbuf, g_w);
    cudaGetSymbolAddress((void**)&valb, g_val);

    cudaFuncSetAttribute(flash_tc,
        cudaFuncAttributeMaxDynamicSharedMemorySize, FSMEM);
    cudaFuncSetAttribute(gemm_tc_t<0,0>,
        cudaFuncAttributeMaxDynamicSharedMemorySize, GSMEM);
    cudaFuncSetAttribute(gemm_tc_t<1,0>,
        cudaFuncAttributeMaxDynamicSharedMemorySize, GSMEM);
    cudaFuncSetAttribute(gemm_tc_t<0,1>,
        cudaFuncAttributeMaxDynamicSharedMemorySize, GSMEM);

    const float* wq  = wbuf + WOFF_QKV;
    const float* wp  = wbuf + WOFF_PROJ;
    const float* wo  = wbuf + WOFF_OFF;
    const float* wa  = wbuf + WOFF_AW;
    const float* wv  = wbuf + WOFF_VPROJ;
    const float* wop = wbuf + WOFF_OPROJ;
    const float* w1  = wbuf + WOFF_FC1;
    const float* w2  = wbuf + WOFF_FC2;

    // pre-round weights + value (rna tf32)
    round_weights<<<(WTOT/4 + 255)/256, 256>>>(qkv_w, proj_w, off_w, aw_w,
        vproj_w, oproj_w, fc1_w, fc2_w, wbuf);
    round_buf<<<(M_*C_/4 + 255)/256, 256>>>(value, valb, M_*C_/4);

    // x1 = x + attn(ln1(x))
    ln_kernel<<<M_, 256>>>(x, ln1w, ln1b, y);
    gemm_tc_t<0,0><<<dim3(6,128), 256, GSMEM>>>(y, wq, nullptr, nullptr, qkvb, M_, 768, 256, 0);
    flash_tc<<<dim3(N_/FQT, NH_, B_), 256, FSMEM>>>(qkvb, tmp);
    gemm_tc_t<0,0><<<dim3(2,128), 256, GSMEM>>>(tmp, wp, proj_b, x, x2, M_, 256, 256, 0);

    // x2 = x1 + deform(ln2(x1))
    ln_kernel<<<M_, 256>>>(x2, ln2w, ln2b, y);
    gemm_tc_t<1,0><<<dim3(1,128), 256, GSMEM>>>(y, wo, off_b, nullptr, offb, M_, 64, 256, 0);
    gemm_tc_t<1,0><<<dim3(1,128), 256, GSMEM>>>(y, wa, aw_b, nullptr, awb, M_, 32, 256, 0);
    gemm_tc_t<0,0><<<dim3(2,128), 256, GSMEM>>>(valb, wv, vproj_b, nullptr, vpb, M_, 256, 256, 0);
    deform_kernel<<<32768, 128>>>(ref, offb, awb, vpb, tmp);
    gemm_tc_t<0,0><<<dim3(2,128), 256, GSMEM>>>(tmp, wop, oproj_b, x2, x2, M_, 256, 256, 0);

    // out = x2 + fc2(gelu(fc1(ln3(x2))))
    ln_kernel<<<M_, 256>>>(x2, ln3w, ln3b, y);
    gemm_tc_t<0,1><<<dim3(8,128), 256, GSMEM>>>(y, w1, fc1_b, nullptr, h1, M_, 1024, 256, 1);
    gemm_tc_t<0,0><<<dim3(2,128), 256, GSMEM>>>(h1, w2, fc2_b, x2, out, M_, 256, 1024, 0);
}

// round 12
// speedup vs baseline: 1.2648x; 1.2648x over previous
#include <cuda_runtime.h>
#include <cuda_fp16.h>
#include <cstdint>
#include <math.h>

typedef unsigned int u32;

// Problem constants
#define B_  16
#define N_  1024
#define C_  256
#define NH_ 8
#define DH_ 32
#define M_  (B_*N_)      // 16384 rows
#define HID_ 1024

// Weight segment sizes (floats)
#define WSZ_QKV   (3*C_*C_)
#define WSZ_PROJ  (C_*C_)
#define WSZ_OFF   (64*C_)
#define WSZ_AW    (32*C_)
#define WSZ_VPROJ (C_*C_)
#define WSZ_OPROJ (C_*C_)
#define WSZ_FC1   (HID_*C_)
#define WSZ_FC2   (C_*HID_)
#define WOFF_QKV   0
#define WOFF_PROJ  (WOFF_QKV  + WSZ_QKV)
#define WOFF_OFF   (WOFF_PROJ + WSZ_PROJ)
#define WOFF_AW    (WOFF_OFF  + WSZ_OFF)
#define WOFF_VPROJ (WOFF_AW   + WSZ_AW)
#define WOFF_OPROJ (WOFF_VPROJ+ WSZ_VPROJ)
#define WOFF_FC1   (WOFF_OPROJ+ WSZ_OPROJ)
#define WOFF_FC2   (WOFF_FC1  + WSZ_FC1)
#define WTOT       (WOFF_FC2  + WSZ_FC2)   // 942080

// ---------------------------------------------------------------------------
// Scratch (static __device__ arrays; no allocations allowed)
// ---------------------------------------------------------------------------
__device__ float  g_qkv[M_*3*C_];
__device__ float  g_x2 [M_*C_];
__device__ float  g_off[M_*64];
__device__ float  g_awl[M_*32];
__device__ float  g_vp [M_*C_];
__device__ __half g_yh  [M_*C_];     // LN output (half, GEMM X)
__device__ __half g_tmph[M_*C_];     // flash-out / deform-out (half, GEMM X)
__device__ __half g_h1h [M_*HID_];   // fc1 output (half, fc2 X)
__device__ __half g_wh  [WTOT];      // fp16 weights
__device__ __half g_valh[M_*C_];     // fp16 value input

// ---------------------------------------------------------------------------
// helpers
// ---------------------------------------------------------------------------
__device__ __forceinline__ float tf32r(float x) {
    u32 u;
    asm("cvt.rna.tf32.f32 %0, %1;" : "=r"(u) : "f"(x));
    return __uint_as_float(u);
}

__device__ __forceinline__ float ex2f(float x) {
    float y;
    asm("ex2.approx.f32 %0, %1;" : "=f"(y) : "f"(x));
    return y;
}

__device__ __forceinline__ void mma_tf32(float (&d)[4],
                                         const u32 (&a)[4],
                                         const u32 (&b)[2]) {
    asm volatile(
        "mma.sync.aligned.m16n8k8.row.col.f32.tf32.tf32.f32 "
        "{%0,%1,%2,%3}, {%4,%5,%6,%7}, {%8,%9}, {%0,%1,%2,%3};"
        : "+f"(d[0]), "+f"(d[1]), "+f"(d[2]), "+f"(d[3])
        : "r"(a[0]), "r"(a[1]), "r"(a[2]), "r"(a[3]),
          "r"(b[0]), "r"(b[1]));
}

__device__ __forceinline__ void mma_f16(float (&d)[4],
                                        const u32 (&a)[4],
                                        const u32 (&b)[2]) {
    asm volatile(
        "mma.sync.aligned.m16n8k16.row.col.f32.f16.f16.f32 "
        "{%0,%1,%2,%3}, {%4,%5,%6,%7}, {%8,%9}, {%0,%1,%2,%3};"
        : "+f"(d[0]), "+f"(d[1]), "+f"(d[2]), "+f"(d[3])
        : "r"(a[0]), "r"(a[1]), "r"(a[2]), "r"(a[3]),
          "r"(b[0]), "r"(b[1]));
}

__device__ __forceinline__ u32 smem_u32(const void* p) {
    return (u32)__cvta_generic_to_shared(p);
}

// ---------------------------------------------------------------------------
// Weight / buffer conversion to fp16 (RN)
// ---------------------------------------------------------------------------
__global__ __launch_bounds__(256) void round_weights_h(
    const float* __restrict__ qkv_w, const float* __restrict__ proj_w,
    const float* __restrict__ off_w, const float* __restrict__ aw_w,
    const float* __restrict__ vproj_w, const float* __restrict__ oproj_w,
    const float* __restrict__ fc1_w, const float* __restrict__ fc2_w,
    __half* __restrict__ dst)
{
    int i4 = blockIdx.x*256 + threadIdx.x;
    if (i4 >= WTOT/4) return;
    int i = i4*4;
    const float* src;
    int off;
    if      (i < WOFF_PROJ)  { src = qkv_w;   off = i - WOFF_QKV;  }
    else if (i < WOFF_OFF)   { src = proj_w;  off = i - WOFF_PROJ; }
    else if (i < WOFF_AW)    { src = off_w;   off = i - WOFF_OFF;  }
    else if (i < WOFF_VPROJ) { src = aw_w;    off = i - WOFF_AW;   }
    else if (i < WOFF_OPROJ) { src = vproj_w; off = i - WOFF_VPROJ;}
    else if (i < WOFF_FC1)   { src = oproj_w; off = i - WOFF_OPROJ;}
    else if (i < WOFF_FC2)   { src = fc1_w;   off = i - WOFF_FC1;  }
    else                     { src = fc2_w;   off = i - WOFF_FC2;  }
    float4 v = *(const float4*)(src + off);
    __half2 h0 = __floats2half2_rn(v.x, v.y);
    __half2 h1 = __floats2half2_rn(v.z, v.w);
    *(uint2*)(dst + i) = make_uint2(*(u32*)&h0, *(u32*)&h1);
}

__global__ __launch_bounds__(256) void round_buf_h(
    const float* __restrict__ src, __half* __restrict__ dst, int n4)
{
    int i4 = blockIdx.x*256 + threadIdx.x;
    if (i4 >= n4) return;
    float4 v = *(const float4*)(src + i4*4);
    __half2 h0 = __floats2half2_rn(v.x, v.y);
    __half2 h1 = __floats2half2_rn(v.z, v.w);
    *(uint2*)(dst + i4*4) = make_uint2(*(u32*)&h0, *(u32*)&h1);
}

// ---------------------------------------------------------------------------
// LayerNorm: one block per row. Output fp16 (GEMM X operand only).
// ---------------------------------------------------------------------------
__global__ __launch_bounds__(256) void ln_kernel(
    const float* __restrict__ in, const float* __restrict__ w,
    const float* __restrict__ b, __half* __restrict__ out)
{
    __shared__ float red[8];
    int row = blockIdx.x;
    int t = threadIdx.x;
    float v = in[(size_t)row*C_ + t];
    float s = v;
    #pragma unroll
    for (int o = 16; o; o >>= 1) s += __shfl_xor_sync(0xffffffffu, s, o);
    if ((t & 31) == 0) red[t >> 5] = s;
    __syncthreads();
    float tot = 0.f;
    #pragma unroll
    for (int i = 0; i < 8; i++) tot += red[i];
    float mean = tot * (1.0f/256.0f);
    __syncthreads();
    float d = v - mean;
    s = d*d;
    #pragma unroll
    for (int o = 16; o; o >>= 1) s += __shfl_xor_sync(0xffffffffu, s, o);
    if ((t & 31) == 0) red[t >> 5] = s;
    __syncthreads();
    tot = 0.f;
    #pragma unroll
    for (int i = 0; i < 8; i++) tot += red[i];
    float rs = rsqrtf(tot*(1.0f/256.0f) + 1e-5f);
    out[(size_t)row*C_ + t] = __float2half_rn(d*rs*w[t] + b[t]);
}

// ---------------------------------------------------------------------------
// fp16 tensor-core GEMM, cp.async 2-stage double buffer (R10 structure).
// Y[M,Nout] = X[M,K] @ W[Nout,K]^T (+bias)(+gelu)(+res)
// Block 128x128, BK=32, 8 warps 2x4, warp tile 64x32 (m16n8k16).
// smem in u32 words, row stride 20 words (40 halves) -> conflict-free frags.
// OUTH: write half output (fc1->fc2); else fp32.
// ---------------------------------------------------------------------------
#define HSTRW 20
#define HTILE (128*HSTRW)             // words per operand-stage (2560)
#define GSMEM (2*2*HTILE*4)           // 40960 B

template <int PAD, int OUTH>
__global__ __launch_bounds__(256, 2) void gemm_h(
    const __half* __restrict__ X, const __half* __restrict__ W,
    const float* __restrict__ bias, const float* __restrict__ res,
    void* __restrict__ Yv, int M, int Nout, int K, int act)
{
    extern __shared__ u32 hsm[];
    int tid  = threadIdx.x;
    int warp = tid >> 5, lane = tid & 31;
    int g = lane >> 2, t = lane & 3;
    int wm0 = (warp >> 2) * 64;
    int wn0 = (warp & 3) * 32;
    int m0 = blockIdx.y * 128, n0 = blockIdx.x * 128;
    u32 sb = smem_u32(hsm);

    auto issue_tile = [&](int s, int k0 /*halves*/) {
        #pragma unroll
        for (int i = 0; i < 2; i++) {
            int idx = tid + (i << 8);       // 0..511
            int r  = idx >> 2;              // 0..127
            int c8 = (idx & 3) << 3;        // half offset 0,8,16,24
            u32 dX = sb + (u32)((s*2*HTILE) + r*HSTRW + (c8 >> 1))*4u;
            const __half* gX = X + (size_t)(m0+r)*K + k0 + c8;
            asm volatile("cp.async.ca.shared.global [%0], [%1], 16;"
                         :: "r"(dX), "l"(gX));
            u32 dW = sb + (u32)((s*2*HTILE) + HTILE + r*HSTRW + (c8 >> 1))*4u;
            const __half* gW = W + (size_t)(n0+r)*K + k0 + c8;
            if (PAD) {
                int vld = (n0 + r < Nout) ? 16 : 0;
                asm volatile("cp.async.ca.shared.global [%0], [%1], 16, %2;"
                             :: "r"(dW), "l"(gW), "r"(vld));
            } else {
                asm volatile("cp.async.ca.shared.global [%0], [%1], 16;"
                             :: "r"(dW), "l"(gW));
            }
        }
    };

    float acc[4][4][4];
    #pragma unroll
    for (int mt = 0; mt < 4; mt++)
        #pragma unroll
        for (int nt = 0; nt < 4; nt++)
            #pragma unroll
            for (int c = 0; c < 4; c++) acc[mt][nt][c] = 0.f;

    issue_tile(0, 0);
    asm volatile("cp.async.commit_group;" ::: "memory");
    issue_tile(1, 32);
    asm volatile("cp.async.commit_group;" ::: "memory");

    int nk = K >> 5;
    for (int it = 0; it < nk; it++) {
        asm volatile("cp.async.wait_group 1;" ::: "memory");
        __syncthreads();

        const u32* sX = hsm + (it & 1)*2*HTILE;
        const u32* sW = sX + HTILE;
        #pragma unroll
        for (int ks = 0; ks < 2; ks++) {
            int kc = ks*8 + t;              // word offset within row
            u32 a[4][4];
            #pragma unroll
            for (int mt = 0; mt < 4; mt++) {
                int r = wm0 + mt*16 + g;
                a[mt][0] = sX[r*HSTRW     + kc];
                a[mt][1] = sX[(r+8)*HSTRW + kc];
                a[mt][2] = sX[r*HSTRW     + kc + 4];
                a[mt][3] = sX[(r+8)*HSTRW + kc + 4];
            }
            u32 bb[4][2];
            #pragma unroll
            for (int nt = 0; nt < 4; nt++) {
                int r = wn0 + nt*8 + g;
                bb[nt][0] = sW[r*HSTRW + kc];
                bb[nt][1] = sW[r*HSTRW + kc + 4];
            }
            #pragma unroll
            for (int mt = 0; mt < 4; mt++)
                #pragma unroll
                for (int nt = 0; nt < 4; nt++)
                    mma_f16(acc[mt][nt], a[mt], bb[nt]);
        }
        __syncthreads();

        int k2 = (it + 2) << 5;
        if (k2 < K) issue_tile(it & 1, k2);
        asm volatile("cp.async.commit_group;" ::: "memory");
    }

    float* Yf = (float*)Yv;
    __half* Yh = (__half*)Yv;
    #pragma unroll
    for (int mt = 0; mt < 4; mt++) {
        #pragma unroll
        for (int nt = 0; nt < 4; nt++) {
            int n = n0 + wn0 + nt*8 + 2*t;
            if (PAD && n >= Nout) continue;
            #pragma unroll
            for (int half2i = 0; half2i < 2; half2i++) {
                int m = m0 + wm0 + mt*16 + g + half2i*8;
                float v0 = acc[mt][nt][half2i*2 + 0];
                float v1 = acc[mt][nt][half2i*2 + 1];
                if (bias) { v0 += bias[n]; v1 += bias[n+1]; }
                if (act)  { v0 *= normcdff(v0); v1 *= normcdff(v1); }
                if (res)  { v0 += res[(size_t)m*Nout + n];
                            v1 += res[(size_t)m*Nout + n + 1]; }
                if (OUTH) {
                    __half2 hv = __floats2half2_rn(v0, v1);
                    *(__half2*)(Yh + (size_t)m*Nout + n) = hv;
                } else {
                    *(float2*)(Yf + (size_t)m*Nout + n) = make_float2(v0, v1);
                }
            }
        }
    }
}

// ---------------------------------------------------------------------------
// Flash attention v3 (tf32 mma): double-buffered K/V, ONE barrier per chunk,
// base-2 online softmax. Output fp16 (proj GEMM X operand).
// ---------------------------------------------------------------------------
#define FQT  128
#define FKC  64
#define QSTR 36
#define VSTR 68
#define KVBUF (FKC*QSTR + 32*VSTR)                 // 4480 floats
#define FSMEM ((FQT*QSTR + 2*KVBUF)*4)             // 54272 B

__global__ __launch_bounds__(256, 2) void flash_tc(
    const float* __restrict__ qkv, __half* __restrict__ out)
{
    extern __shared__ float sm[];
    float* q_s = sm;                    // FQT x 36
    float* kvb = sm + FQT*QSTR;         // 2 x KVBUF

    int tid  = threadIdx.x;
    int warp = tid >> 5, lane = tid & 31;
    int g = lane >> 2, t = lane & 3;
    int b = blockIdx.z, h = blockIdx.y;
    int q0 = blockIdx.x * FQT;
    const float* qb = qkv + (size_t)b*N_*768 + h*32;
    const float qsc = 0.17677669529663687f * 1.4426950408889634f;

    for (int ii = tid; ii < FQT*8; ii += 256) {
        int r = ii >> 3, c4q = (ii & 7) << 2;
        float4 v = *(const float4*)(qb + (size_t)(q0+r)*768 + c4q);
        q_s[r*QSTR + c4q + 0] = tf32r(v.x*qsc);
        q_s[r*QSTR + c4q + 1] = tf32r(v.y*qsc);
        q_s[r*QSTR + c4q + 2] = tf32r(v.z*qsc);
        q_s[r*QSTR + c4q + 3] = tf32r(v.w*qsc);
    }

    int row0 = warp * 16;
    float oa[4][4];
    #pragma unroll
    for (int nt = 0; nt < 4; nt++)
        #pragma unroll
        for (int c = 0; c < 4; c++) oa[nt][c] = 0.f;
    float mr0 = -1e30f, mr1 = -1e30f, lr0 = 0.f, lr1 = 0.f;

    int src_lo = (lane & ~3) | (t >> 1);
    int src_hi = src_lo | 2;

    int rA = tid >> 3, rB = rA + 32;
    int c4 = (tid & 7) << 2;

    float4 kfA = *(const float4*)(qb + (size_t)rA*768 + 256 + c4);
    float4 kfB = *(const float4*)(qb + (size_t)rB*768 + 256 + c4);
    float4 vfA = *(const float4*)(qb + (size_t)rA*768 + 512 + c4);
    float4 vfB = *(const float4*)(qb + (size_t)rB*768 + 512 + c4);

    for (int ic = 0; ic < N_/FKC; ic++) {
        float* k_s = kvb + (ic & 1)*KVBUF;
        float* v_s = k_s + FKC*QSTR;

        k_s[rA*QSTR + c4 + 0] = tf32r(kfA.x);
        k_s[rA*QSTR + c4 + 1] = tf32r(kfA.y);
        k_s[rA*QSTR + c4 + 2] = tf32r(kfA.z);
        k_s[rA*QSTR + c4 + 3] = tf32r(kfA.w);
        k_s[rB*QSTR + c4 + 0] = tf32r(kfB.x);
        k_s[rB*QSTR + c4 + 1] = tf32r(kfB.y);
        k_s[rB*QSTR + c4 + 2] = tf32r(kfB.z);
        k_s[rB*QSTR + c4 + 3] = tf32r(kfB.w);
        v_s[(c4+0)*VSTR + rA] = tf32r(vfA.x);
        v_s[(c4+1)*VSTR + rA] = tf32r(vfA.y);
        v_s[(c4+2)*VSTR + rA] = tf32r(vfA.z);
        v_s[(c4+3)*VSTR + rA] = tf32r(vfA.w);
        v_s[(c4+0)*VSTR + rB] = tf32r(vfB.x);
        v_s[(c4+1)*VSTR + rB] = tf32r(vfB.y);
        v_s[(c4+2)*VSTR + rB] = tf32r(vfB.z);
        v_s[(c4+3)*VSTR + rB] = tf32r(vfB.w);

        int ktn = (ic + 1) * FKC;
        if (ktn < N_) {
            kfA = *(const float4*)(qb + (size_t)(ktn+rA)*768 + 256 + c4);
            kfB = *(const float4*)(qb + (size_t)(ktn+rB)*768 + 256 + c4);
            vfA = *(const float4*)(qb + (size_t)(ktn+rA)*768 + 512 + c4);
            vfB = *(const float4*)(qb + (size_t)(ktn+rB)*768 + 512 + c4);
        }
        __syncthreads();

        float s[8][4];
        #pragma unroll
        for (int nt = 0; nt < 8; nt++)
            #pragma unroll
            for (int c = 0; c < 4; c++) s[nt][c] = 0.f;

        #pragma unroll
        for (int ks = 0; ks < 4; ks++) {
            int kc = ks*8 + t;
            u32 a[4];
            a[0] = __float_as_uint(q_s[(row0+g)*QSTR   + kc]);
            a[1] = __float_as_uint(q_s[(row0+8+g)*QSTR + kc]);
            a[2] = __float_as_uint(q_s[(row0+g)*QSTR   + kc + 4]);
            a[3] = __float_as_uint(q_s[(row0+8+g)*QSTR + kc + 4]);
            u32 bb[8][2];
            #pragma unroll
            for (int nt = 0; nt < 8; nt++) {
                int rr = nt*8 + g;
                bb[nt][0] = __float_as_uint(k_s[rr*QSTR + kc]);
                bb[nt][1] = __float_as_uint(k_s[rr*QSTR + kc + 4]);
            }
            #pragma unroll
            for (int nt = 0; nt < 8; nt++)
                mma_tf32(s[nt], a, bb[nt]);
        }

        {
            float m0 = -1e30f, m1 = -1e30f;
            #pragma unroll
            for (int nt = 0; nt < 8; nt++) {
                m0 = fmaxf(m0, fmaxf(s[nt][0], s[nt][1]));
                m1 = fmaxf(m1, fmaxf(s[nt][2], s[nt][3]));
            }
            #pragma unroll
            for (int o = 1; o <= 2; o <<= 1) {
                m0 = fmaxf(m0, __shfl_xor_sync(0xffffffffu, m0, o));
                m1 = fmaxf(m1, __shfl_xor_sync(0xffffffffu, m1, o));
            }
            float mn0 = fmaxf(mr0, m0);
            float mn1 = fmaxf(mr1, m1);
            float sf0 = ex2f(mr0 - mn0);
            float sf1 = ex2f(mr1 - mn1);
            mr0 = mn0; mr1 = mn1;
            float ls0 = 0.f, ls1 = 0.f;
            #pragma unroll
            for (int nt = 0; nt < 8; nt++) {
                float e0 = ex2f(s[nt][0] - mn0);
                float e1 = ex2f(s[nt][1] - mn0);
                float e2 = ex2f(s[nt][2] - mn1);
                float e3 = ex2f(s[nt][3] - mn1);
                ls0 += e0 + e1;  ls1 += e2 + e3;
                s[nt][0] = tf32r(e0);  s[nt][1] = tf32r(e1);
                s[nt][2] = tf32r(e2);  s[nt][3] = tf32r(e3);
            }
            #pragma unroll
            for (int o = 1; o <= 2; o <<= 1) {
                ls0 += __shfl_xor_sync(0xffffffffu, ls0, o);
                ls1 += __shfl_xor_sync(0xffffffffu, ls1, o);
            }
            lr0 = lr0*sf0 + ls0;
            lr1 = lr1*sf1 + ls1;
            #pragma unroll
            for (int nt = 0; nt < 4; nt++) {
                oa[nt][0] *= sf0;  oa[nt][1] *= sf0;
                oa[nt][2] *= sf1;  oa[nt][3] *= sf1;
            }
        }

        #pragma unroll
        for (int k8 = 0; k8 < 8; k8++) {
            float y00 = __shfl_sync(0xffffffffu, s[k8][0], src_lo);
            float y01 = __shfl_sync(0xffffffffu, s[k8][1], src_lo);
            float y10 = __shfl_sync(0xffffffffu, s[k8][0], src_hi);
            float y11 = __shfl_sync(0xffffffffu, s[k8][1], src_hi);
            float z00 = __shfl_sync(0xffffffffu, s[k8][2], src_lo);
            float z01 = __shfl_sync(0xffffffffu, s[k8][3], src_lo);
            float z10 = __shfl_sync(0xffffffffu, s[k8][2], src_hi);
            float z11 = __shfl_sync(0xffffffffu, s[k8][3], src_hi);
            u32 a[4];
            a[0] = __float_as_uint((t & 1) ? y01 : y00);
            a[2] = __float_as_uint((t & 1) ? y11 : y10);
            a[1] = __float_as_uint((t & 1) ? z01 : z00);
            a[3] = __float_as_uint((t & 1) ? z11 : z10);
            u32 bb[4][2];
            #pragma unroll
            for (int nt = 0; nt < 4; nt++) {
                int d = nt*8 + g;
                bb[nt][0] = __float_as_uint(v_s[d*VSTR + k8*8 + t]);
                bb[nt][1] = __float_as_uint(v_s[d*VSTR + k8*8 + t + 4]);
            }
            #pragma unroll
            for (int nt = 0; nt < 4; nt++)
                mma_tf32(oa[nt], a, bb[nt]);
        }
    }

    float i0 = 1.f / lr0;
    float i1 = 1.f / lr1;
    int r = q0 + row0 + g;
    #pragma unroll
    for (int nt = 0; nt < 4; nt++) {
        int col = h*32 + nt*8 + 2*t;
        *(__half2*)(out + ((size_t)b*N_ + r)*C_ + col) =
            __floats2half2_rn(oa[nt][0]*i0, oa[nt][1]*i0);
        *(__half2*)(out + ((size_t)b*N_ + r + 8)*C_ + col) =
            __floats2half2_rn(oa[nt][2]*i1, oa[nt][3]*i1);
    }
}

// ---------------------------------------------------------------------------
// Deformable gather: one warp per (b, n, head); lane = channel d.
// Output fp16 (oproj GEMM X operand).
// ---------------------------------------------------------------------------
__global__ __launch_bounds__(128) void deform_kernel(
    const float* __restrict__ ref, const float* __restrict__ off,
    const float* __restrict__ awl, const float* __restrict__ vp,
    __half* __restrict__ out)
{
    int u = (blockIdx.x << 2) + (threadIdx.x >> 5);
    int lane = threadIdx.x & 31;
    int h  = u & 7;
    int bn = u >> 3;
    int b  = bn >> 10;

    float rx = ref[(size_t)bn*2 + 0]*32.f - 0.5f;
    float ry = ref[(size_t)bn*2 + 1]*32.f - 0.5f;
    const float* offp = off + (size_t)bn*64 + h*8;
    const float* awp  = awl + (size_t)bn*32 + h*4;

    float a0 = awp[0], a1 = awp[1], a2 = awp[2], a3 = awp[3];
    float mx = fmaxf(fmaxf(a0,a1), fmaxf(a2,a3));
    float e0 = __expf(a0-mx), e1 = __expf(a1-mx), e2 = __expf(a2-mx), e3 = __expf(a3-mx);
    float inv = 1.f/(e0+e1+e2+e3);
    float aw4[4] = {e0*inv, e1*inv, e2*inv, e3*inv};

    const float* vb = vp + (size_t)b*N_*C_ + h*32 + lane;
    float acc = 0.f;
    #pragma unroll
    for (int p = 0; p < 4; p++) {
        float gx = rx + offp[p*2+0];
        float gy = ry + offp[p*2+1];
        float x0f = floorf(gx), y0f = floorf(gy);
        float lx = gx - x0f, ly = gy - y0f;
        int x0 = (int)x0f, y0 = (int)y0f;
        float s = 0.f;
        #pragma unroll
        for (int cy = 0; cy < 2; cy++) {
            int yi = y0 + cy;
            float wy = cy ? ly : (1.f - ly);
            bool vy = (yi >= 0) && (yi < 32);
            int yc = min(max(yi, 0), 31);
            #pragma unroll
            for (int cx = 0; cx < 2; cx++) {
                int xi = x0 + cx;
                float wx = cx ? lx : (1.f - lx);
                bool vx = (xi >= 0) && (xi < 32);
                int xc = min(max(xi, 0), 31);
                float val = (vx && vy) ? vb[(size_t)(yc*32 + xc)*C_] : 0.f;
                s = fmaf(val, wx*wy, s);
            }
        }
        acc = fmaf(aw4[p], s, acc);
    }
    out[(size_t)bn*C_ + h*32 + lane] = __float2half_rn(acc);
}

// ---------------------------------------------------------------------------
// Launch
// ---------------------------------------------------------------------------
extern "C" void kernel_launch(void* const* d_in, const int* in_sizes, int n_in,
                              void* d_out, int out_size)
{
    const float* x       = (const float*)d_in[0];
    const float* ref     = (const float*)d_in[1];
    const float* value   = (const float*)d_in[2];
    const float* ln1w    = (const float*)d_in[3];
    const float* ln1b    = (const float*)d_in[4];
    const float* ln2w    = (const float*)d_in[5];
    const float* ln2b    = (const float*)d_in[6];
    const float* ln3w    = (const float*)d_in[7];
    const float* ln3b    = (const float*)d_in[8];
    const float* qkv_w   = (const float*)d_in[9];
    const float* proj_w  = (const float*)d_in[10];
    const float* proj_b  = (const float*)d_in[11];
    const float* off_w   = (const float*)d_in[12];
    const float* off_b   = (const float*)d_in[13];
    const float* aw_w    = (const float*)d_in[14];
    const float* aw_b    = (const float*)d_in[15];
    const float* vproj_w = (const float*)d_in[16];
    const float* vproj_b = (const float*)d_in[17];
    const float* oproj_w = (const float*)d_in[18];
    const float* oproj_b = (const float*)d_in[19];
    const float* fc1_w   = (const float*)d_in[20];
    const float* fc1_b   = (const float*)d_in[21];
    const float* fc2_w   = (const float*)d_in[22];
    const float* fc2_b   = (const float*)d_in[23];
    float* out = (float*)d_out;

    float  *qkvb, *x2, *offb, *awb, *vpb;
    __half *yh, *tmph, *h1h, *wh, *valh;
    cudaGetSymbolAddress((void**)&qkvb, g_qkv);
    cudaGetSymbolAddress((void**)&x2,   g_x2);
    cudaGetSymbolAddress((void**)&offb, g_off);
    cudaGetSymbolAddress((void**)&awb,  g_awl);
    cudaGetSymbolAddress((void**)&vpb,  g_vp);
    cudaGetSymbolAddress((void**)&yh,   g_yh);
    cudaGetSymbolAddress((void**)&tmph, g_tmph);
    cudaGetSymbolAddress((void**)&h1h,  g_h1h);
    cudaGetSymbolAddress((void**)&wh,   g_wh);
    cudaGetSymbolAddress((void**)&valh, g_valh);

    cudaFuncSetAttribute(flash_tc,
        cudaFuncAttributeMaxDynamicSharedMemorySize, FSMEM);
    cudaFuncSetAttribute(gemm_h<0,0>,
        cudaFuncAttributeMaxDynamicSharedMemorySize, GSMEM);
    cudaFuncSetAttribute(gemm_h<1,0>,
        cudaFuncAttributeMaxDynamicSharedMemorySize, GSMEM);
    cudaFuncSetAttribute(gemm_h<0,1>,
        cudaFuncAttributeMaxDynamicSharedMemorySize, GSMEM);

    const __half* wq  = wh + WOFF_QKV;
    const __half* wp  = wh + WOFF_PROJ;
    const __half* wo  = wh + WOFF_OFF;
    const __half* wa  = wh + WOFF_AW;
    const __half* wv  = wh + WOFF_VPROJ;
    const __half* wop = wh + WOFF_OPROJ;
    const __half* w1  = wh + WOFF_FC1;
    const __half* w2  = wh + WOFF_FC2;

    // pre-convert weights + value to fp16
    round_weights_h<<<(WTOT/4 + 255)/256, 256>>>(qkv_w, proj_w, off_w, aw_w,
        vproj_w, oproj_w, fc1_w, fc2_w, wh);
    round_buf_h<<<(M_*C_/4 + 255)/256, 256>>>(value, valh, M_*C_/4);

    // x1 = x + attn(ln1(x))
    ln_kernel<<<M_, 256>>>(x, ln1w, ln1b, yh);
    gemm_h<0,0><<<dim3(6,128), 256, GSMEM>>>(yh, wq, nullptr, nullptr, qkvb, M_, 768, 256, 0);
    flash_tc<<<dim3(N_/FQT, NH_, B_), 256, FSMEM>>>(qkvb, tmph);
    gemm_h<0,0><<<dim3(2,128), 256, GSMEM>>>(tmph, wp, proj_b, x, x2, M_, 256, 256, 0);

    // x2 = x1 + deform(ln2(x1))
    ln_kernel<<<M_, 256>>>(x2, ln2w, ln2b, yh);
    gemm_h<1,0><<<dim3(1,128), 256, GSMEM>>>(yh, wo, off_b, nullptr, offb, M_, 64, 256, 0);
    gemm_h<1,0><<<dim3(1,128), 256, GSMEM>>>(yh, wa, aw_b, nullptr, awb, M_, 32, 256, 0);
    gemm_h<0,0><<<dim3(2,128), 256, GSMEM>>>(valh, wv, vproj_b, nullptr, vpb, M_, 256, 256, 0);
    deform_kernel<<<32768, 128>>>(ref, offb, awb, vpb, tmph);
    gemm_h<0,0><<<dim3(2,128), 256, GSMEM>>>(tmph, wop, oproj_b, x2, x2, M_, 256, 256, 0);

    // out = x2 + fc2(gelu(fc1(ln3(x2))))
    ln_kernel<<<M_, 256>>>(x2, ln3w, ln3b, yh);
    gemm_h<0,1><<<dim3(8,128), 256, GSMEM>>>(yh, w1, fc1_b, nullptr, h1h, M_, 1024, 256, 1);
    gemm_h<0,0><<<dim3(2,128), 256, GSMEM>>>(h1h, w2, fc2_b, x2, out, M_, 256, 1024, 0);
}

// round 13
// speedup vs baseline: 1.5034x; 1.1886x over previous
#include <cuda_runtime.h>
#include <cuda_fp16.h>
#include <cstdint>
#include <math.h>

typedef unsigned int u32;

// Problem constants
#define B_  16
#define N_  1024
#define C_  256
#define NH_ 8
#define DH_ 32
#define M_  (B_*N_)      // 16384 rows
#define HID_ 1024

// Weight segment sizes (floats)
#define WSZ_QKV   (3*C_*C_)
#define WSZ_PROJ  (C_*C_)
#define WSZ_OFF   (64*C_)
#define WSZ_AW    (32*C_)
#define WSZ_VPROJ (C_*C_)
#define WSZ_OPROJ (C_*C_)
#define WSZ_FC1   (HID_*C_)
#define WSZ_FC2   (C_*HID_)
#define WOFF_QKV   0
#define WOFF_PROJ  (WOFF_QKV  + WSZ_QKV)
#define WOFF_OFF   (WOFF_PROJ + WSZ_PROJ)
#define WOFF_AW    (WOFF_OFF  + WSZ_OFF)
#define WOFF_VPROJ (WOFF_AW   + WSZ_AW)
#define WOFF_OPROJ (WOFF_VPROJ+ WSZ_VPROJ)
#define WOFF_FC1   (WOFF_OPROJ+ WSZ_OPROJ)
#define WOFF_FC2   (WOFF_FC1  + WSZ_FC1)
#define WTOT       (WOFF_FC2  + WSZ_FC2)   // 942080

// ---------------------------------------------------------------------------
// Scratch (static __device__ arrays; no allocations allowed)
// ---------------------------------------------------------------------------
__device__ float  g_x2   [M_*C_];
__device__ float  g_vp   [M_*C_];
__device__ float  g_offaw[M_*96];
__device__ float  g_oab  [96];
__device__ __half g_qkvh [M_*3*C_];   // qkv projection (half)
__device__ __half g_yh   [M_*C_];     // LN output (half, GEMM X)
__device__ __half g_tmph [M_*C_];     // flash-out / deform-out (half, GEMM X)
__device__ __half g_h1h  [M_*HID_];   // fc1 output (half, fc2 X)
__device__ __half g_wh   [WTOT];      // fp16 weights
__device__ __half g_valh [M_*C_];     // fp16 value input

// ---------------------------------------------------------------------------
// helpers
// ---------------------------------------------------------------------------
__device__ __forceinline__ float ex2f(float x) {
    float y;
    asm("ex2.approx.f32 %0, %1;" : "=f"(y) : "f"(x));
    return y;
}

__device__ __forceinline__ void mma_f16(float (&d)[4],
                                        const u32 (&a)[4],
                                        const u32 (&b)[2]) {
    asm volatile(
        "mma.sync.aligned.m16n8k16.row.col.f32.f16.f16.f32 "
        "{%0,%1,%2,%3}, {%4,%5,%6,%7}, {%8,%9}, {%0,%1,%2,%3};"
        : "+f"(d[0]), "+f"(d[1]), "+f"(d[2]), "+f"(d[3])
        : "r"(a[0]), "r"(a[1]), "r"(a[2]), "r"(a[3]),
          "r"(b[0]), "r"(b[1]));
}

__device__ __forceinline__ u32 smem_u32(const void* p) {
    return (u32)__cvta_generic_to_shared(p);
}

__device__ __forceinline__ u32 packh2(float a, float b) {
    __half2 h = __floats2half2_rn(a, b);
    return *(u32*)&h;
}

// ---------------------------------------------------------------------------
// Weight / buffer conversion to fp16 (RN)
// ---------------------------------------------------------------------------
__global__ __launch_bounds__(256) void round_weights_h(
    const float* __restrict__ qkv_w, const float* __restrict__ proj_w,
    const float* __restrict__ off_w, const float* __restrict__ aw_w,
    const float* __restrict__ vproj_w, const float* __restrict__ oproj_w,
    const float* __restrict__ fc1_w, const float* __restrict__ fc2_w,
    __half* __restrict__ dst)
{
    int i4 = blockIdx.x*256 + threadIdx.x;
    if (i4 >= WTOT/4) return;
    int i = i4*4;
    const float* src;
    int off;
    if      (i < WOFF_PROJ)  { src = qkv_w;   off = i - WOFF_QKV;  }
    else if (i < WOFF_OFF)   { src = proj_w;  off = i - WOFF_PROJ; }
    else if (i < WOFF_AW)    { src = off_w;   off = i - WOFF_OFF;  }
    else if (i < WOFF_VPROJ) { src = aw_w;    off = i - WOFF_AW;   }
    else if (i < WOFF_OPROJ) { src = vproj_w; off = i - WOFF_VPROJ;}
    else if (i < WOFF_FC1)   { src = oproj_w; off = i - WOFF_OPROJ;}
    else if (i < WOFF_FC2)   { src = fc1_w;   off = i - WOFF_FC1;  }
    else                     { src = fc2_w;   off = i - WOFF_FC2;  }
    float4 v = *(const float4*)(src + off);
    __half2 h0 = __floats2half2_rn(v.x, v.y);
    __half2 h1 = __floats2half2_rn(v.z, v.w);
    *(uint2*)(dst + i) = make_uint2(*(u32*)&h0, *(u32*)&h1);
}

__global__ __launch_bounds__(256) void round_buf_h(
    const float* __restrict__ src, __half* __restrict__ dst, int n4)
{
    int i4 = blockIdx.x*256 + threadIdx.x;
    if (i4 >= n4) return;
    float4 v = *(const float4*)(src + i4*4);
    __half2 h0 = __floats2half2_rn(v.x, v.y);
    __half2 h1 = __floats2half2_rn(v.z, v.w);
    *(uint2*)(dst + i4*4) = make_uint2(*(u32*)&h0, *(u32*)&h1);
}

__global__ void concat_bias(const float* __restrict__ ob,
                            const float* __restrict__ ab,
                            float* __restrict__ dst)
{
    int i = threadIdx.x;
    if (i < 64) dst[i] = ob[i];
    else if (i < 96) dst[i] = ab[i-64];
}

// ---------------------------------------------------------------------------
// LayerNorm: one block per row. Output fp16 (GEMM X operand only).
// ---------------------------------------------------------------------------
__global__ __launch_bounds__(256) void ln_kernel(
    const float* __restrict__ in, const float* __restrict__ w,
    const float* __restrict__ b, __half* __restrict__ out)
{
    __shared__ float red[8];
    int row = blockIdx.x;
    int t = threadIdx.x;
    float v = in[(size_t)row*C_ + t];
    float s = v;
    #pragma unroll
    for (int o = 16; o; o >>= 1) s += __shfl_xor_sync(0xffffffffu, s, o);
    if ((t & 31) == 0) red[t >> 5] = s;
    __syncthreads();
    float tot = 0.f;
    #pragma unroll
    for (int i = 0; i < 8; i++) tot += red[i];
    float mean = tot * (1.0f/256.0f);
    __syncthreads();
    float d = v - mean;
    s = d*d;
    #pragma unroll
    for (int o = 16; o; o >>= 1) s += __shfl_xor_sync(0xffffffffu, s, o);
    if ((t & 31) == 0) red[t >> 5] = s;
    __syncthreads();
    tot = 0.f;
    #pragma unroll
    for (int i = 0; i < 8; i++) tot += red[i];
    float rs = rsqrtf(tot*(1.0f/256.0f) + 1e-5f);
    out[(size_t)row*C_ + t] = __float2half_rn(d*rs*w[t] + b[t]);
}

// ---------------------------------------------------------------------------
// fp16 tensor-core GEMM, cp.async 2-stage double buffer.
// Block 128x128, BK=32, 8 warps 2x4, warp tile 64x32 (m16n8k16).
// OUTH: half output; else fp32.
// ---------------------------------------------------------------------------
#define HSTRW 20
#define HTILE (128*HSTRW)             // words per operand-stage (2560)
#define GSMEM (2*2*HTILE*4)           // 40960 B

template <int PAD, int OUTH>
__global__ __launch_bounds__(256, 2) void gemm_h(
    const __half* __restrict__ X, const __half* __restrict__ W,
    const float* __restrict__ bias, const float* __restrict__ res,
    void* __restrict__ Yv, int M, int Nout, int K, int act)
{
    extern __shared__ u32 hsm[];
    int tid  = threadIdx.x;
    int warp = tid >> 5, lane = tid & 31;
    int g = lane >> 2, t = lane & 3;
    int wm0 = (warp >> 2) * 64;
    int wn0 = (warp & 3) * 32;
    int m0 = blockIdx.y * 128, n0 = blockIdx.x * 128;
    u32 sb = smem_u32(hsm);

    auto issue_tile = [&](int s, int k0 /*halves*/) {
        #pragma unroll
        for (int i = 0; i < 2; i++) {
            int idx = tid + (i << 8);
            int r  = idx >> 2;
            int c8 = (idx & 3) << 3;
            u32 dX = sb + (u32)((s*2*HTILE) + r*HSTRW + (c8 >> 1))*4u;
            const __half* gX = X + (size_t)(m0+r)*K + k0 + c8;
            asm volatile("cp.async.ca.shared.global [%0], [%1], 16;"
                         :: "r"(dX), "l"(gX));
            u32 dW = sb + (u32)((s*2*HTILE) + HTILE + r*HSTRW + (c8 >> 1))*4u;
            const __half* gW = W + (size_t)(n0+r)*K + k0 + c8;
            if (PAD) {
                int vld = (n0 + r < Nout) ? 16 : 0;
                asm volatile("cp.async.ca.shared.global [%0], [%1], 16, %2;"
                             :: "r"(dW), "l"(gW), "r"(vld));
            } else {
                asm volatile("cp.async.ca.shared.global [%0], [%1], 16;"
                             :: "r"(dW), "l"(gW));
            }
        }
    };

    float acc[4][4][4];
    #pragma unroll
    for (int mt = 0; mt < 4; mt++)
        #pragma unroll
        for (int nt = 0; nt < 4; nt++)
            #pragma unroll
            for (int c = 0; c < 4; c++) acc[mt][nt][c] = 0.f;

    issue_tile(0, 0);
    asm volatile("cp.async.commit_group;" ::: "memory");
    issue_tile(1, 32);
    asm volatile("cp.async.commit_group;" ::: "memory");

    int nk = K >> 5;
    for (int it = 0; it < nk; it++) {
        asm volatile("cp.async.wait_group 1;" ::: "memory");
        __syncthreads();

        const u32* sX = hsm + (it & 1)*2*HTILE;
        const u32* sW = sX + HTILE;
        #pragma unroll
        for (int ks = 0; ks < 2; ks++) {
            int kc = ks*8 + t;
            u32 a[4][4];
            #pragma unroll
            for (int mt = 0; mt < 4; mt++) {
                int r = wm0 + mt*16 + g;
                a[mt][0] = sX[r*HSTRW     + kc];
                a[mt][1] = sX[(r+8)*HSTRW + kc];
                a[mt][2] = sX[r*HSTRW     + kc + 4];
                a[mt][3] = sX[(r+8)*HSTRW + kc + 4];
            }
            u32 bb[4][2];
            #pragma unroll
            for (int nt = 0; nt < 4; nt++) {
                int r = wn0 + nt*8 + g;
                bb[nt][0] = sW[r*HSTRW + kc];
                bb[nt][1] = sW[r*HSTRW + kc + 4];
            }
            #pragma unroll
            for (int mt = 0; mt < 4; mt++)
                #pragma unroll
                for (int nt = 0; nt < 4; nt++)
                    mma_f16(acc[mt][nt], a[mt], bb[nt]);
        }
        __syncthreads();

        int k2 = (it + 2) << 5;
        if (k2 < K) issue_tile(it & 1, k2);
        asm volatile("cp.async.commit_group;" ::: "memory");
    }

    float* Yf = (float*)Yv;
    __half* Yh = (__half*)Yv;
    #pragma unroll
    for (int mt = 0; mt < 4; mt++) {
        #pragma unroll
        for (int nt = 0; nt < 4; nt++) {
            int n = n0 + wn0 + nt*8 + 2*t;
            if (PAD && n >= Nout) continue;
            #pragma unroll
            for (int h2 = 0; h2 < 2; h2++) {
                int m = m0 + wm0 + mt*16 + g + h2*8;
                float v0 = acc[mt][nt][h2*2 + 0];
                float v1 = acc[mt][nt][h2*2 + 1];
                if (bias) { v0 += bias[n]; v1 += bias[n+1]; }
                if (act)  { v0 *= normcdff(v0); v1 *= normcdff(v1); }
                if (res)  { v0 += res[(size_t)m*Nout + n];
                            v1 += res[(size_t)m*Nout + n + 1]; }
                if (OUTH) {
                    __half2 hv = __floats2half2_rn(v0, v1);
                    *(__half2*)(Yh + (size_t)m*Nout + n) = hv;
                } else {
                    *(float2*)(Yf + (size_t)m*Nout + n) = make_float2(v0, v1);
                }
            }
        }
    }
}

// ---------------------------------------------------------------------------
// Flash attention v4: all-fp16 MMA (m16n8k16), double-buffered K/V,
// ONE barrier per chunk, base-2 online softmax, NO shuffle transpose
// (fp16 S-accumulator layout == fp16 A-fragment layout after half2 pack).
// qkv is fp16: (b*N+n)*768 + s*256 + h*32 + d. Output fp16.
// ---------------------------------------------------------------------------
#define FQT  128
#define FKC  64
#define QSTRW 20                      // words per 32-half row (16 + pad 4)
#define VSTRW 36                      // words per 64-half V row (32 + pad 4)
#define QWORDS (FQT*QSTRW)            // 2560
#define KVWORDS (FKC*QSTRW + 32*VSTRW)  // 1280 + 1152 = 2432
#define FSMEM ((QWORDS + 2*KVWORDS)*4)  // 29696 B

__global__ __launch_bounds__(256, 2) void flash_h(
    const __half* __restrict__ qkvh, __half* __restrict__ out)
{
    extern __shared__ u32 fsm[];
    u32* q_s = fsm;                   // FQT x QSTRW
    u32* kvb = fsm + QWORDS;          // 2 x KVWORDS

    int tid  = threadIdx.x;
    int warp = tid >> 5, lane = tid & 31;
    int g = lane >> 2, t = lane & 3;
    int b = blockIdx.z, h = blockIdx.y;
    int q0 = blockIdx.x * FQT;
    const __half* qb = qkvh + (size_t)b*N_*768 + h*32;
    // 32^-0.5 * log2(e) folded into Q (applied in half)
    const __half2 qsc2 = __half2half2(__float2half_rn(0.25506704f));

    // ---- load Q tile (128 x 32 halves), scaled ----
    #pragma unroll
    for (int i = 0; i < 2; i++) {
        int idx = tid + (i << 8);
        int r  = idx >> 2;
        int w4 = (idx & 3) << 2;      // word offset 0,4,8,12
        uint4 v = *(const uint4*)(qb + (size_t)(q0+r)*768 + w4*2);
        __half2* hv = (__half2*)&v;
        hv[0] = __hmul2(hv[0], qsc2);
        hv[1] = __hmul2(hv[1], qsc2);
        hv[2] = __hmul2(hv[2], qsc2);
        hv[3] = __hmul2(hv[3], qsc2);
        q_s[r*QSTRW + w4 + 0] = v.x;
        q_s[r*QSTRW + w4 + 1] = v.y;
        q_s[r*QSTRW + w4 + 2] = v.z;
        q_s[r*QSTRW + w4 + 3] = v.w;
    }

    int row0 = warp * 16;
    float oa[4][4];
    #pragma unroll
    for (int nt = 0; nt < 4; nt++)
        #pragma unroll
        for (int c = 0; c < 4; c++) oa[nt][c] = 0.f;
    float mr0 = -1e30f, mr1 = -1e30f, lr0 = 0.f, lr1 = 0.f;

    // staging indices
    int rK = tid >> 2, w4K = (tid & 3) << 2;      // K: row 0..63, words 0,4,8,12
    int keyV = tid >> 2, dh0 = (tid & 3) << 3;    // V: key 0..63, dh 0,8,16,24

    // prefetch chunk 0
    uint4 kf = *(const uint4*)(qb + (size_t)rK*768 + 256 + w4K*2);
    uint4 vf = *(const uint4*)(qb + (size_t)keyV*768 + 512 + dh0);

    for (int ic = 0; ic < N_/FKC; ic++) {
        u32* k_s = kvb + (ic & 1)*KVWORDS;
        u32* v_s = k_s + FKC*QSTRW;
        __half* v_sh = (__half*)v_s;

        // stage K (pure copy)
        k_s[rK*QSTRW + w4K + 0] = kf.x;
        k_s[rK*QSTRW + w4K + 1] = kf.y;
        k_s[rK*QSTRW + w4K + 2] = kf.z;
        k_s[rK*QSTRW + w4K + 3] = kf.w;
        // stage V transposed: [dh][key] halves
        {
            __half* hv = (__half*)&vf;
            #pragma unroll
            for (int j = 0; j < 8; j++)
                v_sh[(dh0 + j)*(2*VSTRW) + keyV] = hv[j];
        }

        // prefetch chunk ic+1
        int ktn = (ic + 1) * FKC;
        if (ktn < N_) {
            kf = *(const uint4*)(qb + (size_t)(ktn+rK)*768 + 256 + w4K*2);
            vf = *(const uint4*)(qb + (size_t)(ktn+keyV)*768 + 512 + dh0);
        }
        __syncthreads();

        // ---- S = Q @ K^T (fp16 mma, 2 k-steps) ----
        float s[8][4];
        #pragma unroll
        for (int nt = 0; nt < 8; nt++)
            #pragma unroll
            for (int c = 0; c < 4; c++) s[nt][c] = 0.f;

        #pragma unroll
        for (int ks = 0; ks < 2; ks++) {
            int kc = ks*8 + t;
            u32 a[4];
            a[0] = q_s[(row0+g)*QSTRW   + kc];
            a[1] = q_s[(row0+8+g)*QSTRW + kc];
            a[2] = q_s[(row0+g)*QSTRW   + kc + 4];
            a[3] = q_s[(row0+8+g)*QSTRW + kc + 4];
            #pragma unroll
            for (int nt = 0; nt < 8; nt++) {
                u32 bb[2];
                bb[0] = k_s[(nt*8+g)*QSTRW + kc];
                bb[1] = k_s[(nt*8+g)*QSTRW + kc + 4];
                mma_f16(s[nt], a, bb);
            }
        }

        // ---- online softmax in base-2 ----
        u32 pl[8], ph[8];
        {
            float m0 = -1e30f, m1 = -1e30f;
            #pragma unroll
            for (int nt = 0; nt < 8; nt++) {
                m0 = fmaxf(m0, fmaxf(s[nt][0], s[nt][1]));
                m1 = fmaxf(m1, fmaxf(s[nt][2], s[nt][3]));
            }
            #pragma unroll
            for (int o = 1; o <= 2; o <<= 1) {
                m0 = fmaxf(m0, __shfl_xor_sync(0xffffffffu, m0, o));
                m1 = fmaxf(m1, __shfl_xor_sync(0xffffffffu, m1, o));
            }
            float mn0 = fmaxf(mr0, m0);
            float mn1 = fmaxf(mr1, m1);
            float sf0 = ex2f(mr0 - mn0);
            float sf1 = ex2f(mr1 - mn1);
            mr0 = mn0; mr1 = mn1;
            float ls0 = 0.f, ls1 = 0.f;
            #pragma unroll
            for (int nt = 0; nt < 8; nt++) {
                float e0 = ex2f(s[nt][0] - mn0);
                float e1 = ex2f(s[nt][1] - mn0);
                float e2 = ex2f(s[nt][2] - mn1);
                float e3 = ex2f(s[nt][3] - mn1);
                ls0 += e0 + e1;  ls1 += e2 + e3;
                pl[nt] = packh2(e0, e1);
                ph[nt] = packh2(e2, e3);
            }
            #pragma unroll
            for (int o = 1; o <= 2; o <<= 1) {
                ls0 += __shfl_xor_sync(0xffffffffu, ls0, o);
                ls1 += __shfl_xor_sync(0xffffffffu, ls1, o);
            }
            lr0 = lr0*sf0 + ls0;
            lr1 = lr1*sf1 + ls1;
            #pragma unroll
            for (int nt = 0; nt < 4; nt++) {
                oa[nt][0] *= sf0;  oa[nt][1] *= sf0;
                oa[nt][2] *= sf1;  oa[nt][3] *= sf1;
            }
        }

        // ---- O += P @ V (fp16 mma, 4 k-chunks of 16 keys, no shuffles) ----
        #pragma unroll
        for (int j = 0; j < 4; j++) {
            u32 a[4];
            a[0] = pl[2*j];       // row g,   keys 16j+2t,+1
            a[1] = ph[2*j];       // row g+8, keys 16j+2t,+1
            a[2] = pl[2*j+1];     // row g,   keys 16j+8+2t,+1
            a[3] = ph[2*j+1];     // row g+8, keys 16j+8+2t,+1
            #pragma unroll
            for (int nt = 0; nt < 4; nt++) {
                int d = nt*8 + g;
                u32 bb[2];
                bb[0] = v_s[d*VSTRW + j*8 + t];
                bb[1] = v_s[d*VSTRW + j*8 + t + 4];
                mma_f16(oa[nt], a, bb);
            }
        }
    }

    float i0 = 1.f / lr0;
    float i1 = 1.f / lr1;
    int r = q0 + row0 + g;
    #pragma unroll
    for (int nt = 0; nt < 4; nt++) {
        int col = h*32 + nt*8 + 2*t;
        *(__half2*)(out + ((size_t)b*N_ + r)*C_ + col) =
            __floats2half2_rn(oa[nt][0]*i0, oa[nt][1]*i0);
        *(__half2*)(out + ((size_t)b*N_ + r + 8)*C_ + col) =
            __floats2half2_rn(oa[nt][2]*i1, oa[nt][3]*i1);
    }
}

// ---------------------------------------------------------------------------
// Deformable gather: one warp per (b, n, head); lane = channel d.
// offsets/logits come from the merged [M,96] buffer. Output fp16.
// ---------------------------------------------------------------------------
__global__ __launch_bounds__(128) void deform_kernel(
    const float* __restrict__ ref, const float* __restrict__ offaw,
    const float* __restrict__ vp, __half* __restrict__ out)
{
    int u = (blockIdx.x << 2) + (threadIdx.x >> 5);
    int lane = threadIdx.x & 31;
    int h  = u & 7;
    int bn = u >> 3;
    int b  = bn >> 10;

    float rx = ref[(size_t)bn*2 + 0]*32.f - 0.5f;
    float ry = ref[(size_t)bn*2 + 1]*32.f - 0.5f;
    const float* offp = offaw + (size_t)bn*96 + h*8;
    const float* awp  = offaw + (size_t)bn*96 + 64 + h*4;

    float a0 = awp[0], a1 = awp[1], a2 = awp[2], a3 = awp[3];
    float mx = fmaxf(fmaxf(a0,a1), fmaxf(a2,a3));
    float e0 = __expf(a0-mx), e1 = __expf(a1-mx), e2 = __expf(a2-mx), e3 = __expf(a3-mx);
    float inv = 1.f/(e0+e1+e2+e3);
    float aw4[4] = {e0*inv, e1*inv, e2*inv, e3*inv};

    const float* vb = vp + (size_t)b*N_*C_ + h*32 + lane;
    float acc = 0.f;
    #pragma unroll
    for (int p = 0; p < 4; p++) {
        float gx = rx + offp[p*2+0];
        float gy = ry + offp[p*2+1];
        float x0f = floorf(gx), y0f = floorf(gy);
        float lx = gx - x0f, ly = gy - y0f;
        int x0 = (int)x0f, y0 = (int)y0f;
        float s = 0.f;
        #pragma unroll
        for (int cy = 0; cy < 2; cy++) {
            int yi = y0 + cy;
            float wy = cy ? ly : (1.f - ly);
            bool vy = (yi >= 0) && (yi < 32);
            int yc = min(max(yi, 0), 31);
            #pragma unroll
            for (int cx = 0; cx < 2; cx++) {
                int xi = x0 + cx;
                float wx = cx ? lx : (1.f - lx);
                bool vx = (xi >= 0) && (xi < 32);
                int xc = min(max(xi, 0), 31);
                float val = (vx && vy) ? vb[(size_t)(yc*32 + xc)*C_] : 0.f;
                s = fmaf(val, wx*wy, s);
            }
        }
        acc = fmaf(aw4[p], s, acc);
    }
    out[(size_t)bn*C_ + h*32 + lane] = __float2half_rn(acc);
}

// ---------------------------------------------------------------------------
// Launch
// ---------------------------------------------------------------------------
extern "C" void kernel_launch(void* const* d_in, const int* in_sizes, int n_in,
                              void* d_out, int out_size)
{
    const float* x       = (const float*)d_in[0];
    const float* ref     = (const float*)d_in[1];
    const float* value   = (const float*)d_in[2];
    const float* ln1w    = (const float*)d_in[3];
    const float* ln1b    = (const float*)d_in[4];
    const float* ln2w    = (const float*)d_in[5];
    const float* ln2b    = (const float*)d_in[6];
    const float* ln3w    = (const float*)d_in[7];
    const float* ln3b    = (const float*)d_in[8];
    const float* qkv_w   = (const float*)d_in[9];
    const float* proj_w  = (const float*)d_in[10];
    const float* proj_b  = (const float*)d_in[11];
    const float* off_w   = (const float*)d_in[12];
    const float* off_b   = (const float*)d_in[13];
    const float* aw_w    = (const float*)d_in[14];
    const float* aw_b    = (const float*)d_in[15];
    const float* vproj_w = (const float*)d_in[16];
    const float* vproj_b = (const float*)d_in[17];
    const float* oproj_w = (const float*)d_in[18];
    const float* oproj_b = (const float*)d_in[19];
    const float* fc1_w   = (const float*)d_in[20];
    const float* fc1_b   = (const float*)d_in[21];
    const float* fc2_w   = (const float*)d_in[22];
    const float* fc2_b   = (const float*)d_in[23];
    float* out = (float*)d_out;

    float  *x2, *vpb, *offaw, *oab;
    __half *qkvh, *yh, *tmph, *h1h, *wh, *valh;
    cudaGetSymbolAddress((void**)&x2,    g_x2);
    cudaGetSymbolAddress((void**)&vpb,   g_vp);
    cudaGetSymbolAddress((void**)&offaw, g_offaw);
    cudaGetSymbolAddress((void**)&oab,   g_oab);
    cudaGetSymbolAddress((void**)&qkvh,  g_qkvh);
    cudaGetSymbolAddress((void**)&yh,    g_yh);
    cudaGetSymbolAddress((void**)&tmph,  g_tmph);
    cudaGetSymbolAddress((void**)&h1h,   g_h1h);
    cudaGetSymbolAddress((void**)&wh,    g_wh);
    cudaGetSymbolAddress((void**)&valh,  g_valh);

    cudaFuncSetAttribute(flash_h,
        cudaFuncAttributeMaxDynamicSharedMemorySize, FSMEM);
    cudaFuncSetAttribute(gemm_h<0,0>,
        cudaFuncAttributeMaxDynamicSharedMemorySize, GSMEM);
    cudaFuncSetAttribute(gemm_h<1,0>,
        cudaFuncAttributeMaxDynamicSharedMemorySize, GSMEM);
    cudaFuncSetAttribute(gemm_h<0,1>,
        cudaFuncAttributeMaxDynamicSharedMemorySize, GSMEM);

    const __half* wq  = wh + WOFF_QKV;
    const __half* wp  = wh + WOFF_PROJ;
    const __half* woa = wh + WOFF_OFF;    // off||aw rows contiguous (96 rows)
    const __half* wv  = wh + WOFF_VPROJ;
    const __half* wop = wh + WOFF_OPROJ;
    const __half* w1  = wh + WOFF_FC1;
    const __half* w2  = wh + WOFF_FC2;

    // pre-convert weights + value to fp16; build merged off/aw bias
    round_weights_h<<<(WTOT/4 + 255)/256, 256>>>(qkv_w, proj_w, off_w, aw_w,
        vproj_w, oproj_w, fc1_w, fc2_w, wh);
    round_buf_h<<<(M_*C_/4 + 255)/256, 256>>>(value, valh, M_*C_/4);
    concat_bias<<<1, 96>>>(off_b, aw_b, oab);

    // x1 = x + attn(ln1(x))
    ln_kernel<<<M_, 256>>>(x, ln1w, ln1b, yh);
    gemm_h<0,1><<<dim3(6,128), 256, GSMEM>>>(yh, wq, nullptr, nullptr, qkvh, M_, 768, 256, 0);
    flash_h<<<dim3(N_/FQT, NH_, B_), 256, FSMEM>>>(qkvh, tmph);
    gemm_h<0,0><<<dim3(2,128), 256, GSMEM>>>(tmph, wp, proj_b, x, x2, M_, 256, 256, 0);

    // x2 = x1 + deform(ln2(x1))
    ln_kernel<<<M_, 256>>>(x2, ln2w, ln2b, yh);
    gemm_h<1,0><<<dim3(1,128), 256, GSMEM>>>(yh, woa, oab, nullptr, offaw, M_, 96, 256, 0);
    gemm_h<0,0><<<dim3(2,128), 256, GSMEM>>>(valh, wv, vproj_b, nullptr, vpb, M_, 256, 256, 0);
    deform_kernel<<<32768, 128>>>(ref, offaw, vpb, tmph);
    gemm_h<0,0><<<dim3(2,128), 256, GSMEM>>>(tmph, wop, oproj_b, x2, x2, M_, 256, 256, 0);

    // out = x2 + fc2(gelu(fc1(ln3(x2))))
    ln_kernel<<<M_, 256>>>(x2, ln3w, ln3b, yh);
    gemm_h<0,1><<<dim3(8,128), 256, GSMEM>>>(yh, w1, fc1_b, nullptr, h1h, M_, 1024, 256, 1);
    gemm_h<0,0><<<dim3(2,128), 256, GSMEM>>>(h1h, w2, fc2_b, x2, out, M_, 256, 1024, 0);
}

// round 14
// speedup vs baseline: 1.6212x; 1.0784x over previous
#include <cuda_runtime.h>
#include <cuda_fp16.h>
#include <cstdint>
#include <math.h>

typedef unsigned int u32;

// Problem constants
#define B_  16
#define N_  1024
#define C_  256
#define NH_ 8
#define DH_ 32
#define M_  (B_*N_)      // 16384 rows
#define HID_ 1024

// Weight segment sizes (floats)
#define WSZ_QKV   (3*C_*C_)
#define WSZ_PROJ  (C_*C_)
#define WSZ_OFF   (64*C_)
#define WSZ_AW    (32*C_)
#define WSZ_VPROJ (C_*C_)
#define WSZ_OPROJ (C_*C_)
#define WSZ_FC1   (HID_*C_)
#define WSZ_FC2   (C_*HID_)
#define WOFF_QKV   0
#define WOFF_PROJ  (WOFF_QKV  + WSZ_QKV)
#define WOFF_OFF   (WOFF_PROJ + WSZ_PROJ)
#define WOFF_AW    (WOFF_OFF  + WSZ_OFF)
#define WOFF_VPROJ (WOFF_AW   + WSZ_AW)
#define WOFF_OPROJ (WOFF_VPROJ+ WSZ_VPROJ)
#define WOFF_FC1   (WOFF_OPROJ+ WSZ_OPROJ)
#define WOFF_FC2   (WOFF_FC1  + WSZ_FC1)
#define WTOT       (WOFF_FC2  + WSZ_FC2)   // 942080

// ---------------------------------------------------------------------------
// Scratch (static __device__ arrays; no allocations allowed)
// ---------------------------------------------------------------------------
__device__ float  g_x2   [M_*C_];
__device__ float  g_vp   [M_*C_];
__device__ float  g_offaw[M_*96];
__device__ float  g_oab  [96];
__device__ __half g_qkvh [M_*3*C_];   // qkv projection (half)
__device__ __half g_yh   [M_*C_];     // LN output (half, GEMM X)
__device__ __half g_tmph [M_*C_];     // flash-out / deform-out (half, GEMM X)
__device__ __half g_h1h  [M_*HID_];   // fc1 output (half, fc2 X)
__device__ __half g_wh   [WTOT];      // fp16 weights
__device__ __half g_valh [M_*C_];     // fp16 value input

// ---------------------------------------------------------------------------
// helpers
// ---------------------------------------------------------------------------
__device__ __forceinline__ float ex2f(float x) {
    float y;
    asm("ex2.approx.f32 %0, %1;" : "=f"(y) : "f"(x));
    return y;
}

__device__ __forceinline__ void mma_f16(float (&d)[4],
                                        const u32 (&a)[4],
                                        const u32 (&b)[2]) {
    asm volatile(
        "mma.sync.aligned.m16n8k16.row.col.f32.f16.f16.f32 "
        "{%0,%1,%2,%3}, {%4,%5,%6,%7}, {%8,%9}, {%0,%1,%2,%3};"
        : "+f"(d[0]), "+f"(d[1]), "+f"(d[2]), "+f"(d[3])
        : "r"(a[0]), "r"(a[1]), "r"(a[2]), "r"(a[3]),
          "r"(b[0]), "r"(b[1]));
}

__device__ __forceinline__ u32 smem_u32(const void* p) {
    return (u32)__cvta_generic_to_shared(p);
}

__device__ __forceinline__ u32 packh2(float a, float b) {
    __half2 h = __floats2half2_rn(a, b);
    return *(u32*)&h;
}

// ---------------------------------------------------------------------------
// Weight / buffer conversion to fp16 (RN)
// ---------------------------------------------------------------------------
__global__ __launch_bounds__(256) void round_weights_h(
    const float* __restrict__ qkv_w, const float* __restrict__ proj_w,
    const float* __restrict__ off_w, const float* __restrict__ aw_w,
    const float* __restrict__ vproj_w, const float* __restrict__ oproj_w,
    const float* __restrict__ fc1_w, const float* __restrict__ fc2_w,
    __half* __restrict__ dst)
{
    int i4 = blockIdx.x*256 + threadIdx.x;
    if (i4 >= WTOT/4) return;
    int i = i4*4;
    const float* src;
    int off;
    if      (i < WOFF_PROJ)  { src = qkv_w;   off = i - WOFF_QKV;  }
    else if (i < WOFF_OFF)   { src = proj_w;  off = i - WOFF_PROJ; }
    else if (i < WOFF_AW)    { src = off_w;   off = i - WOFF_OFF;  }
    else if (i < WOFF_VPROJ) { src = aw_w;    off = i - WOFF_AW;   }
    else if (i < WOFF_OPROJ) { src = vproj_w; off = i - WOFF_VPROJ;}
    else if (i < WOFF_FC1)   { src = oproj_w; off = i - WOFF_OPROJ;}
    else if (i < WOFF_FC2)   { src = fc1_w;   off = i - WOFF_FC1;  }
    else                     { src = fc2_w;   off = i - WOFF_FC2;  }
    float4 v = *(const float4*)(src + off);
    __half2 h0 = __floats2half2_rn(v.x, v.y);
    __half2 h1 = __floats2half2_rn(v.z, v.w);
    *(uint2*)(dst + i) = make_uint2(*(u32*)&h0, *(u32*)&h1);
}

__global__ __launch_bounds__(256) void round_buf_h(
    const float* __restrict__ src, __half* __restrict__ dst, int n4)
{
    int i4 = blockIdx.x*256 + threadIdx.x;
    if (i4 >= n4) return;
    float4 v = *(const float4*)(src + i4*4);
    __half2 h0 = __floats2half2_rn(v.x, v.y);
    __half2 h1 = __floats2half2_rn(v.z, v.w);
    *(uint2*)(dst + i4*4) = make_uint2(*(u32*)&h0, *(u32*)&h1);
}

__global__ void concat_bias(const float* __restrict__ ob,
                            const float* __restrict__ ab,
                            float* __restrict__ dst)
{
    int i = threadIdx.x;
    if (i < 64) dst[i] = ob[i];
    else if (i < 96) dst[i] = ab[i-64];
}

// ---------------------------------------------------------------------------
// LayerNorm, warp-per-row: lane holds 8 consecutive floats, all reductions
// via shuffles (no smem/barriers). 8 rows per 256-thread block.
// Output fp16 (GEMM X operand only).
// ---------------------------------------------------------------------------
__global__ __launch_bounds__(256) void ln_kernel(
    const float* __restrict__ in, const float* __restrict__ w,
    const float* __restrict__ b, __half* __restrict__ out)
{
    int warp = threadIdx.x >> 5, lane = threadIdx.x & 31;
    int row = blockIdx.x*8 + warp;
    const float* p = in + (size_t)row*C_ + lane*8;
    float4 v0 = *(const float4*)(p);
    float4 v1 = *(const float4*)(p + 4);

    float s = v0.x+v0.y+v0.z+v0.w + v1.x+v1.y+v1.z+v1.w;
    #pragma unroll
    for (int o = 16; o; o >>= 1) s += __shfl_xor_sync(0xffffffffu, s, o);
    float mean = s * (1.0f/256.0f);

    float d[8] = {v0.x-mean, v0.y-mean, v0.z-mean, v0.w-mean,
                  v1.x-mean, v1.y-mean, v1.z-mean, v1.w-mean};
    float q = 0.f;
    #pragma unroll
    for (int i = 0; i < 8; i++) q = fmaf(d[i], d[i], q);
    #pragma unroll
    for (int o = 16; o; o >>= 1) q += __shfl_xor_sync(0xffffffffu, q, o);
    float rs = rsqrtf(q*(1.0f/256.0f) + 1e-5f);

    float4 w0 = *(const float4*)(w + lane*8);
    float4 w1 = *(const float4*)(w + lane*8 + 4);
    float4 b0 = *(const float4*)(b + lane*8);
    float4 b1 = *(const float4*)(b + lane*8 + 4);

    uint4 o4;
    o4.x = packh2(d[0]*rs*w0.x + b0.x, d[1]*rs*w0.y + b0.y);
    o4.y = packh2(d[2]*rs*w0.z + b0.z, d[3]*rs*w0.w + b0.w);
    o4.z = packh2(d[4]*rs*w1.x + b1.x, d[5]*rs*w1.y + b1.y);
    o4.w = packh2(d[6]*rs*w1.z + b1.z, d[7]*rs*w1.w + b1.w);
    *(uint4*)(out + (size_t)row*C_ + lane*8) = o4;
}

// ---------------------------------------------------------------------------
// fp16 tensor-core GEMM, cp.async 2-stage double buffer.
// Block 128x128, BK=32, 8 warps 2x4, warp tile 64x32 (m16n8k16).
// OUTH: half output; else fp32.
// ---------------------------------------------------------------------------
#define HSTRW 20
#define HTILE (128*HSTRW)             // words per operand-stage (2560)
#define GSMEM (2*2*HTILE*4)           // 40960 B

template <int PAD, int OUTH>
__global__ __launch_bounds__(256, 2) void gemm_h(
    const __half* __restrict__ X, const __half* __restrict__ W,
    const float* __restrict__ bias, const float* __restrict__ res,
    void* __restrict__ Yv, int M, int Nout, int K, int act)
{
    extern __shared__ u32 hsm[];
    int tid  = threadIdx.x;
    int warp = tid >> 5, lane = tid & 31;
    int g = lane >> 2, t = lane & 3;
    int wm0 = (warp >> 2) * 64;
    int wn0 = (warp & 3) * 32;
    int m0 = blockIdx.y * 128, n0 = blockIdx.x * 128;
    u32 sb = smem_u32(hsm);

    auto issue_tile = [&](int s, int k0 /*halves*/) {
        #pragma unroll
        for (int i = 0; i < 2; i++) {
            int idx = tid + (i << 8);
            int r  = idx >> 2;
            int c8 = (idx & 3) << 3;
            u32 dX = sb + (u32)((s*2*HTILE) + r*HSTRW + (c8 >> 1))*4u;
            const __half* gX = X + (size_t)(m0+r)*K + k0 + c8;
            asm volatile("cp.async.ca.shared.global [%0], [%1], 16;"
                         :: "r"(dX), "l"(gX));
            u32 dW = sb + (u32)((s*2*HTILE) + HTILE + r*HSTRW + (c8 >> 1))*4u;
            const __half* gW = W + (size_t)(n0+r)*K + k0 + c8;
            if (PAD) {
                int vld = (n0 + r < Nout) ? 16 : 0;
                asm volatile("cp.async.ca.shared.global [%0], [%1], 16, %2;"
                             :: "r"(dW), "l"(gW), "r"(vld));
            } else {
                asm volatile("cp.async.ca.shared.global [%0], [%1], 16;"
                             :: "r"(dW), "l"(gW));
            }
        }
    };

    float acc[4][4][4];
    #pragma unroll
    for (int mt = 0; mt < 4; mt++)
        #pragma unroll
        for (int nt = 0; nt < 4; nt++)
            #pragma unroll
            for (int c = 0; c < 4; c++) acc[mt][nt][c] = 0.f;

    issue_tile(0, 0);
    asm volatile("cp.async.commit_group;" ::: "memory");
    issue_tile(1, 32);
    asm volatile("cp.async.commit_group;" ::: "memory");

    int nk = K >> 5;
    for (int it = 0; it < nk; it++) {
        asm volatile("cp.async.wait_group 1;" ::: "memory");
        __syncthreads();

        const u32* sX = hsm + (it & 1)*2*HTILE;
        const u32* sW = sX + HTILE;
        #pragma unroll
        for (int ks = 0; ks < 2; ks++) {
            int kc = ks*8 + t;
            u32 a[4][4];
            #pragma unroll
            for (int mt = 0; mt < 4; mt++) {
                int r = wm0 + mt*16 + g;
                a[mt][0] = sX[r*HSTRW     + kc];
                a[mt][1] = sX[(r+8)*HSTRW + kc];
                a[mt][2] = sX[r*HSTRW     + kc + 4];
                a[mt][3] = sX[(r+8)*HSTRW + kc + 4];
            }
            u32 bb[4][2];
            #pragma unroll
            for (int nt = 0; nt < 4; nt++) {
                int r = wn0 + nt*8 + g;
                bb[nt][0] = sW[r*HSTRW + kc];
                bb[nt][1] = sW[r*HSTRW + kc + 4];
            }
            #pragma unroll
            for (int mt = 0; mt < 4; mt++)
                #pragma unroll
                for (int nt = 0; nt < 4; nt++)
                    mma_f16(acc[mt][nt], a[mt], bb[nt]);
        }
        __syncthreads();

        int k2 = (it + 2) << 5;
        if (k2 < K) issue_tile(it & 1, k2);
        asm volatile("cp.async.commit_group;" ::: "memory");
    }

    float* Yf = (float*)Yv;
    __half* Yh = (__half*)Yv;
    #pragma unroll
    for (int mt = 0; mt < 4; mt++) {
        #pragma unroll
        for (int nt = 0; nt < 4; nt++) {
            int n = n0 + wn0 + nt*8 + 2*t;
            if (PAD && n >= Nout) continue;
            #pragma unroll
            for (int h2 = 0; h2 < 2; h2++) {
                int m = m0 + wm0 + mt*16 + g + h2*8;
                float v0 = acc[mt][nt][h2*2 + 0];
                float v1 = acc[mt][nt][h2*2 + 1];
                if (bias) { v0 += bias[n]; v1 += bias[n+1]; }
                if (act)  { v0 *= normcdff(v0); v1 *= normcdff(v1); }
                if (res)  { v0 += res[(size_t)m*Nout + n];
                            v1 += res[(size_t)m*Nout + n + 1]; }
                if (OUTH) {
                    __half2 hv = __floats2half2_rn(v0, v1);
                    *(__half2*)(Yh + (size_t)m*Nout + n) = hv;
                } else {
                    *(float2*)(Yf + (size_t)m*Nout + n) = make_float2(v0, v1);
                }
            }
        }
    }
}

// ---------------------------------------------------------------------------
// Flash attention v4: all-fp16 MMA (m16n8k16), double-buffered K/V,
// ONE barrier per chunk, base-2 online softmax, no shuffle transpose.
// qkv is fp16: (b*N+n)*768 + s*256 + h*32 + d. Output fp16.
// ---------------------------------------------------------------------------
#define FQT  128
#define FKC  64
#define QSTRW 20                      // words per 32-half row (16 + pad 4)
#define VSTRW 36                      // words per 64-half V row (32 + pad 4)
#define QWORDS (FQT*QSTRW)            // 2560
#define KVWORDS (FKC*QSTRW + 32*VSTRW)  // 2432
#define FSMEM ((QWORDS + 2*KVWORDS)*4)  // 29696 B

__global__ __launch_bounds__(256, 2) void flash_h(
    const __half* __restrict__ qkvh, __half* __restrict__ out)
{
    extern __shared__ u32 fsm[];
    u32* q_s = fsm;                   // FQT x QSTRW
    u32* kvb = fsm + QWORDS;          // 2 x KVWORDS

    int tid  = threadIdx.x;
    int warp = tid >> 5, lane = tid & 31;
    int g = lane >> 2, t = lane & 3;
    int b = blockIdx.z, h = blockIdx.y;
    int q0 = blockIdx.x * FQT;
    const __half* qb = qkvh + (size_t)b*N_*768 + h*32;
    const __half2 qsc2 = __half2half2(__float2half_rn(0.25506704f));

    #pragma unroll
    for (int i = 0; i < 2; i++) {
        int idx = tid + (i << 8);
        int r  = idx >> 2;
        int w4 = (idx & 3) << 2;
        uint4 v = *(const uint4*)(qb + (size_t)(q0+r)*768 + w4*2);
        __half2* hv = (__half2*)&v;
        hv[0] = __hmul2(hv[0], qsc2);
        hv[1] = __hmul2(hv[1], qsc2);
        hv[2] = __hmul2(hv[2], qsc2);
        hv[3] = __hmul2(hv[3], qsc2);
        q_s[r*QSTRW + w4 + 0] = v.x;
        q_s[r*QSTRW + w4 + 1] = v.y;
        q_s[r*QSTRW + w4 + 2] = v.z;
        q_s[r*QSTRW + w4 + 3] = v.w;
    }

    int row0 = warp * 16;
    float oa[4][4];
    #pragma unroll
    for (int nt = 0; nt < 4; nt++)
        #pragma unroll
        for (int c = 0; c < 4; c++) oa[nt][c] = 0.f;
    float mr0 = -1e30f, mr1 = -1e30f, lr0 = 0.f, lr1 = 0.f;

    int rK = tid >> 2, w4K = (tid & 3) << 2;
    int keyV = tid >> 2, dh0 = (tid & 3) << 3;

    uint4 kf = *(const uint4*)(qb + (size_t)rK*768 + 256 + w4K*2);
    uint4 vf = *(const uint4*)(qb + (size_t)keyV*768 + 512 + dh0);

    for (int ic = 0; ic < N_/FKC; ic++) {
        u32* k_s = kvb + (ic & 1)*KVWORDS;
        u32* v_s = k_s + FKC*QSTRW;
        __half* v_sh = (__half*)v_s;

        k_s[rK*QSTRW + w4K + 0] = kf.x;
        k_s[rK*QSTRW + w4K + 1] = kf.y;
        k_s[rK*QSTRW + w4K + 2] = kf.z;
        k_s[rK*QSTRW + w4K + 3] = kf.w;
        {
            __half* hv = (__half*)&vf;
            #pragma unroll
            for (int j = 0; j < 8; j++)
                v_sh[(dh0 + j)*(2*VSTRW) + keyV] = hv[j];
        }

        int ktn = (ic + 1) * FKC;
        if (ktn < N_) {
            kf = *(const uint4*)(qb + (size_t)(ktn+rK)*768 + 256 + w4K*2);
            vf = *(const uint4*)(qb + (size_t)(ktn+keyV)*768 + 512 + dh0);
        }
        __syncthreads();

        float s[8][4];
        #pragma unroll
        for (int nt = 0; nt < 8; nt++)
            #pragma unroll
            for (int c = 0; c < 4; c++) s[nt][c] = 0.f;

        #pragma unroll
        for (int ks = 0; ks < 2; ks++) {
            int kc = ks*8 + t;
            u32 a[4];
            a[0] = q_s[(row0+g)*QSTRW   + kc];
            a[1] = q_s[(row0+8+g)*QSTRW + kc];
            a[2] = q_s[(row0+g)*QSTRW   + kc + 4];
            a[3] = q_s[(row0+8+g)*QSTRW + kc + 4];
            #pragma unroll
            for (int nt = 0; nt < 8; nt++) {
                u32 bb[2];
                bb[0] = k_s[(nt*8+g)*QSTRW + kc];
                bb[1] = k_s[(nt*8+g)*QSTRW + kc + 4];
                mma_f16(s[nt], a, bb);
            }
        }

        u32 pl[8], ph[8];
        {
            float m0 = -1e30f, m1 = -1e30f;
            #pragma unroll
            for (int nt = 0; nt < 8; nt++) {
                m0 = fmaxf(m0, fmaxf(s[nt][0], s[nt][1]));
                m1 = fmaxf(m1, fmaxf(s[nt][2], s[nt][3]));
            }
            #pragma unroll
            for (int o = 1; o <= 2; o <<= 1) {
                m0 = fmaxf(m0, __shfl_xor_sync(0xffffffffu, m0, o));
                m1 = fmaxf(m1, __shfl_xor_sync(0xffffffffu, m1, o));
            }
            float mn0 = fmaxf(mr0, m0);
            float mn1 = fmaxf(mr1, m1);
            float sf0 = ex2f(mr0 - mn0);
            float sf1 = ex2f(mr1 - mn1);
            mr0 = mn0; mr1 = mn1;
            float ls0 = 0.f, ls1 = 0.f;
            #pragma unroll
            for (int nt = 0; nt < 8; nt++) {
                float e0 = ex2f(s[nt][0] - mn0);
                float e1 = ex2f(s[nt][1] - mn0);
                float e2 = ex2f(s[nt][2] - mn1);
                float e3 = ex2f(s[nt][3] - mn1);
                ls0 += e0 + e1;  ls1 += e2 + e3;
                pl[nt] = packh2(e0, e1);
                ph[nt] = packh2(e2, e3);
            }
            #pragma unroll
            for (int o = 1; o <= 2; o <<= 1) {
                ls0 += __shfl_xor_sync(0xffffffffu, ls0, o);
                ls1 += __shfl_xor_sync(0xffffffffu, ls1, o);
            }
            lr0 = lr0*sf0 + ls0;
            lr1 = lr1*sf1 + ls1;
            #pragma unroll
            for (int nt = 0; nt < 4; nt++) {
                oa[nt][0] *= sf0;  oa[nt][1] *= sf0;
                oa[nt][2] *= sf1;  oa[nt][3] *= sf1;
            }
        }

        #pragma unroll
        for (int j = 0; j < 4; j++) {
            u32 a[4];
            a[0] = pl[2*j];
            a[1] = ph[2*j];
            a[2] = pl[2*j+1];
            a[3] = ph[2*j+1];
            #pragma unroll
            for (int nt = 0; nt < 4; nt++) {
                int d = nt*8 + g;
                u32 bb[2];
                bb[0] = v_s[d*VSTRW + j*8 + t];
                bb[1] = v_s[d*VSTRW + j*8 + t + 4];
                mma_f16(oa[nt], a, bb);
            }
        }
    }

    float i0 = 1.f / lr0;
    float i1 = 1.f / lr1;
    int r = q0 + row0 + g;
    #pragma unroll
    for (int nt = 0; nt < 4; nt++) {
        int col = h*32 + nt*8 + 2*t;
        *(__half2*)(out + ((size_t)b*N_ + r)*C_ + col) =
            __floats2half2_rn(oa[nt][0]*i0, oa[nt][1]*i0);
        *(__half2*)(out + ((size_t)b*N_ + r + 8)*C_ + col) =
            __floats2half2_rn(oa[nt][2]*i1, oa[nt][3]*i1);
    }
}

// ---------------------------------------------------------------------------
// Deformable gather: one warp per (b, n, head); lane = channel d.
// offsets/logits come from the merged [M,96] buffer. Output fp16.
// ---------------------------------------------------------------------------
__global__ __launch_bounds__(128) void deform_kernel(
    const float* __restrict__ ref, const float* __restrict__ offaw,
    const float* __restrict__ vp, __half* __restrict__ out)
{
    int u = (blockIdx.x << 2) + (threadIdx.x >> 5);
    int lane = threadIdx.x & 31;
    int h  = u & 7;
    int bn = u >> 3;
    int b  = bn >> 10;

    float rx = ref[(size_t)bn*2 + 0]*32.f - 0.5f;
    float ry = ref[(size_t)bn*2 + 1]*32.f - 0.5f;
    const float* offp = offaw + (size_t)bn*96 + h*8;
    const float* awp  = offaw + (size_t)bn*96 + 64 + h*4;

    float a0 = awp[0], a1 = awp[1], a2 = awp[2], a3 = awp[3];
    float mx = fmaxf(fmaxf(a0,a1), fmaxf(a2,a3));
    float e0 = __expf(a0-mx), e1 = __expf(a1-mx), e2 = __expf(a2-mx), e3 = __expf(a3-mx);
    float inv = 1.f/(e0+e1+e2+e3);
    float aw4[4] = {e0*inv, e1*inv, e2*inv, e3*inv};

    const float* vb = vp + (size_t)b*N_*C_ + h*32 + lane;
    float acc = 0.f;
    #pragma unroll
    for (int p = 0; p < 4; p++) {
        float gx = rx + offp[p*2+0];
        float gy = ry + offp[p*2+1];
        float x0f = floorf(gx), y0f = floorf(gy);
        float lx = gx - x0f, ly = gy - y0f;
        int x0 = (int)x0f, y0 = (int)y0f;
        float s = 0.f;
        #pragma unroll
        for (int cy = 0; cy < 2; cy++) {
            int yi = y0 + cy;
            float wy = cy ? ly : (1.f - ly);
            bool vy = (yi >= 0) && (yi < 32);
            int yc = min(max(yi, 0), 31);
            #pragma unroll
            for (int cx = 0; cx < 2; cx++) {
                int xi = x0 + cx;
                float wx = cx ? lx : (1.f - lx);
                bool vx = (xi >= 0) && (xi < 32);
                int xc = min(max(xi, 0), 31);
                float val = (vx && vy) ? vb[(size_t)(yc*32 + xc)*C_] : 0.f;
                s = fmaf(val, wx*wy, s);
            }
        }
        acc = fmaf(aw4[p], s, acc);
    }
    out[(size_t)bn*C_ + h*32 + lane] = __float2half_rn(acc);
}

// ---------------------------------------------------------------------------
// Launch
// ---------------------------------------------------------------------------
extern "C" void kernel_launch(void* const* d_in, const int* in_sizes, int n_in,
                              void* d_out, int out_size)
{
    const float* x       = (const float*)d_in[0];
    const float* ref     = (const float*)d_in[1];
    const float* value   = (const float*)d_in[2];
    const float* ln1w    = (const float*)d_in[3];
    const float* ln1b    = (const float*)d_in[4];
    const float* ln2w    = (const float*)d_in[5];
    const float* ln2b    = (const float*)d_in[6];
    const float* ln3w    = (const float*)d_in[7];
    const float* ln3b    = (const float*)d_in[8];
    const float* qkv_w   = (const float*)d_in[9];
    const float* proj_w  = (const float*)d_in[10];
    const float* proj_b  = (const float*)d_in[11];
    const float* off_w   = (const float*)d_in[12];
    const float* off_b   = (const float*)d_in[13];
    const float* aw_w    = (const float*)d_in[14];
    const float* aw_b    = (const float*)d_in[15];
    const float* vproj_w = (const float*)d_in[16];
    const float* vproj_b = (const float*)d_in[17];
    const float* oproj_w = (const float*)d_in[18];
    const float* oproj_b = (const float*)d_in[19];
    const float* fc1_w   = (const float*)d_in[20];
    const float* fc1_b   = (const float*)d_in[21];
    const float* fc2_w   = (const float*)d_in[22];
    const float* fc2_b   = (const float*)d_in[23];
    float* out = (float*)d_out;

    float  *x2, *vpb, *offaw, *oab;
    __half *qkvh, *yh, *tmph, *h1h, *wh, *valh;
    cudaGetSymbolAddress((void**)&x2,    g_x2);
    cudaGetSymbolAddress((void**)&vpb,   g_vp);
    cudaGetSymbolAddress((void**)&offaw, g_offaw);
    cudaGetSymbolAddress((void**)&oab,   g_oab);
    cudaGetSymbolAddress((void**)&qkvh,  g_qkvh);
    cudaGetSymbolAddress((void**)&yh,    g_yh);
    cudaGetSymbolAddress((void**)&tmph,  g_tmph);
    cudaGetSymbolAddress((void**)&h1h,   g_h1h);
    cudaGetSymbolAddress((void**)&wh,    g_wh);
    cudaGetSymbolAddress((void**)&valh,  g_valh);

    cudaFuncSetAttribute(flash_h,
        cudaFuncAttributeMaxDynamicSharedMemorySize, FSMEM);
    cudaFuncSetAttribute(gemm_h<0,0>,
        cudaFuncAttributeMaxDynamicSharedMemorySize, GSMEM);
    cudaFuncSetAttribute(gemm_h<1,0>,
        cudaFuncAttributeMaxDynamicSharedMemorySize, GSMEM);
    cudaFuncSetAttribute(gemm_h<0,1>,
        cudaFuncAttributeMaxDynamicSharedMemorySize, GSMEM);

    const __half* wq  = wh + WOFF_QKV;
    const __half* wp  = wh + WOFF_PROJ;
    const __half* woa = wh + WOFF_OFF;    // off||aw rows contiguous (96 rows)
    const __half* wv  = wh + WOFF_VPROJ;
    const __half* wop = wh + WOFF_OPROJ;
    const __half* w1  = wh + WOFF_FC1;
    const __half* w2  = wh + WOFF_FC2;

    // pre-convert weights + value to fp16; build merged off/aw bias
    round_weights_h<<<(WTOT/4 + 255)/256, 256>>>(qkv_w, proj_w, off_w, aw_w,
        vproj_w, oproj_w, fc1_w, fc2_w, wh);
    round_buf_h<<<(M_*C_/4 + 255)/256, 256>>>(value, valh, M_*C_/4);
    concat_bias<<<1, 96>>>(off_b, aw_b, oab);

    // x1 = x + attn(ln1(x))
    ln_kernel<<<M_/8, 256>>>(x, ln1w, ln1b, yh);
    gemm_h<0,1><<<dim3(6,128), 256, GSMEM>>>(yh, wq, nullptr, nullptr, qkvh, M_, 768, 256, 0);
    flash_h<<<dim3(N_/FQT, NH_, B_), 256, FSMEM>>>(qkvh, tmph);
    gemm_h<0,0><<<dim3(2,128), 256, GSMEM>>>(tmph, wp, proj_b, x, x2, M_, 256, 256, 0);

    // x2 = x1 + deform(ln2(x1))
    ln_kernel<<<M_/8, 256>>>(x2, ln2w, ln2b, yh);
    gemm_h<1,0><<<dim3(1,128), 256, GSMEM>>>(yh, woa, oab, nullptr, offaw, M_, 96, 256, 0);
    gemm_h<0,0><<<dim3(2,128), 256, GSMEM>>>(valh, wv, vproj_b, nullptr, vpb, M_, 256, 256, 0);
    deform_kernel<<<32768, 128>>>(ref, offaw, vpb, tmph);
    gemm_h<0,0><<<dim3(2,128), 256, GSMEM>>>(tmph, wop, oproj_b, x2, x2, M_, 256, 256, 0);

    // out = x2 + fc2(gelu(fc1(ln3(x2))))
    ln_kernel<<<M_/8, 256>>>(x2, ln3w, ln3b, yh);
    gemm_h<0,1><<<dim3(8,128), 256, GSMEM>>>(yh, w1, fc1_b, nullptr, h1h, M_, 1024, 256, 1);
    gemm_h<0,0><<<dim3(2,128), 256, GSMEM>>>(h1h, w2, fc2_b, x2, out, M_, 256, 1024, 0);
}

// round 15
// speedup vs baseline: 1.7150x; 1.0578x over previous
#include <cuda_runtime.h>
#include <cuda_fp16.h>
#include <cstdint>
#include <math.h>

typedef unsigned int u32;

// Problem constants
#define B_  16
#define N_  1024
#define C_  256
#define NH_ 8
#define DH_ 32
#define M_  (B_*N_)      // 16384 rows
#define HID_ 1024

// Weight segment sizes (floats)
#define WSZ_QKV   (3*C_*C_)
#define WSZ_PROJ  (C_*C_)
#define WSZ_OFF   (64*C_)
#define WSZ_AW    (32*C_)
#define WSZ_VPROJ (C_*C_)
#define WSZ_OPROJ (C_*C_)
#define WSZ_FC1   (HID_*C_)
#define WSZ_FC2   (C_*HID_)
#define WOFF_QKV   0
#define WOFF_PROJ  (WOFF_QKV  + WSZ_QKV)
#define WOFF_OFF   (WOFF_PROJ + WSZ_PROJ)
#define WOFF_AW    (WOFF_OFF  + WSZ_OFF)
#define WOFF_VPROJ (WOFF_AW   + WSZ_AW)
#define WOFF_OPROJ (WOFF_VPROJ+ WSZ_VPROJ)
#define WOFF_FC1   (WOFF_OPROJ+ WSZ_OPROJ)
#define WOFF_FC2   (WOFF_FC1  + WSZ_FC1)
#define WTOT       (WOFF_FC2  + WSZ_FC2)   // 942080

// ---------------------------------------------------------------------------
// Scratch (static __device__ arrays; no allocations allowed)
// ---------------------------------------------------------------------------
__device__ float  g_x2   [M_*C_];
__device__ float  g_vp   [M_*C_];
__device__ float  g_offaw[M_*96];
__device__ float  g_oab  [96];
__device__ __half g_qkvh [M_*3*C_];
__device__ __half g_yh   [M_*C_];
__device__ __half g_tmph [M_*C_];
__device__ __half g_h1h  [M_*HID_];
__device__ __half g_wh   [WTOT];
__device__ __half g_valh [M_*C_];

// ---------------------------------------------------------------------------
// helpers
// ---------------------------------------------------------------------------
__device__ __forceinline__ float ex2f(float x) {
    float y;
    asm("ex2.approx.f32 %0, %1;" : "=f"(y) : "f"(x));
    return y;
}

__device__ __forceinline__ void mma_f16(float (&d)[4],
                                        const u32 (&a)[4],
                                        const u32 (&b)[2]) {
    asm volatile(
        "mma.sync.aligned.m16n8k16.row.col.f32.f16.f16.f32 "
        "{%0,%1,%2,%3}, {%4,%5,%6,%7}, {%8,%9}, {%0,%1,%2,%3};"
        : "+f"(d[0]), "+f"(d[1]), "+f"(d[2]), "+f"(d[3])
        : "r"(a[0]), "r"(a[1]), "r"(a[2]), "r"(a[3]),
          "r"(b[0]), "r"(b[1]));
}

__device__ __forceinline__ void ldsm4(u32& r0, u32& r1, u32& r2, u32& r3,
                                      u32 addr) {
    asm volatile("ldmatrix.sync.aligned.m8n8.x4.shared.b16 {%0,%1,%2,%3}, [%4];"
                 : "=r"(r0), "=r"(r1), "=r"(r2), "=r"(r3) : "r"(addr));
}

__device__ __forceinline__ u32 smem_u32(const void* p) {
    return (u32)__cvta_generic_to_shared(p);
}

__device__ __forceinline__ u32 packh2(float a, float b) {
    __half2 h = __floats2half2_rn(a, b);
    return *(u32*)&h;
}

// ---------------------------------------------------------------------------
// Weight / buffer conversion to fp16 (RN)
// ---------------------------------------------------------------------------
__global__ __launch_bounds__(256) void round_weights_h(
    const float* __restrict__ qkv_w, const float* __restrict__ proj_w,
    const float* __restrict__ off_w, const float* __restrict__ aw_w,
    const float* __restrict__ vproj_w, const float* __restrict__ oproj_w,
    const float* __restrict__ fc1_w, const float* __restrict__ fc2_w,
    __half* __restrict__ dst)
{
    int i4 = blockIdx.x*256 + threadIdx.x;
    if (i4 >= WTOT/4) return;
    int i = i4*4;
    const float* src;
    int off;
    if      (i < WOFF_PROJ)  { src = qkv_w;   off = i - WOFF_QKV;  }
    else if (i < WOFF_OFF)   { src = proj_w;  off = i - WOFF_PROJ; }
    else if (i < WOFF_AW)    { src = off_w;   off = i - WOFF_OFF;  }
    else if (i < WOFF_VPROJ) { src = aw_w;    off = i - WOFF_AW;   }
    else if (i < WOFF_OPROJ) { src = vproj_w; off = i - WOFF_VPROJ;}
    else if (i < WOFF_FC1)   { src = oproj_w; off = i - WOFF_OPROJ;}
    else if (i < WOFF_FC2)   { src = fc1_w;   off = i - WOFF_FC1;  }
    else                     { src = fc2_w;   off = i - WOFF_FC2;  }
    float4 v = *(const float4*)(src + off);
    __half2 h0 = __floats2half2_rn(v.x, v.y);
    __half2 h1 = __floats2half2_rn(v.z, v.w);
    *(uint2*)(dst + i) = make_uint2(*(u32*)&h0, *(u32*)&h1);
}

__global__ __launch_bounds__(256) void round_buf_h(
    const float* __restrict__ src, __half* __restrict__ dst, int n4)
{
    int i4 = blockIdx.x*256 + threadIdx.x;
    if (i4 >= n4) return;
    float4 v = *(const float4*)(src + i4*4);
    __half2 h0 = __floats2half2_rn(v.x, v.y);
    __half2 h1 = __floats2half2_rn(v.z, v.w);
    *(uint2*)(dst + i4*4) = make_uint2(*(u32*)&h0, *(u32*)&h1);
}

__global__ void concat_bias(const float* __restrict__ ob,
                            const float* __restrict__ ab,
                            float* __restrict__ dst)
{
    int i = threadIdx.x;
    if (i < 64) dst[i] = ob[i];
    else if (i < 96) dst[i] = ab[i-64];
}

// ---------------------------------------------------------------------------
// LayerNorm, warp-per-row, shuffle reductions, fp16 output.
// ---------------------------------------------------------------------------
__global__ __launch_bounds__(256) void ln_kernel(
    const float* __restrict__ in, const float* __restrict__ w,
    const float* __restrict__ b, __half* __restrict__ out)
{
    int warp = threadIdx.x >> 5, lane = threadIdx.x & 31;
    int row = blockIdx.x*8 + warp;
    const float* p = in + (size_t)row*C_ + lane*8;
    float4 v0 = *(const float4*)(p);
    float4 v1 = *(const float4*)(p + 4);

    float s = v0.x+v0.y+v0.z+v0.w + v1.x+v1.y+v1.z+v1.w;
    #pragma unroll
    for (int o = 16; o; o >>= 1) s += __shfl_xor_sync(0xffffffffu, s, o);
    float mean = s * (1.0f/256.0f);

    float d[8] = {v0.x-mean, v0.y-mean, v0.z-mean, v0.w-mean,
                  v1.x-mean, v1.y-mean, v1.z-mean, v1.w-mean};
    float q = 0.f;
    #pragma unroll
    for (int i = 0; i < 8; i++) q = fmaf(d[i], d[i], q);
    #pragma unroll
    for (int o = 16; o; o >>= 1) q += __shfl_xor_sync(0xffffffffu, q, o);
    float rs = rsqrtf(q*(1.0f/256.0f) + 1e-5f);

    float4 w0 = *(const float4*)(w + lane*8);
    float4 w1 = *(const float4*)(w + lane*8 + 4);
    float4 b0 = *(const float4*)(b + lane*8);
    float4 b1 = *(const float4*)(b + lane*8 + 4);

    uint4 o4;
    o4.x = packh2(d[0]*rs*w0.x + b0.x, d[1]*rs*w0.y + b0.y);
    o4.y = packh2(d[2]*rs*w0.z + b0.z, d[3]*rs*w0.w + b0.w);
    o4.z = packh2(d[4]*rs*w1.x + b1.x, d[5]*rs*w1.y + b1.y);
    o4.w = packh2(d[6]*rs*w1.z + b1.z, d[7]*rs*w1.w + b1.w);
    *(uint4*)(out + (size_t)row*C_ + lane*8) = o4;
}

// ---------------------------------------------------------------------------
// fp16 tensor-core GEMM, cp.async 2-stage double buffer + ldmatrix fragments.
// Block 128x128, BK=32, 8 warps 2x4, warp tile 64x32 (m16n8k16).
// ---------------------------------------------------------------------------
#define HSTRW 20
#define HTILE (128*HSTRW)
#define GSMEM (2*2*HTILE*4)           // 40960 B

template <int PAD, int OUTH>
__global__ __launch_bounds__(256, 2) void gemm_h(
    const __half* __restrict__ X, const __half* __restrict__ W,
    const float* __restrict__ bias, const float* __restrict__ res,
    void* __restrict__ Yv, int M, int Nout, int K, int act)
{
    extern __shared__ u32 hsm[];
    int tid  = threadIdx.x;
    int warp = tid >> 5, lane = tid & 31;
    int g = lane >> 2, t = lane & 3;
    int wm0 = (warp >> 2) * 64;
    int wn0 = (warp & 3) * 32;
    int m0 = blockIdx.y * 128, n0 = blockIdx.x * 128;
    u32 sb = smem_u32(hsm);

    // ldmatrix lane addressing
    int lr8  = lane & 7;
    int lrow = lr8 + ((lane >> 3) & 1) * 8;   // A: row within 16
    int lkb  = (lane >> 4) & 1;               // A: k half-block
    // A lane offset (words): row (wm0+lrow), k-word lkb*4
    u32 aoff = (u32)((wm0 + lrow)*HSTRW + lkb*4) * 4u;
    // B lane offset: row wn0 + ((lane>>4)&1)*8 + lr8, k-word ((lane>>3)&1)*4
    u32 boff = (u32)((wn0 + ((lane >> 4) & 1)*8 + lr8)*HSTRW
                     + ((lane >> 3) & 1)*4) * 4u;

    auto issue_tile = [&](int s, int k0 /*halves*/) {
        #pragma unroll
        for (int i = 0; i < 2; i++) {
            int idx = tid + (i << 8);
            int r  = idx >> 2;
            int c8 = (idx & 3) << 3;
            u32 dX = sb + (u32)((s*2*HTILE) + r*HSTRW + (c8 >> 1))*4u;
            const __half* gX = X + (size_t)(m0+r)*K + k0 + c8;
            asm volatile("cp.async.ca.shared.global [%0], [%1], 16;"
                         :: "r"(dX), "l"(gX));
            u32 dW = sb + (u32)((s*2*HTILE) + HTILE + r*HSTRW + (c8 >> 1))*4u;
            const __half* gW = W + (size_t)(n0+r)*K + k0 + c8;
            if (PAD) {
                int vld = (n0 + r < Nout) ? 16 : 0;
                asm volatile("cp.async.ca.shared.global [%0], [%1], 16, %2;"
                             :: "r"(dW), "l"(gW), "r"(vld));
            } else {
                asm volatile("cp.async.ca.shared.global [%0], [%1], 16;"
                             :: "r"(dW), "l"(gW));
            }
        }
    };

    float acc[4][4][4];
    #pragma unroll
    for (int mt = 0; mt < 4; mt++)
        #pragma unroll
        for (int nt = 0; nt < 4; nt++)
            #pragma unroll
            for (int c = 0; c < 4; c++) acc[mt][nt][c] = 0.f;

    issue_tile(0, 0);
    asm volatile("cp.async.commit_group;" ::: "memory");
    issue_tile(1, 32);
    asm volatile("cp.async.commit_group;" ::: "memory");

    int nk = K >> 5;
    for (int it = 0; it < nk; it++) {
        asm volatile("cp.async.wait_group 1;" ::: "memory");
        __syncthreads();

        u32 sbX = sb + (u32)((it & 1)*2*HTILE)*4u;
        u32 sbW = sbX + (u32)HTILE*4u;
        #pragma unroll
        for (int ks = 0; ks < 2; ks++) {
            u32 a[4][4];
            #pragma unroll
            for (int mt = 0; mt < 4; mt++)
                ldsm4(a[mt][0], a[mt][1], a[mt][2], a[mt][3],
                      sbX + aoff + (u32)(mt*16*HSTRW + ks*8)*4u);
            u32 bb[4][2];
            #pragma unroll
            for (int p = 0; p < 2; p++)
                ldsm4(bb[2*p][0], bb[2*p][1], bb[2*p+1][0], bb[2*p+1][1],
                      sbW + boff + (u32)(p*16*HSTRW + ks*8)*4u);
            #pragma unroll
            for (int mt = 0; mt < 4; mt++)
                #pragma unroll
                for (int nt = 0; nt < 4; nt++)
                    mma_f16(acc[mt][nt], a[mt], bb[nt]);
        }
        __syncthreads();

        int k2 = (it + 2) << 5;
        if (k2 < K) issue_tile(it & 1, k2);
        asm volatile("cp.async.commit_group;" ::: "memory");
    }

    float* Yf = (float*)Yv;
    __half* Yh = (__half*)Yv;
    #pragma unroll
    for (int mt = 0; mt < 4; mt++) {
        #pragma unroll
        for (int nt = 0; nt < 4; nt++) {
            int n = n0 + wn0 + nt*8 + 2*t;
            if (PAD && n >= Nout) continue;
            #pragma unroll
            for (int h2 = 0; h2 < 2; h2++) {
                int m = m0 + wm0 + mt*16 + g + h2*8;
                float v0 = acc[mt][nt][h2*2 + 0];
                float v1 = acc[mt][nt][h2*2 + 1];
                if (bias) { v0 += bias[n]; v1 += bias[n+1]; }
                if (act)  { v0 *= normcdff(v0); v1 *= normcdff(v1); }
                if (res)  { v0 += res[(size_t)m*Nout + n];
                            v1 += res[(size_t)m*Nout + n + 1]; }
                if (OUTH) {
                    __half2 hv = __floats2half2_rn(v0, v1);
                    *(__half2*)(Yh + (size_t)m*Nout + n) = hv;
                } else {
                    *(float2*)(Yf + (size_t)m*Nout + n) = make_float2(v0, v1);
                }
            }
        }
    }
}

// ---------------------------------------------------------------------------
// Flash attention v5: all-fp16 MMA + ldmatrix fragments, double-buffered K/V,
// ONE barrier per chunk, base-2 online softmax, no shuffle transpose.
// ---------------------------------------------------------------------------
#define FQT  128
#define FKC  64
#define QSTRW 20
#define VSTRW 36
#define QWORDS (FQT*QSTRW)
#define KVWORDS (FKC*QSTRW + 32*VSTRW)
#define FSMEM ((QWORDS + 2*KVWORDS)*4)  // 29696 B

__global__ __launch_bounds__(256, 2) void flash_h(
    const __half* __restrict__ qkvh, __half* __restrict__ out)
{
    extern __shared__ u32 fsm[];
    u32* q_s = fsm;
    u32* kvb = fsm + QWORDS;

    int tid  = threadIdx.x;
    int warp = tid >> 5, lane = tid & 31;
    int g = lane >> 2, t = lane & 3;
    int b = blockIdx.z, h = blockIdx.y;
    int q0 = blockIdx.x * FQT;
    const __half* qb = qkvh + (size_t)b*N_*768 + h*32;
    const __half2 qsc2 = __half2half2(__float2half_rn(0.25506704f));

    u32 sq = smem_u32(q_s);
    u32 skv = smem_u32(kvb);

    // ldmatrix lane addressing
    int lr8  = lane & 7;
    int lrow = lr8 + ((lane >> 3) & 1) * 8;
    int lkb  = (lane >> 4) & 1;
    u32 qoff = (u32)(lrow*QSTRW + lkb*4) * 4u;     // + row0*QSTRW*4 + ks*32
    u32 koff = (u32)((((lane >> 4) & 1)*8 + lr8)*QSTRW
                     + ((lane >> 3) & 1)*4) * 4u;  // + p*16*QSTRW*4 + ks*32
    u32 voff = (u32)((((lane >> 4) & 1)*8 + lr8)*VSTRW
                     + ((lane >> 3) & 1)*4) * 4u;  // + p*16*VSTRW*4 + j*32

    #pragma unroll
    for (int i = 0; i < 2; i++) {
        int idx = tid + (i << 8);
        int r  = idx >> 2;
        int w4 = (idx & 3) << 2;
        uint4 v = *(const uint4*)(qb + (size_t)(q0+r)*768 + w4*2);
        __half2* hv = (__half2*)&v;
        hv[0] = __hmul2(hv[0], qsc2);
        hv[1] = __hmul2(hv[1], qsc2);
        hv[2] = __hmul2(hv[2], qsc2);
        hv[3] = __hmul2(hv[3], qsc2);
        q_s[r*QSTRW + w4 + 0] = v.x;
        q_s[r*QSTRW + w4 + 1] = v.y;
        q_s[r*QSTRW + w4 + 2] = v.z;
        q_s[r*QSTRW + w4 + 3] = v.w;
    }

    int row0 = warp * 16;
    float oa[4][4];
    #pragma unroll
    for (int nt = 0; nt < 4; nt++)
        #pragma unroll
        for (int c = 0; c < 4; c++) oa[nt][c] = 0.f;
    float mr0 = -1e30f, mr1 = -1e30f, lr0 = 0.f, lr1 = 0.f;

    int rK = tid >> 2, w4K = (tid & 3) << 2;
    int keyV = tid >> 2, dh0 = (tid & 3) << 3;

    uint4 kf = *(const uint4*)(qb + (size_t)rK*768 + 256 + w4K*2);
    uint4 vf = *(const uint4*)(qb + (size_t)keyV*768 + 512 + dh0);

    for (int ic = 0; ic < N_/FKC; ic++) {
        u32* k_s = kvb + (ic & 1)*KVWORDS;
        u32* v_s = k_s + FKC*QSTRW;
        __half* v_sh = (__half*)v_s;
        u32 skc = skv + (u32)((ic & 1)*KVWORDS)*4u;
        u32 svc = skc + (u32)(FKC*QSTRW)*4u;

        k_s[rK*QSTRW + w4K + 0] = kf.x;
        k_s[rK*QSTRW + w4K + 1] = kf.y;
        k_s[rK*QSTRW + w4K + 2] = kf.z;
        k_s[rK*QSTRW + w4K + 3] = kf.w;
        {
            __half* hv = (__half*)&vf;
            #pragma unroll
            for (int j = 0; j < 8; j++)
                v_sh[(dh0 + j)*(2*VSTRW) + keyV] = hv[j];
        }

        int ktn = (ic + 1) * FKC;
        if (ktn < N_) {
            kf = *(const uint4*)(qb + (size_t)(ktn+rK)*768 + 256 + w4K*2);
            vf = *(const uint4*)(qb + (size_t)(ktn+keyV)*768 + 512 + dh0);
        }
        __syncthreads();

        // ---- S = Q @ K^T ----
        float s[8][4];
        #pragma unroll
        for (int nt = 0; nt < 8; nt++)
            #pragma unroll
            for (int c = 0; c < 4; c++) s[nt][c] = 0.f;

        #pragma unroll
        for (int ks = 0; ks < 2; ks++) {
            u32 a[4];
            ldsm4(a[0], a[1], a[2], a[3],
                  sq + qoff + (u32)(row0*QSTRW + ks*8)*4u);
            u32 bb[8][2];
            #pragma unroll
            for (int p = 0; p < 4; p++)
                ldsm4(bb[2*p][0], bb[2*p][1], bb[2*p+1][0], bb[2*p+1][1],
                      skc + koff + (u32)(p*16*QSTRW + ks*8)*4u);
            #pragma unroll
            for (int nt = 0; nt < 8; nt++)
                mma_f16(s[nt], a, bb[nt]);
        }

        // ---- online softmax (base-2) ----
        u32 pl[8], ph[8];
        {
            float m0 = -1e30f, m1 = -1e30f;
            #pragma unroll
            for (int nt = 0; nt < 8; nt++) {
                m0 = fmaxf(m0, fmaxf(s[nt][0], s[nt][1]));
                m1 = fmaxf(m1, fmaxf(s[nt][2], s[nt][3]));
            }
            #pragma unroll
            for (int o = 1; o <= 2; o <<= 1) {
                m0 = fmaxf(m0, __shfl_xor_sync(0xffffffffu, m0, o));
                m1 = fmaxf(m1, __shfl_xor_sync(0xffffffffu, m1, o));
            }
            float mn0 = fmaxf(mr0, m0);
            float mn1 = fmaxf(mr1, m1);
            float sf0 = ex2f(mr0 - mn0);
            float sf1 = ex2f(mr1 - mn1);
            mr0 = mn0; mr1 = mn1;
            float ls0 = 0.f, ls1 = 0.f;
            #pragma unroll
            for (int nt = 0; nt < 8; nt++) {
                float e0 = ex2f(s[nt][0] - mn0);
                float e1 = ex2f(s[nt][1] - mn0);
                float e2 = ex2f(s[nt][2] - mn1);
                float e3 = ex2f(s[nt][3] - mn1);
                ls0 += e0 + e1;  ls1 += e2 + e3;
                pl[nt] = packh2(e0, e1);
                ph[nt] = packh2(e2, e3);
            }
            #pragma unroll
            for (int o = 1; o <= 2; o <<= 1) {
                ls0 += __shfl_xor_sync(0xffffffffu, ls0, o);
                ls1 += __shfl_xor_sync(0xffffffffu, ls1, o);
            }
            lr0 = lr0*sf0 + ls0;
            lr1 = lr1*sf1 + ls1;
            #pragma unroll
            for (int nt = 0; nt < 4; nt++) {
                oa[nt][0] *= sf0;  oa[nt][1] *= sf0;
                oa[nt][2] *= sf1;  oa[nt][3] *= sf1;
            }
        }

        // ---- O += P @ V ----
        #pragma unroll
        for (int j = 0; j < 4; j++) {
            u32 a[4];
            a[0] = pl[2*j];
            a[1] = ph[2*j];
            a[2] = pl[2*j+1];
            a[3] = ph[2*j+1];
            u32 bb[4][2];
            #pragma unroll
            for (int p = 0; p < 2; p++)
                ldsm4(bb[2*p][0], bb[2*p][1], bb[2*p+1][0], bb[2*p+1][1],
                      svc + voff + (u32)(p*16*VSTRW + j*8)*4u);
            #pragma unroll
            for (int nt = 0; nt < 4; nt++)
                mma_f16(oa[nt], a, bb[nt]);
        }
    }

    float i0 = 1.f / lr0;
    float i1 = 1.f / lr1;
    int r = q0 + row0 + g;
    #pragma unroll
    for (int nt = 0; nt < 4; nt++) {
        int col = h*32 + nt*8 + 2*t;
        *(__half2*)(out + ((size_t)b*N_ + r)*C_ + col) =
            __floats2half2_rn(oa[nt][0]*i0, oa[nt][1]*i0);
        *(__half2*)(out + ((size_t)b*N_ + r + 8)*C_ + col) =
            __floats2half2_rn(oa[nt][2]*i1, oa[nt][3]*i1);
    }
}

// ---------------------------------------------------------------------------
// Deformable gather: one warp per (b, n, head); lane = channel d.
// ---------------------------------------------------------------------------
__global__ __launch_bounds__(128) void deform_kernel(
    const float* __restrict__ ref, const float* __restrict__ offaw,
    const float* __restrict__ vp, __half* __restrict__ out)
{
    int u = (blockIdx.x << 2) + (threadIdx.x >> 5);
    int lane = threadIdx.x & 31;
    int h  = u & 7;
    int bn = u >> 3;
    int b  = bn >> 10;

    float rx = ref[(size_t)bn*2 + 0]*32.f - 0.5f;
    float ry = ref[(size_t)bn*2 + 1]*32.f - 0.5f;
    const float* offp = offaw + (size_t)bn*96 + h*8;
    const float* awp  = offaw + (size_t)bn*96 + 64 + h*4;

    float a0 = awp[0], a1 = awp[1], a2 = awp[2], a3 = awp[3];
    float mx = fmaxf(fmaxf(a0,a1), fmaxf(a2,a3));
    float e0 = __expf(a0-mx), e1 = __expf(a1-mx), e2 = __expf(a2-mx), e3 = __expf(a3-mx);
    float inv = 1.f/(e0+e1+e2+e3);
    float aw4[4] = {e0*inv, e1*inv, e2*inv, e3*inv};

    const float* vb = vp + (size_t)b*N_*C_ + h*32 + lane;
    float acc = 0.f;
    #pragma unroll
    for (int p = 0; p < 4; p++) {
        float gx = rx + offp[p*2+0];
        float gy = ry + offp[p*2+1];
        float x0f = floorf(gx), y0f = floorf(gy);
        float lx = gx - x0f, ly = gy - y0f;
        int x0 = (int)x0f, y0 = (int)y0f;
        float s = 0.f;
        #pragma unroll
        for (int cy = 0; cy < 2; cy++) {
            int yi = y0 + cy;
            float wy = cy ? ly : (1.f - ly);
            bool vy = (yi >= 0) && (yi < 32);
            int yc = min(max(yi, 0), 31);
            #pragma unroll
            for (int cx = 0; cx < 2; cx++) {
                int xi = x0 + cx;
                float wx = cx ? lx : (1.f - lx);
                bool vx = (xi >= 0) && (xi < 32);
                int xc = min(max(xi, 0), 31);
                float val = (vx && vy) ? vb[(size_t)(yc*32 + xc)*C_] : 0.f;
                s = fmaf(val, wx*wy, s);
            }
        }
        acc = fmaf(aw4[p], s, acc);
    }
    out[(size_t)bn*C_ + h*32 + lane] = __float2half_rn(acc);
}

// ---------------------------------------------------------------------------
// Launch
// ---------------------------------------------------------------------------
extern "C" void kernel_launch(void* const* d_in, const int* in_sizes, int n_in,
                              void* d_out, int out_size)
{
    const float* x       = (const float*)d_in[0];
    const float* ref     = (const float*)d_in[1];
    const float* value   = (const float*)d_in[2];
    const float* ln1w    = (const float*)d_in[3];
    const float* ln1b    = (const float*)d_in[4];
    const float* ln2w    = (const float*)d_in[5];
    const float* ln2b    = (const float*)d_in[6];
    const float* ln3w    = (const float*)d_in[7];
    const float* ln3b    = (const float*)d_in[8];
    const float* qkv_w   = (const float*)d_in[9];
    const float* proj_w  = (const float*)d_in[10];
    const float* proj_b  = (const float*)d_in[11];
    const float* off_w   = (const float*)d_in[12];
    const float* off_b   = (const float*)d_in[13];
    const float* aw_w    = (const float*)d_in[14];
    const float* aw_b    = (const float*)d_in[15];
    const float* vproj_w = (const float*)d_in[16];
    const float* vproj_b = (const float*)d_in[17];
    const float* oproj_w = (const float*)d_in[18];
    const float* oproj_b = (const float*)d_in[19];
    const float* fc1_w   = (const float*)d_in[20];
    const float* fc1_b   = (const float*)d_in[21];
    const float* fc2_w   = (const float*)d_in[22];
    const float* fc2_b   = (const float*)d_in[23];
    float* out = (float*)d_out;

    float  *x2, *vpb, *offaw, *oab;
    __half *qkvh, *yh, *tmph, *h1h, *wh, *valh;
    cudaGetSymbolAddress((void**)&x2,    g_x2);
    cudaGetSymbolAddress((void**)&vpb,   g_vp);
    cudaGetSymbolAddress((void**)&offaw, g_offaw);
    cudaGetSymbolAddress((void**)&oab,   g_oab);
    cudaGetSymbolAddress((void**)&qkvh,  g_qkvh);
    cudaGetSymbolAddress((void**)&yh,    g_yh);
    cudaGetSymbolAddress((void**)&tmph,  g_tmph);
    cudaGetSymbolAddress((void**)&h1h,   g_h1h);
    cudaGetSymbolAddress((void**)&wh,    g_wh);
    cudaGetSymbolAddress((void**)&valh,  g_valh);

    cudaFuncSetAttribute(flash_h,
        cudaFuncAttributeMaxDynamicSharedMemorySize, FSMEM);
    cudaFuncSetAttribute(gemm_h<0,0>,
        cudaFuncAttributeMaxDynamicSharedMemorySize, GSMEM);
    cudaFuncSetAttribute(gemm_h<1,0>,
        cudaFuncAttributeMaxDynamicSharedMemorySize, GSMEM);
    cudaFuncSetAttribute(gemm_h<0,1>,
        cudaFuncAttributeMaxDynamicSharedMemorySize, GSMEM);

    const __half* wq  = wh + WOFF_QKV;
    const __half* wp  = wh + WOFF_PROJ;
    const __half* woa = wh + WOFF_OFF;
    const __half* wv  = wh + WOFF_VPROJ;
    const __half* wop = wh + WOFF_OPROJ;
    const __half* w1  = wh + WOFF_FC1;
    const __half* w2  = wh + WOFF_FC2;

    round_weights_h<<<(WTOT/4 + 255)/256, 256>>>(qkv_w, proj_w, off_w, aw_w,
        vproj_w, oproj_w, fc1_w, fc2_w, wh);
    round_buf_h<<<(M_*C_/4 + 255)/256, 256>>>(value, valh, M_*C_/4);
    concat_bias<<<1, 96>>>(off_b, aw_b, oab);

    // x1 = x + attn(ln1(x))
    ln_kernel<<<M_/8, 256>>>(x, ln1w, ln1b, yh);
    gemm_h<0,1><<<dim3(6,128), 256, GSMEM>>>(yh, wq, nullptr, nullptr, qkvh, M_, 768, 256, 0);
    flash_h<<<dim3(N_/FQT, NH_, B_), 256, FSMEM>>>(qkvh, tmph);
    gemm_h<0,0><<<dim3(2,128), 256, GSMEM>>>(tmph, wp, proj_b, x, x2, M_, 256, 256, 0);

    // x2 = x1 + deform(ln2(x1))
    ln_kernel<<<M_/8, 256>>>(x2, ln2w, ln2b, yh);
    gemm_h<1,0><<<dim3(1,128), 256, GSMEM>>>(yh, woa, oab, nullptr, offaw, M_, 96, 256, 0);
    gemm_h<0,0><<<dim3(2,128), 256, GSMEM>>>(valh, wv, vproj_b, nullptr, vpb, M_, 256, 256, 0);
    deform_kernel<<<32768, 128>>>(ref, offaw, vpb, tmph);
    gemm_h<0,0><<<dim3(2,128), 256, GSMEM>>>(tmph, wop, oproj_b, x2, x2, M_, 256, 256, 0);

    // out = x2 + fc2(gelu(fc1(ln3(x2))))
    ln_kernel<<<M_/8, 256>>>(x2, ln3w, ln3b, yh);
    gemm_h<0,1><<<dim3(8,128), 256, GSMEM>>>(yh, w1, fc1_b, nullptr, h1h, M_, 1024, 256, 1);
    gemm_h<0,0><<<dim3(2,128), 256, GSMEM>>>(h1h, w2, fc2_b, x2, out, M_, 256, 1024, 0);
}

// round 16
// speedup vs baseline: 1.7480x; 1.0193x over previous
#include <cuda_runtime.h>
#include <cuda_fp16.h>
#include <cstdint>
#include <math.h>

typedef unsigned int u32;

// Problem constants
#define B_  16
#define N_  1024
#define C_  256
#define NH_ 8
#define DH_ 32
#define M_  (B_*N_)      // 16384 rows
#define HID_ 1024

// Weight segment sizes (floats)
#define WSZ_QKV   (3*C_*C_)
#define WSZ_PROJ  (C_*C_)
#define WSZ_OFF   (64*C_)
#define WSZ_AW    (32*C_)
#define WSZ_VPROJ (C_*C_)
#define WSZ_OPROJ (C_*C_)
#define WSZ_FC1   (HID_*C_)
#define WSZ_FC2   (C_*HID_)
#define WOFF_QKV   0
#define WOFF_PROJ  (WOFF_QKV  + WSZ_QKV)
#define WOFF_OFF   (WOFF_PROJ + WSZ_PROJ)
#define WOFF_AW    (WOFF_OFF  + WSZ_OFF)
#define WOFF_VPROJ (WOFF_AW   + WSZ_AW)
#define WOFF_OPROJ (WOFF_VPROJ+ WSZ_VPROJ)
#define WOFF_FC1   (WOFF_OPROJ+ WSZ_OPROJ)
#define WOFF_FC2   (WOFF_FC1  + WSZ_FC1)
#define WTOT       (WOFF_FC2  + WSZ_FC2)   // 942080

// ---------------------------------------------------------------------------
// Scratch (static __device__ arrays; no allocations allowed)
// ---------------------------------------------------------------------------
__device__ float  g_x2   [M_*C_];
__device__ float  g_offaw[M_*96];
__device__ float  g_oab  [96];
__device__ __half g_vph  [M_*C_];     // vproj output (half, deform table)
__device__ __half g_qkvh [M_*3*C_];
__device__ __half g_yh   [M_*C_];
__device__ __half g_tmph [M_*C_];
__device__ __half g_h1h  [M_*HID_];
__device__ __half g_wh   [WTOT];
__device__ __half g_valh [M_*C_];

// ---------------------------------------------------------------------------
// helpers
// ---------------------------------------------------------------------------
__device__ __forceinline__ float ex2f(float x) {
    float y;
    asm("ex2.approx.f32 %0, %1;" : "=f"(y) : "f"(x));
    return y;
}

__device__ __forceinline__ void mma_f16(float (&d)[4],
                                        const u32 (&a)[4],
                                        const u32 (&b)[2]) {
    asm volatile(
        "mma.sync.aligned.m16n8k16.row.col.f32.f16.f16.f32 "
        "{%0,%1,%2,%3}, {%4,%5,%6,%7}, {%8,%9}, {%0,%1,%2,%3};"
        : "+f"(d[0]), "+f"(d[1]), "+f"(d[2]), "+f"(d[3])
        : "r"(a[0]), "r"(a[1]), "r"(a[2]), "r"(a[3]),
          "r"(b[0]), "r"(b[1]));
}

__device__ __forceinline__ void ldsm4(u32& r0, u32& r1, u32& r2, u32& r3,
                                      u32 addr) {
    asm volatile("ldmatrix.sync.aligned.m8n8.x4.shared.b16 {%0,%1,%2,%3}, [%4];"
                 : "=r"(r0), "=r"(r1), "=r"(r2), "=r"(r3) : "r"(addr));
}

__device__ __forceinline__ u32 smem_u32(const void* p) {
    return (u32)__cvta_generic_to_shared(p);
}

__device__ __forceinline__ u32 packh2(float a, float b) {
    __half2 h = __floats2half2_rn(a, b);
    return *(u32*)&h;
}

// ---------------------------------------------------------------------------
// Weight / buffer conversion to fp16 (RN)
// ---------------------------------------------------------------------------
__global__ __launch_bounds__(256) void round_weights_h(
    const float* __restrict__ qkv_w, const float* __restrict__ proj_w,
    const float* __restrict__ off_w, const float* __restrict__ aw_w,
    const float* __restrict__ vproj_w, const float* __restrict__ oproj_w,
    const float* __restrict__ fc1_w, const float* __restrict__ fc2_w,
    __half* __restrict__ dst)
{
    int i4 = blockIdx.x*256 + threadIdx.x;
    if (i4 >= WTOT/4) return;
    int i = i4*4;
    const float* src;
    int off;
    if      (i < WOFF_PROJ)  { src = qkv_w;   off = i - WOFF_QKV;  }
    else if (i < WOFF_OFF)   { src = proj_w;  off = i - WOFF_PROJ; }
    else if (i < WOFF_AW)    { src = off_w;   off = i - WOFF_OFF;  }
    else if (i < WOFF_VPROJ) { src = aw_w;    off = i - WOFF_AW;   }
    else if (i < WOFF_OPROJ) { src = vproj_w; off = i - WOFF_VPROJ;}
    else if (i < WOFF_FC1)   { src = oproj_w; off = i - WOFF_OPROJ;}
    else if (i < WOFF_FC2)   { src = fc1_w;   off = i - WOFF_FC1;  }
    else                     { src = fc2_w;   off = i - WOFF_FC2;  }
    float4 v = *(const float4*)(src + off);
    __half2 h0 = __floats2half2_rn(v.x, v.y);
    __half2 h1 = __floats2half2_rn(v.z, v.w);
    *(uint2*)(dst + i) = make_uint2(*(u32*)&h0, *(u32*)&h1);
}

__global__ __launch_bounds__(256) void round_buf_h(
    const float* __restrict__ src, __half* __restrict__ dst, int n4)
{
    int i4 = blockIdx.x*256 + threadIdx.x;
    if (i4 >= n4) return;
    float4 v = *(const float4*)(src + i4*4);
    __half2 h0 = __floats2half2_rn(v.x, v.y);
    __half2 h1 = __floats2half2_rn(v.z, v.w);
    *(uint2*)(dst + i4*4) = make_uint2(*(u32*)&h0, *(u32*)&h1);
}

__global__ void concat_bias(const float* __restrict__ ob,
                            const float* __restrict__ ab,
                            float* __restrict__ dst)
{
    int i = threadIdx.x;
    if (i < 64) dst[i] = ob[i];
    else if (i < 96) dst[i] = ab[i-64];
}

// ---------------------------------------------------------------------------
// LayerNorm, warp-per-row, shuffle reductions, fp16 output.
// ---------------------------------------------------------------------------
__global__ __launch_bounds__(256) void ln_kernel(
    const float* __restrict__ in, const float* __restrict__ w,
    const float* __restrict__ b, __half* __restrict__ out)
{
    int warp = threadIdx.x >> 5, lane = threadIdx.x & 31;
    int row = blockIdx.x*8 + warp;
    const float* p = in + (size_t)row*C_ + lane*8;
    float4 v0 = *(const float4*)(p);
    float4 v1 = *(const float4*)(p + 4);

    float s = v0.x+v0.y+v0.z+v0.w + v1.x+v1.y+v1.z+v1.w;
    #pragma unroll
    for (int o = 16; o; o >>= 1) s += __shfl_xor_sync(0xffffffffu, s, o);
    float mean = s * (1.0f/256.0f);

    float d[8] = {v0.x-mean, v0.y-mean, v0.z-mean, v0.w-mean,
                  v1.x-mean, v1.y-mean, v1.z-mean, v1.w-mean};
    float q = 0.f;
    #pragma unroll
    for (int i = 0; i < 8; i++) q = fmaf(d[i], d[i], q);
    #pragma unroll
    for (int o = 16; o; o >>= 1) q += __shfl_xor_sync(0xffffffffu, q, o);
    float rs = rsqrtf(q*(1.0f/256.0f) + 1e-5f);

    float4 w0 = *(const float4*)(w + lane*8);
    float4 w1 = *(const float4*)(w + lane*8 + 4);
    float4 b0 = *(const float4*)(b + lane*8);
    float4 b1 = *(const float4*)(b + lane*8 + 4);

    uint4 o4;
    o4.x = packh2(d[0]*rs*w0.x + b0.x, d[1]*rs*w0.y + b0.y);
    o4.y = packh2(d[2]*rs*w0.z + b0.z, d[3]*rs*w0.w + b0.w);
    o4.z = packh2(d[4]*rs*w1.x + b1.x, d[5]*rs*w1.y + b1.y);
    o4.w = packh2(d[6]*rs*w1.z + b1.z, d[7]*rs*w1.w + b1.w);
    *(uint4*)(out + (size_t)row*C_ + lane*8) = o4;
}

// ---------------------------------------------------------------------------
// fp16 tensor-core GEMM, cp.async 2-stage double buffer + ldmatrix, BK=64.
// Block 128x128, 8 warps 2x4, warp tile 64x32 (m16n8k16).
// Row stride 36 words (64 halves + 8 pad) -> conflict-free ldmatrix.
// ---------------------------------------------------------------------------
#define HSTRW 36
#define HTILE (128*HSTRW)             // words per operand-stage (4608)
#define GSMEM (2*2*HTILE*4)           // 73728 B

template <int PAD, int OUTH>
__global__ __launch_bounds__(256, 2) void gemm_h(
    const __half* __restrict__ X, const __half* __restrict__ W,
    const float* __restrict__ bias, const float* __restrict__ res,
    void* __restrict__ Yv, int M, int Nout, int K, int act)
{
    extern __shared__ u32 hsm[];
    int tid  = threadIdx.x;
    int warp = tid >> 5, lane = tid & 31;
    int g = lane >> 2, t = lane & 3;
    int wm0 = (warp >> 2) * 64;
    int wn0 = (warp & 3) * 32;
    int m0 = blockIdx.y * 128, n0 = blockIdx.x * 128;
    u32 sb = smem_u32(hsm);

    // ldmatrix lane addressing
    int lr8  = lane & 7;
    int lrow = lr8 + ((lane >> 3) & 1) * 8;
    int lkb  = (lane >> 4) & 1;
    u32 aoff = (u32)((wm0 + lrow)*HSTRW + lkb*4) * 4u;
    u32 boff = (u32)((wn0 + ((lane >> 4) & 1)*8 + lr8)*HSTRW
                     + ((lane >> 3) & 1)*4) * 4u;

    auto issue_tile = [&](int s, int k0 /*halves*/) {
        #pragma unroll
        for (int i = 0; i < 4; i++) {
            int idx = tid + (i << 8);       // 0..1023
            int r  = idx >> 3;              // 0..127
            int c8 = (idx & 7) << 3;        // half offset 0..56
            u32 dX = sb + (u32)((s*2*HTILE) + r*HSTRW + (c8 >> 1))*4u;
            const __half* gX = X + (size_t)(m0+r)*K + k0 + c8;
            asm volatile("cp.async.ca.shared.global [%0], [%1], 16;"
                         :: "r"(dX), "l"(gX));
            u32 dW = sb + (u32)((s*2*HTILE) + HTILE + r*HSTRW + (c8 >> 1))*4u;
            const __half* gW = W + (size_t)(n0+r)*K + k0 + c8;
            if (PAD) {
                int vld = (n0 + r < Nout) ? 16 : 0;
                asm volatile("cp.async.ca.shared.global [%0], [%1], 16, %2;"
                             :: "r"(dW), "l"(gW), "r"(vld));
            } else {
                asm volatile("cp.async.ca.shared.global [%0], [%1], 16;"
                             :: "r"(dW), "l"(gW));
            }
        }
    };

    float acc[4][4][4];
    #pragma unroll
    for (int mt = 0; mt < 4; mt++)
        #pragma unroll
        for (int nt = 0; nt < 4; nt++)
            #pragma unroll
            for (int c = 0; c < 4; c++) acc[mt][nt][c] = 0.f;

    issue_tile(0, 0);
    asm volatile("cp.async.commit_group;" ::: "memory");
    issue_tile(1, 64);
    asm volatile("cp.async.commit_group;" ::: "memory");

    int nk = K >> 6;
    for (int it = 0; it < nk; it++) {
        asm volatile("cp.async.wait_group 1;" ::: "memory");
        __syncthreads();

        u32 sbX = sb + (u32)((it & 1)*2*HTILE)*4u;
        u32 sbW = sbX + (u32)HTILE*4u;
        #pragma unroll
        for (int ks = 0; ks < 4; ks++) {
            u32 a[4][4];
            #pragma unroll
            for (int mt = 0; mt < 4; mt++)
                ldsm4(a[mt][0], a[mt][1], a[mt][2], a[mt][3],
                      sbX + aoff + (u32)(mt*16*HSTRW + ks*8)*4u);
            u32 bb[4][2];
            #pragma unroll
            for (int p = 0; p < 2; p++)
                ldsm4(bb[2*p][0], bb[2*p][1], bb[2*p+1][0], bb[2*p+1][1],
                      sbW + boff + (u32)(p*16*HSTRW + ks*8)*4u);
            #pragma unroll
            for (int mt = 0; mt < 4; mt++)
                #pragma unroll
                for (int nt = 0; nt < 4; nt++)
                    mma_f16(acc[mt][nt], a[mt], bb[nt]);
        }
        __syncthreads();

        int k2 = (it + 2) << 6;
        if (k2 < K) issue_tile(it & 1, k2);
        asm volatile("cp.async.commit_group;" ::: "memory");
    }

    float* Yf = (float*)Yv;
    __half* Yh = (__half*)Yv;
    #pragma unroll
    for (int mt = 0; mt < 4; mt++) {
        #pragma unroll
        for (int nt = 0; nt < 4; nt++) {
            int n = n0 + wn0 + nt*8 + 2*t;
            if (PAD && n >= Nout) continue;
            #pragma unroll
            for (int h2 = 0; h2 < 2; h2++) {
                int m = m0 + wm0 + mt*16 + g + h2*8;
                float v0 = acc[mt][nt][h2*2 + 0];
                float v1 = acc[mt][nt][h2*2 + 1];
                if (bias) { v0 += bias[n]; v1 += bias[n+1]; }
                if (act)  { v0 *= normcdff(v0); v1 *= normcdff(v1); }
                if (res)  { v0 += res[(size_t)m*Nout + n];
                            v1 += res[(size_t)m*Nout + n + 1]; }
                if (OUTH) {
                    __half2 hv = __floats2half2_rn(v0, v1);
                    *(__half2*)(Yh + (size_t)m*Nout + n) = hv;
                } else {
                    *(float2*)(Yf + (size_t)m*Nout + n) = make_float2(v0, v1);
                }
            }
        }
    }
}

// ---------------------------------------------------------------------------
// Flash attention v5: all-fp16 MMA + ldmatrix fragments, double-buffered K/V,
// ONE barrier per chunk, base-2 online softmax, no shuffle transpose.
// ---------------------------------------------------------------------------
#define FQT  128
#define FKC  64
#define QSTRW 20
#define VSTRW 36
#define QWORDS (FQT*QSTRW)
#define KVWORDS (FKC*QSTRW + 32*VSTRW)
#define FSMEM ((QWORDS + 2*KVWORDS)*4)  // 29696 B

__global__ __launch_bounds__(256, 2) void flash_h(
    const __half* __restrict__ qkvh, __half* __restrict__ out)
{
    extern __shared__ u32 fsm[];
    u32* q_s = fsm;
    u32* kvb = fsm + QWORDS;

    int tid  = threadIdx.x;
    int warp = tid >> 5, lane = tid & 31;
    int g = lane >> 2, t = lane & 3;
    int b = blockIdx.z, h = blockIdx.y;
    int q0 = blockIdx.x * FQT;
    const __half* qb = qkvh + (size_t)b*N_*768 + h*32;
    const __half2 qsc2 = __half2half2(__float2half_rn(0.25506704f));

    u32 sq = smem_u32(q_s);
    u32 skv = smem_u32(kvb);

    int lr8  = lane & 7;
    int lrow = lr8 + ((lane >> 3) & 1) * 8;
    int lkb  = (lane >> 4) & 1;
    u32 qoff = (u32)(lrow*QSTRW + lkb*4) * 4u;
    u32 koff = (u32)((((lane >> 4) & 1)*8 + lr8)*QSTRW
                     + ((lane >> 3) & 1)*4) * 4u;
    u32 voff = (u32)((((lane >> 4) & 1)*8 + lr8)*VSTRW
                     + ((lane >> 3) & 1)*4) * 4u;

    #pragma unroll
    for (int i = 0; i < 2; i++) {
        int idx = tid + (i << 8);
        int r  = idx >> 2;
        int w4 = (idx & 3) << 2;
        uint4 v = *(const uint4*)(qb + (size_t)(q0+r)*768 + w4*2);
        __half2* hv = (__half2*)&v;
        hv[0] = __hmul2(hv[0], qsc2);
        hv[1] = __hmul2(hv[1], qsc2);
        hv[2] = __hmul2(hv[2], qsc2);
        hv[3] = __hmul2(hv[3], qsc2);
        q_s[r*QSTRW + w4 + 0] = v.x;
        q_s[r*QSTRW + w4 + 1] = v.y;
        q_s[r*QSTRW + w4 + 2] = v.z;
        q_s[r*QSTRW + w4 + 3] = v.w;
    }

    int row0 = warp * 16;
    float oa[4][4];
    #pragma unroll
    for (int nt = 0; nt < 4; nt++)
        #pragma unroll
        for (int c = 0; c < 4; c++) oa[nt][c] = 0.f;
    float mr0 = -1e30f, mr1 = -1e30f, lr0 = 0.f, lr1 = 0.f;

    int rK = tid >> 2, w4K = (tid & 3) << 2;
    int keyV = tid >> 2, dh0 = (tid & 3) << 3;

    uint4 kf = *(const uint4*)(qb + (size_t)rK*768 + 256 + w4K*2);
    uint4 vf = *(const uint4*)(qb + (size_t)keyV*768 + 512 + dh0);

    for (int ic = 0; ic < N_/FKC; ic++) {
        u32* k_s = kvb + (ic & 1)*KVWORDS;
        u32* v_s = k_s + FKC*QSTRW;
        __half* v_sh = (__half*)v_s;
        u32 skc = skv + (u32)((ic & 1)*KVWORDS)*4u;
        u32 svc = skc + (u32)(FKC*QSTRW)*4u;

        k_s[rK*QSTRW + w4K + 0] = kf.x;
        k_s[rK*QSTRW + w4K + 1] = kf.y;
        k_s[rK*QSTRW + w4K + 2] = kf.z;
        k_s[rK*QSTRW + w4K + 3] = kf.w;
        {
            __half* hv = (__half*)&vf;
            #pragma unroll
            for (int j = 0; j < 8; j++)
                v_sh[(dh0 + j)*(2*VSTRW) + keyV] = hv[j];
        }

        int ktn = (ic + 1) * FKC;
        if (ktn < N_) {
            kf = *(const uint4*)(qb + (size_t)(ktn+rK)*768 + 256 + w4K*2);
            vf = *(const uint4*)(qb + (size_t)(ktn+keyV)*768 + 512 + dh0);
        }
        __syncthreads();

        float s[8][4];
        #pragma unroll
        for (int nt = 0; nt < 8; nt++)
            #pragma unroll
            for (int c = 0; c < 4; c++) s[nt][c] = 0.f;

        #pragma unroll
        for (int ks = 0; ks < 2; ks++) {
            u32 a[4];
            ldsm4(a[0], a[1], a[2], a[3],
                  sq + qoff + (u32)(row0*QSTRW + ks*8)*4u);
            u32 bb[8][2];
            #pragma unroll
            for (int p = 0; p < 4; p++)
                ldsm4(bb[2*p][0], bb[2*p][1], bb[2*p+1][0], bb[2*p+1][1],
                      skc + koff + (u32)(p*16*QSTRW + ks*8)*4u);
            #pragma unroll
            for (int nt = 0; nt < 8; nt++)
                mma_f16(s[nt], a, bb[nt]);
        }

        u32 pl[8], ph[8];
        {
            float m0 = -1e30f, m1 = -1e30f;
            #pragma unroll
            for (int nt = 0; nt < 8; nt++) {
                m0 = fmaxf(m0, fmaxf(s[nt][0], s[nt][1]));
                m1 = fmaxf(m1, fmaxf(s[nt][2], s[nt][3]));
            }
            #pragma unroll
            for (int o = 1; o <= 2; o <<= 1) {
                m0 = fmaxf(m0, __shfl_xor_sync(0xffffffffu, m0, o));
                m1 = fmaxf(m1, __shfl_xor_sync(0xffffffffu, m1, o));
            }
            float mn0 = fmaxf(mr0, m0);
            float mn1 = fmaxf(mr1, m1);
            float sf0 = ex2f(mr0 - mn0);
            float sf1 = ex2f(mr1 - mn1);
            mr0 = mn0; mr1 = mn1;
            float ls0 = 0.f, ls1 = 0.f;
            #pragma unroll
            for (int nt = 0; nt < 8; nt++) {
                float e0 = ex2f(s[nt][0] - mn0);
                float e1 = ex2f(s[nt][1] - mn0);
                float e2 = ex2f(s[nt][2] - mn1);
                float e3 = ex2f(s[nt][3] - mn1);
                ls0 += e0 + e1;  ls1 += e2 + e3;
                pl[nt] = packh2(e0, e1);
                ph[nt] = packh2(e2, e3);
            }
            #pragma unroll
            for (int o = 1; o <= 2; o <<= 1) {
                ls0 += __shfl_xor_sync(0xffffffffu, ls0, o);
                ls1 += __shfl_xor_sync(0xffffffffu, ls1, o);
            }
            lr0 = lr0*sf0 + ls0;
            lr1 = lr1*sf1 + ls1;
            #pragma unroll
            for (int nt = 0; nt < 4; nt++) {
                oa[nt][0] *= sf0;  oa[nt][1] *= sf0;
                oa[nt][2] *= sf1;  oa[nt][3] *= sf1;
            }
        }

        #pragma unroll
        for (int j = 0; j < 4; j++) {
            u32 a[4];
            a[0] = pl[2*j];
            a[1] = ph[2*j];
            a[2] = pl[2*j+1];
            a[3] = ph[2*j+1];
            u32 bb[4][2];
            #pragma unroll
            for (int p = 0; p < 2; p++)
                ldsm4(bb[2*p][0], bb[2*p][1], bb[2*p+1][0], bb[2*p+1][1],
                      svc + voff + (u32)(p*16*VSTRW + j*8)*4u);
            #pragma unroll
            for (int nt = 0; nt < 4; nt++)
                mma_f16(oa[nt], a, bb[nt]);
        }
    }

    float i0 = 1.f / lr0;
    float i1 = 1.f / lr1;
    int r = q0 + row0 + g;
    #pragma unroll
    for (int nt = 0; nt < 4; nt++) {
        int col = h*32 + nt*8 + 2*t;
        *(__half2*)(out + ((size_t)b*N_ + r)*C_ + col) =
            __floats2half2_rn(oa[nt][0]*i0, oa[nt][1]*i0);
        *(__half2*)(out + ((size_t)b*N_ + r + 8)*C_ + col) =
            __floats2half2_rn(oa[nt][2]*i1, oa[nt][3]*i1);
    }
}

// ---------------------------------------------------------------------------
// Deformable gather: one warp per (b, n, head); lane = channel d.
// V-table is fp16 (halves L2 traffic). Output fp16.
// ---------------------------------------------------------------------------
__global__ __launch_bounds__(128) void deform_kernel(
    const float* __restrict__ ref, const float* __restrict__ offaw,
    const __half* __restrict__ vp, __half* __restrict__ out)
{
    int u = (blockIdx.x << 2) + (threadIdx.x >> 5);
    int lane = threadIdx.x & 31;
    int h  = u & 7;
    int bn = u >> 3;
    int b  = bn >> 10;

    float rx = ref[(size_t)bn*2 + 0]*32.f - 0.5f;
    float ry = ref[(size_t)bn*2 + 1]*32.f - 0.5f;
    const float* offp = offaw + (size_t)bn*96 + h*8;
    const float* awp  = offaw + (size_t)bn*96 + 64 + h*4;

    float a0 = awp[0], a1 = awp[1], a2 = awp[2], a3 = awp[3];
    float mx = fmaxf(fmaxf(a0,a1), fmaxf(a2,a3));
    float e0 = __expf(a0-mx), e1 = __expf(a1-mx), e2 = __expf(a2-mx), e3 = __expf(a3-mx);
    float inv = 1.f/(e0+e1+e2+e3);
    float aw4[4] = {e0*inv, e1*inv, e2*inv, e3*inv};

    const __half* vb = vp + (size_t)b*N_*C_ + h*32 + lane;
    float acc = 0.f;
    #pragma unroll
    for (int p = 0; p < 4; p++) {
        float gx = rx + offp[p*2+0];
        float gy = ry + offp[p*2+1];
        float x0f = floorf(gx), y0f = floorf(gy);
        float lx = gx - x0f, ly = gy - y0f;
        int x0 = (int)x0f, y0 = (int)y0f;
        float s = 0.f;
        #pragma unroll
        for (int cy = 0; cy < 2; cy++) {
            int yi = y0 + cy;
            float wy = cy ? ly : (1.f - ly);
            bool vy = (yi >= 0) && (yi < 32);
            int yc = min(max(yi, 0), 31);
            #pragma unroll
            for (int cx = 0; cx < 2; cx++) {
                int xi = x0 + cx;
                float wx = cx ? lx : (1.f - lx);
                bool vx = (xi >= 0) && (xi < 32);
                int xc = min(max(xi, 0), 31);
                float val = (vx && vy)
                    ? __half2float(vb[(size_t)(yc*32 + xc)*C_]) : 0.f;
                s = fmaf(val, wx*wy, s);
            }
        }
        acc = fmaf(aw4[p], s, acc);
    }
    out[(size_t)bn*C_ + h*32 + lane] = __float2half_rn(acc);
}

// ---------------------------------------------------------------------------
// Launch
// ---------------------------------------------------------------------------
extern "C" void kernel_launch(void* const* d_in, const int* in_sizes, int n_in,
                              void* d_out, int out_size)
{
    const float* x       = (const float*)d_in[0];
    const float* ref     = (const float*)d_in[1];
    const float* value   = (const float*)d_in[2];
    const float* ln1w    = (const float*)d_in[3];
    const float* ln1b    = (const float*)d_in[4];
    const float* ln2w    = (const float*)d_in[5];
    const float* ln2b    = (const float*)d_in[6];
    const float* ln3w    = (const float*)d_in[7];
    const float* ln3b    = (const float*)d_in[8];
    const float* qkv_w   = (const float*)d_in[9];
    const float* proj_w  = (const float*)d_in[10];
    const float* proj_b  = (const float*)d_in[11];
    const float* off_w   = (const float*)d_in[12];
    const float* off_b   = (const float*)d_in[13];
    const float* aw_w    = (const float*)d_in[14];
    const float* aw_b    = (const float*)d_in[15];
    const float* vproj_w = (const float*)d_in[16];
    const float* vproj_b = (const float*)d_in[17];
    const float* oproj_w = (const float*)d_in[18];
    const float* oproj_b = (const float*)d_in[19];
    const float* fc1_w   = (const float*)d_in[20];
    const float* fc1_b   = (const float*)d_in[21];
    const float* fc2_w   = (const float*)d_in[22];
    const float* fc2_b   = (const float*)d_in[23];
    float* out = (float*)d_out;

    float  *x2, *offaw, *oab;
    __half *vph, *qkvh, *yh, *tmph, *h1h, *wh, *valh;
    cudaGetSymbolAddress((void**)&x2,    g_x2);
    cudaGetSymbolAddress((void**)&offaw, g_offaw);
    cudaGetSymbolAddress((void**)&oab,   g_oab);
    cudaGetSymbolAddress((void**)&vph,   g_vph);
    cudaGetSymbolAddress((void**)&qkvh,  g_qkvh);
    cudaGetSymbolAddress((void**)&yh,    g_yh);
    cudaGetSymbolAddress((void**)&tmph,  g_tmph);
    cudaGetSymbolAddress((void**)&h1h,   g_h1h);
    cudaGetSymbolAddress((void**)&wh,    g_wh);
    cudaGetSymbolAddress((void**)&valh,  g_valh);

    cudaFuncSetAttribute(flash_h,
        cudaFuncAttributeMaxDynamicSharedMemorySize, FSMEM);
    cudaFuncSetAttribute(gemm_h<0,0>,
        cudaFuncAttributeMaxDynamicSharedMemorySize, GSMEM);
    cudaFuncSetAttribute(gemm_h<1,0>,
        cudaFuncAttributeMaxDynamicSharedMemorySize, GSMEM);
    cudaFuncSetAttribute(gemm_h<0,1>,
        cudaFuncAttributeMaxDynamicSharedMemorySize, GSMEM);
    cudaFuncSetAttribute(gemm_h<1,1>,
        cudaFuncAttributeMaxDynamicSharedMemorySize, GSMEM);

    const __half* wq  = wh + WOFF_QKV;
    const __half* wp  = wh + WOFF_PROJ;
    const __half* woa = wh + WOFF_OFF;
    const __half* wv  = wh + WOFF_VPROJ;
    const __half* wop = wh + WOFF_OPROJ;
    const __half* w1  = wh + WOFF_FC1;
    const __half* w2  = wh + WOFF_FC2;

    round_weights_h<<<(WTOT/4 + 255)/256, 256>>>(qkv_w, proj_w, off_w, aw_w,
        vproj_w, oproj_w, fc1_w, fc2_w, wh);
    round_buf_h<<<(M_*C_/4 + 255)/256, 256>>>(value, valh, M_*C_/4);
    concat_bias<<<1, 96>>>(off_b, aw_b, oab);

    // x1 = x + attn(ln1(x))
    ln_kernel<<<M_/8, 256>>>(x, ln1w, ln1b, yh);
    gemm_h<0,1><<<dim3(6,128), 256, GSMEM>>>(yh, wq, nullptr, nullptr, qkvh, M_, 768, 256, 0);
    flash_h<<<dim3(N_/FQT, NH_, B_), 256, FSMEM>>>(qkvh, tmph);
    gemm_h<0,0><<<dim3(2,128), 256, GSMEM>>>(tmph, wp, proj_b, x, x2, M_, 256, 256, 0);

    // x2 = x1 + deform(ln2(x1))
    ln_kernel<<<M_/8, 256>>>(x2, ln2w, ln2b, yh);
    gemm_h<1,0><<<dim3(1,128), 256, GSMEM>>>(yh, woa, oab, nullptr, offaw, M_, 96, 256, 0);
    gemm_h<0,1><<<dim3(2,128), 256, GSMEM>>>(valh, wv, vproj_b, nullptr, vph, M_, 256, 256, 0);
    deform_kernel<<<32768, 128>>>(ref, offaw, vph, tmph);
    gemm_h<0,0><<<dim3(2,128), 256, GSMEM>>>(tmph, wop, oproj_b, x2, x2, M_, 256, 256, 0);

    // out = x2 + fc2(gelu(fc1(ln3(x2))))
    ln_kernel<<<M_/8, 256>>>(x2, ln3w, ln3b, yh);
    gemm_h<0,1><<<dim3(8,128), 256, GSMEM>>>(yh, w1, fc1_b, nullptr, h1h, M_, 1024, 256, 1);
    gemm_h<0,0><<<dim3(2,128), 256, GSMEM>>>(h1h, w2, fc2_b, x2, out, M_, 256, 1024, 0);
}

// round 17
// speedup vs baseline: 1.7806x; 1.0186x over previous
#include <cuda_runtime.h>
#include <cuda_fp16.h>
#include <cstdint>
#include <math.h>

typedef unsigned int u32;

// Problem constants
#define B_  16
#define N_  1024
#define C_  256
#define NH_ 8
#define DH_ 32
#define M_  (B_*N_)      // 16384 rows
#define HID_ 1024

// Weight segment sizes (floats)
#define WSZ_QKV   (3*C_*C_)
#define WSZ_PROJ  (C_*C_)
#define WSZ_OFF   (64*C_)
#define WSZ_AW    (32*C_)
#define WSZ_VPROJ (C_*C_)
#define WSZ_OPROJ (C_*C_)
#define WSZ_FC1   (HID_*C_)
#define WSZ_FC2   (C_*HID_)
#define WOFF_QKV   0
#define WOFF_PROJ  (WOFF_QKV  + WSZ_QKV)
#define WOFF_OFF   (WOFF_PROJ + WSZ_PROJ)
#define WOFF_AW    (WOFF_OFF  + WSZ_OFF)
#define WOFF_VPROJ (WOFF_AW   + WSZ_AW)
#define WOFF_OPROJ (WOFF_VPROJ+ WSZ_VPROJ)
#define WOFF_FC1   (WOFF_OPROJ+ WSZ_OPROJ)
#define WOFF_FC2   (WOFF_FC1  + WSZ_FC1)
#define WTOT       (WOFF_FC2  + WSZ_FC2)   // 942080

// ---------------------------------------------------------------------------
// Scratch (static __device__ arrays; no allocations allowed)
// ---------------------------------------------------------------------------
__device__ float  g_x2   [M_*C_];
__device__ float  g_offaw[M_*96];
__device__ float  g_oab  [96];
__device__ __half g_vph  [M_*C_];
__device__ __half g_qkvh [M_*3*C_];
__device__ __half g_yh   [M_*C_];
__device__ __half g_tmph [M_*C_];
__device__ __half g_h1h  [M_*HID_];
__device__ __half g_wh   [WTOT];
__device__ __half g_valh [M_*C_];

// ---------------------------------------------------------------------------
// Side stream + events (created at static init; NOT in kernel_launch).
// Stream is non-blocking so it can overlap the legacy default stream and
// participate in graph capture via explicit event fork/join.
// ---------------------------------------------------------------------------
struct SideStream {
    cudaStream_t s1;
    cudaEvent_t evFork, evW, evV;
    SideStream() {
        cudaStreamCreateWithFlags(&s1, cudaStreamNonBlocking);
        cudaEventCreateWithFlags(&evFork, cudaEventDisableTiming);
        cudaEventCreateWithFlags(&evW,    cudaEventDisableTiming);
        cudaEventCreateWithFlags(&evV,    cudaEventDisableTiming);
    }
};
static SideStream g_ss;

// ---------------------------------------------------------------------------
// helpers
// ---------------------------------------------------------------------------
__device__ __forceinline__ float ex2f(float x) {
    float y;
    asm("ex2.approx.f32 %0, %1;" : "=f"(y) : "f"(x));
    return y;
}

__device__ __forceinline__ void mma_f16(float (&d)[4],
                                        const u32 (&a)[4],
                                        const u32 (&b)[2]) {
    asm volatile(
        "mma.sync.aligned.m16n8k16.row.col.f32.f16.f16.f32 "
        "{%0,%1,%2,%3}, {%4,%5,%6,%7}, {%8,%9}, {%0,%1,%2,%3};"
        : "+f"(d[0]), "+f"(d[1]), "+f"(d[2]), "+f"(d[3])
        : "r"(a[0]), "r"(a[1]), "r"(a[2]), "r"(a[3]),
          "r"(b[0]), "r"(b[1]));
}

__device__ __forceinline__ void ldsm4(u32& r0, u32& r1, u32& r2, u32& r3,
                                      u32 addr) {
    asm volatile("ldmatrix.sync.aligned.m8n8.x4.shared.b16 {%0,%1,%2,%3}, [%4];"
                 : "=r"(r0), "=r"(r1), "=r"(r2), "=r"(r3) : "r"(addr));
}

__device__ __forceinline__ u32 smem_u32(const void* p) {
    return (u32)__cvta_generic_to_shared(p);
}

__device__ __forceinline__ u32 packh2(float a, float b) {
    __half2 h = __floats2half2_rn(a, b);
    return *(u32*)&h;
}

// ---------------------------------------------------------------------------
// Weight / buffer conversion to fp16 (RN)
// ---------------------------------------------------------------------------
__global__ __launch_bounds__(256) void round_weights_h(
    const float* __restrict__ qkv_w, const float* __restrict__ proj_w,
    const float* __restrict__ off_w, const float* __restrict__ aw_w,
    const float* __restrict__ vproj_w, const float* __restrict__ oproj_w,
    const float* __restrict__ fc1_w, const float* __restrict__ fc2_w,
    __half* __restrict__ dst)
{
    int i4 = blockIdx.x*256 + threadIdx.x;
    if (i4 >= WTOT/4) return;
    int i = i4*4;
    const float* src;
    int off;
    if      (i < WOFF_PROJ)  { src = qkv_w;   off = i - WOFF_QKV;  }
    else if (i < WOFF_OFF)   { src = proj_w;  off = i - WOFF_PROJ; }
    else if (i < WOFF_AW)    { src = off_w;   off = i - WOFF_OFF;  }
    else if (i < WOFF_VPROJ) { src = aw_w;    off = i - WOFF_AW;   }
    else if (i < WOFF_OPROJ) { src = vproj_w; off = i - WOFF_VPROJ;}
    else if (i < WOFF_FC1)   { src = oproj_w; off = i - WOFF_OPROJ;}
    else if (i < WOFF_FC2)   { src = fc1_w;   off = i - WOFF_FC1;  }
    else                     { src = fc2_w;   off = i - WOFF_FC2;  }
    float4 v = *(const float4*)(src + off);
    __half2 h0 = __floats2half2_rn(v.x, v.y);
    __half2 h1 = __floats2half2_rn(v.z, v.w);
    *(uint2*)(dst + i) = make_uint2(*(u32*)&h0, *(u32*)&h1);
}

__global__ __launch_bounds__(256) void round_buf_h(
    const float* __restrict__ src, __half* __restrict__ dst, int n4)
{
    int i4 = blockIdx.x*256 + threadIdx.x;
    if (i4 >= n4) return;
    float4 v = *(const float4*)(src + i4*4);
    __half2 h0 = __floats2half2_rn(v.x, v.y);
    __half2 h1 = __floats2half2_rn(v.z, v.w);
    *(uint2*)(dst + i4*4) = make_uint2(*(u32*)&h0, *(u32*)&h1);
}

__global__ void concat_bias(const float* __restrict__ ob,
                            const float* __restrict__ ab,
                            float* __restrict__ dst)
{
    int i = threadIdx.x;
    if (i < 64) dst[i] = ob[i];
    else if (i < 96) dst[i] = ab[i-64];
}

// ---------------------------------------------------------------------------
// LayerNorm, warp-per-2-rows (ILP on the shuffle chains), fp16 output.
// ---------------------------------------------------------------------------
__global__ __launch_bounds__(256) void ln_kernel(
    const float* __restrict__ in, const float* __restrict__ w,
    const float* __restrict__ b, __half* __restrict__ out)
{
    int warp = threadIdx.x >> 5, lane = threadIdx.x & 31;
    int row = (blockIdx.x*8 + warp)*2;
    const float* pA = in + (size_t)row*C_ + lane*8;
    const float* pB = pA + C_;
    float4 a0 = *(const float4*)(pA);
    float4 a1 = *(const float4*)(pA + 4);
    float4 b0v = *(const float4*)(pB);
    float4 b1v = *(const float4*)(pB + 4);

    float sA = a0.x+a0.y+a0.z+a0.w + a1.x+a1.y+a1.z+a1.w;
    float sB = b0v.x+b0v.y+b0v.z+b0v.w + b1v.x+b1v.y+b1v.z+b1v.w;
    #pragma unroll
    for (int o = 16; o; o >>= 1) {
        sA += __shfl_xor_sync(0xffffffffu, sA, o);
        sB += __shfl_xor_sync(0xffffffffu, sB, o);
    }
    float mA = sA * (1.0f/256.0f);
    float mB = sB * (1.0f/256.0f);

    float dA[8] = {a0.x-mA, a0.y-mA, a0.z-mA, a0.w-mA,
                   a1.x-mA, a1.y-mA, a1.z-mA, a1.w-mA};
    float dB[8] = {b0v.x-mB, b0v.y-mB, b0v.z-mB, b0v.w-mB,
                   b1v.x-mB, b1v.y-mB, b1v.z-mB, b1v.w-mB};
    float qA = 0.f, qB = 0.f;
    #pragma unroll
    for (int i = 0; i < 8; i++) {
        qA = fmaf(dA[i], dA[i], qA);
        qB = fmaf(dB[i], dB[i], qB);
    }
    #pragma unroll
    for (int o = 16; o; o >>= 1) {
        qA += __shfl_xor_sync(0xffffffffu, qA, o);
        qB += __shfl_xor_sync(0xffffffffu, qB, o);
    }
    float rA = rsqrtf(qA*(1.0f/256.0f) + 1e-5f);
    float rB = rsqrtf(qB*(1.0f/256.0f) + 1e-5f);

    float4 w0 = *(const float4*)(w + lane*8);
    float4 w1 = *(const float4*)(w + lane*8 + 4);
    float4 bb0 = *(const float4*)(b + lane*8);
    float4 bb1 = *(const float4*)(b + lane*8 + 4);
    float wv[8] = {w0.x,w0.y,w0.z,w0.w,w1.x,w1.y,w1.z,w1.w};
    float bv[8] = {bb0.x,bb0.y,bb0.z,bb0.w,bb1.x,bb1.y,bb1.z,bb1.w};

    uint4 oA, oB;
    oA.x = packh2(dA[0]*rA*wv[0] + bv[0], dA[1]*rA*wv[1] + bv[1]);
    oA.y = packh2(dA[2]*rA*wv[2] + bv[2], dA[3]*rA*wv[3] + bv[3]);
    oA.z = packh2(dA[4]*rA*wv[4] + bv[4], dA[5]*rA*wv[5] + bv[5]);
    oA.w = packh2(dA[6]*rA*wv[6] + bv[6], dA[7]*rA*wv[7] + bv[7]);
    oB.x = packh2(dB[0]*rB*wv[0] + bv[0], dB[1]*rB*wv[1] + bv[1]);
    oB.y = packh2(dB[2]*rB*wv[2] + bv[2], dB[3]*rB*wv[3] + bv[3]);
    oB.z = packh2(dB[4]*rB*wv[4] + bv[4], dB[5]*rB*wv[5] + bv[5]);
    oB.w = packh2(dB[6]*rB*wv[6] + bv[6], dB[7]*rB*wv[7] + bv[7]);
    *(uint4*)(out + (size_t)row*C_ + lane*8) = oA;
    *(uint4*)(out + (size_t)(row+1)*C_ + lane*8) = oB;
}

// ---------------------------------------------------------------------------
// fp16 tensor-core GEMM, cp.async 2-stage double buffer + ldmatrix, BK=64.
// ---------------------------------------------------------------------------
#define HSTRW 36
#define HTILE (128*HSTRW)
#define GSMEM (2*2*HTILE*4)           // 73728 B

template <int PAD, int OUTH>
__global__ __launch_bounds__(256, 2) void gemm_h(
    const __half* __restrict__ X, const __half* __restrict__ W,
    const float* __restrict__ bias, const float* __restrict__ res,
    void* __restrict__ Yv, int M, int Nout, int K, int act)
{
    extern __shared__ u32 hsm[];
    int tid  = threadIdx.x;
    int warp = tid >> 5, lane = tid & 31;
    int g = lane >> 2, t = lane & 3;
    int wm0 = (warp >> 2) * 64;
    int wn0 = (warp & 3) * 32;
    int m0 = blockIdx.y * 128, n0 = blockIdx.x * 128;
    u32 sb = smem_u32(hsm);

    int lr8  = lane & 7;
    int lrow = lr8 + ((lane >> 3) & 1) * 8;
    int lkb  = (lane >> 4) & 1;
    u32 aoff = (u32)((wm0 + lrow)*HSTRW + lkb*4) * 4u;
    u32 boff = (u32)((wn0 + ((lane >> 4) & 1)*8 + lr8)*HSTRW
                     + ((lane >> 3) & 1)*4) * 4u;

    auto issue_tile = [&](int s, int k0) {
        #pragma unroll
        for (int i = 0; i < 4; i++) {
            int idx = tid + (i << 8);
            int r  = idx >> 3;
            int c8 = (idx & 7) << 3;
            u32 dX = sb + (u32)((s*2*HTILE) + r*HSTRW + (c8 >> 1))*4u;
            const __half* gX = X + (size_t)(m0+r)*K + k0 + c8;
            asm volatile("cp.async.ca.shared.global [%0], [%1], 16;"
                         :: "r"(dX), "l"(gX));
            u32 dW = sb + (u32)((s*2*HTILE) + HTILE + r*HSTRW + (c8 >> 1))*4u;
            const __half* gW = W + (size_t)(n0+r)*K + k0 + c8;
            if (PAD) {
                int vld = (n0 + r < Nout) ? 16 : 0;
                asm volatile("cp.async.ca.shared.global [%0], [%1], 16, %2;"
                             :: "r"(dW), "l"(gW), "r"(vld));
            } else {
                asm volatile("cp.async.ca.shared.global [%0], [%1], 16;"
                             :: "r"(dW), "l"(gW));
            }
        }
    };

    float acc[4][4][4];
    #pragma unroll
    for (int mt = 0; mt < 4; mt++)
        #pragma unroll
        for (int nt = 0; nt < 4; nt++)
            #pragma unroll
            for (int c = 0; c < 4; c++) acc[mt][nt][c] = 0.f;

    issue_tile(0, 0);
    asm volatile("cp.async.commit_group;" ::: "memory");
    issue_tile(1, 64);
    asm volatile("cp.async.commit_group;" ::: "memory");

    int nk = K >> 6;
    for (int it = 0; it < nk; it++) {
        asm volatile("cp.async.wait_group 1;" ::: "memory");
        __syncthreads();

        u32 sbX = sb + (u32)((it & 1)*2*HTILE)*4u;
        u32 sbW = sbX + (u32)HTILE*4u;
        #pragma unroll
        for (int ks = 0; ks < 4; ks++) {
            u32 a[4][4];
            #pragma unroll
            for (int mt = 0; mt < 4; mt++)
                ldsm4(a[mt][0], a[mt][1], a[mt][2], a[mt][3],
                      sbX + aoff + (u32)(mt*16*HSTRW + ks*8)*4u);
            u32 bb[4][2];
            #pragma unroll
            for (int p = 0; p < 2; p++)
                ldsm4(bb[2*p][0], bb[2*p][1], bb[2*p+1][0], bb[2*p+1][1],
                      sbW + boff + (u32)(p*16*HSTRW + ks*8)*4u);
            #pragma unroll
            for (int mt = 0; mt < 4; mt++)
                #pragma unroll
                for (int nt = 0; nt < 4; nt++)
                    mma_f16(acc[mt][nt], a[mt], bb[nt]);
        }
        __syncthreads();

        int k2 = (it + 2) << 6;
        if (k2 < K) issue_tile(it & 1, k2);
        asm volatile("cp.async.commit_group;" ::: "memory");
    }

    float* Yf = (float*)Yv;
    __half* Yh = (__half*)Yv;
    #pragma unroll
    for (int mt = 0; mt < 4; mt++) {
        #pragma unroll
        for (int nt = 0; nt < 4; nt++) {
            int n = n0 + wn0 + nt*8 + 2*t;
            if (PAD && n >= Nout) continue;
            #pragma unroll
            for (int h2 = 0; h2 < 2; h2++) {
                int m = m0 + wm0 + mt*16 + g + h2*8;
                float v0 = acc[mt][nt][h2*2 + 0];
                float v1 = acc[mt][nt][h2*2 + 1];
                if (bias) { v0 += bias[n]; v1 += bias[n+1]; }
                if (act)  { v0 *= normcdff(v0); v1 *= normcdff(v1); }
                if (res)  { v0 += res[(size_t)m*Nout + n];
                            v1 += res[(size_t)m*Nout + n + 1]; }
                if (OUTH) {
                    __half2 hv = __floats2half2_rn(v0, v1);
                    *(__half2*)(Yh + (size_t)m*Nout + n) = hv;
                } else {
                    *(float2*)(Yf + (size_t)m*Nout + n) = make_float2(v0, v1);
                }
            }
        }
    }
}

// ---------------------------------------------------------------------------
// Flash attention v5: all-fp16 MMA + ldmatrix, double-buffered K/V,
// ONE barrier per chunk, base-2 online softmax.
// ---------------------------------------------------------------------------
#define FQT  128
#define FKC  64
#define QSTRW 20
#define VSTRW 36
#define QWORDS (FQT*QSTRW)
#define KVWORDS (FKC*QSTRW + 32*VSTRW)
#define FSMEM ((QWORDS + 2*KVWORDS)*4)  // 29696 B

__global__ __launch_bounds__(256, 2) void flash_h(
    const __half* __restrict__ qkvh, __half* __restrict__ out)
{
    extern __shared__ u32 fsm[];
    u32* q_s = fsm;
    u32* kvb = fsm + QWORDS;

    int tid  = threadIdx.x;
    int warp = tid >> 5, lane = tid & 31;
    int g = lane >> 2, t = lane & 3;
    int b = blockIdx.z, h = blockIdx.y;
    int q0 = blockIdx.x * FQT;
    const __half* qb = qkvh + (size_t)b*N_*768 + h*32;
    const __half2 qsc2 = __half2half2(__float2half_rn(0.25506704f));

    u32 sq = smem_u32(q_s);
    u32 skv = smem_u32(kvb);

    int lr8  = lane & 7;
    int lrow = lr8 + ((lane >> 3) & 1) * 8;
    int lkb  = (lane >> 4) & 1;
    u32 qoff = (u32)(lrow*QSTRW + lkb*4) * 4u;
    u32 koff = (u32)((((lane >> 4) & 1)*8 + lr8)*QSTRW
                     + ((lane >> 3) & 1)*4) * 4u;
    u32 voff = (u32)((((lane >> 4) & 1)*8 + lr8)*VSTRW
                     + ((lane >> 3) & 1)*4) * 4u;

    #pragma unroll
    for (int i = 0; i < 2; i++) {
        int idx = tid + (i << 8);
        int r  = idx >> 2;
        int w4 = (idx & 3) << 2;
        uint4 v = *(const uint4*)(qb + (size_t)(q0+r)*768 + w4*2);
        __half2* hv = (__half2*)&v;
        hv[0] = __hmul2(hv[0], qsc2);
        hv[1] = __hmul2(hv[1], qsc2);
        hv[2] = __hmul2(hv[2], qsc2);
        hv[3] = __hmul2(hv[3], qsc2);
        q_s[r*QSTRW + w4 + 0] = v.x;
        q_s[r*QSTRW + w4 + 1] = v.y;
        q_s[r*QSTRW + w4 + 2] = v.z;
        q_s[r*QSTRW + w4 + 3] = v.w;
    }

    int row0 = warp * 16;
    float oa[4][4];
    #pragma unroll
    for (int nt = 0; nt < 4; nt++)
        #pragma unroll
        for (int c = 0; c < 4; c++) oa[nt][c] = 0.f;
    float mr0 = -1e30f, mr1 = -1e30f, lr0 = 0.f, lr1 = 0.f;

    int rK = tid >> 2, w4K = (tid & 3) << 2;
    int keyV = tid >> 2, dh0 = (tid & 3) << 3;

    uint4 kf = *(const uint4*)(qb + (size_t)rK*768 + 256 + w4K*2);
    uint4 vf = *(const uint4*)(qb + (size_t)keyV*768 + 512 + dh0);

    for (int ic = 0; ic < N_/FKC; ic++) {
        u32* k_s = kvb + (ic & 1)*KVWORDS;
        u32* v_s = k_s + FKC*QSTRW;
        __half* v_sh = (__half*)v_s;
        u32 skc = skv + (u32)((ic & 1)*KVWORDS)*4u;
        u32 svc = skc + (u32)(FKC*QSTRW)*4u;

        k_s[rK*QSTRW + w4K + 0] = kf.x;
        k_s[rK*QSTRW + w4K + 1] = kf.y;
        k_s[rK*QSTRW + w4K + 2] = kf.z;
        k_s[rK*QSTRW + w4K + 3] = kf.w;
        {
            __half* hv = (__half*)&vf;
            #pragma unroll
            for (int j = 0; j < 8; j++)
                v_sh[(dh0 + j)*(2*VSTRW) + keyV] = hv[j];
        }

        int ktn = (ic + 1) * FKC;
        if (ktn < N_) {
            kf = *(const uint4*)(qb + (size_t)(ktn+rK)*768 + 256 + w4K*2);
            vf = *(const uint4*)(qb + (size_t)(ktn+keyV)*768 + 512 + dh0);
        }
        __syncthreads();

        float s[8][4];
        #pragma unroll
        for (int nt = 0; nt < 8; nt++)
            #pragma unroll
            for (int c = 0; c < 4; c++) s[nt][c] = 0.f;

        #pragma unroll
        for (int ks = 0; ks < 2; ks++) {
            u32 a[4];
            ldsm4(a[0], a[1], a[2], a[3],
                  sq + qoff + (u32)(row0*QSTRW + ks*8)*4u);
            u32 bb[8][2];
            #pragma unroll
            for (int p = 0; p < 4; p++)
                ldsm4(bb[2*p][0], bb[2*p][1], bb[2*p+1][0], bb[2*p+1][1],
                      skc + koff + (u32)(p*16*QSTRW + ks*8)*4u);
            #pragma unroll
            for (int nt = 0; nt < 8; nt++)
                mma_f16(s[nt], a, bb[nt]);
        }

        u32 pl[8], ph[8];
        {
            float m0 = -1e30f, m1 = -1e30f;
            #pragma unroll
            for (int nt = 0; nt < 8; nt++) {
                m0 = fmaxf(m0, fmaxf(s[nt][0], s[nt][1]));
                m1 = fmaxf(m1, fmaxf(s[nt][2], s[nt][3]));
            }
            #pragma unroll
            for (int o = 1; o <= 2; o <<= 1) {
                m0 = fmaxf(m0, __shfl_xor_sync(0xffffffffu, m0, o));
                m1 = fmaxf(m1, __shfl_xor_sync(0xffffffffu, m1, o));
            }
            float mn0 = fmaxf(mr0, m0);
            float mn1 = fmaxf(mr1, m1);
            float sf0 = ex2f(mr0 - mn0);
            float sf1 = ex2f(mr1 - mn1);
            mr0 = mn0; mr1 = mn1;
            float ls0 = 0.f, ls1 = 0.f;
            #pragma unroll
            for (int nt = 0; nt < 8; nt++) {
                float e0 = ex2f(s[nt][0] - mn0);
                float e1 = ex2f(s[nt][1] - mn0);
                float e2 = ex2f(s[nt][2] - mn1);
                float e3 = ex2f(s[nt][3] - mn1);
                ls0 += e0 + e1;  ls1 += e2 + e3;
                pl[nt] = packh2(e0, e1);
                ph[nt] = packh2(e2, e3);
            }
            #pragma unroll
            for (int o = 1; o <= 2; o <<= 1) {
                ls0 += __shfl_xor_sync(0xffffffffu, ls0, o);
                ls1 += __shfl_xor_sync(0xffffffffu, ls1, o);
            }
            lr0 = lr0*sf0 + ls0;
            lr1 = lr1*sf1 + ls1;
            #pragma unroll
            for (int nt = 0; nt < 4; nt++) {
                oa[nt][0] *= sf0;  oa[nt][1] *= sf0;
                oa[nt][2] *= sf1;  oa[nt][3] *= sf1;
            }
        }

        #pragma unroll
        for (int j = 0; j < 4; j++) {
            u32 a[4];
            a[0] = pl[2*j];
            a[1] = ph[2*j];
            a[2] = pl[2*j+1];
            a[3] = ph[2*j+1];
            u32 bb[4][2];
            #pragma unroll
            for (int p = 0; p < 2; p++)
                ldsm4(bb[2*p][0], bb[2*p][1], bb[2*p+1][0], bb[2*p+1][1],
                      svc + voff + (u32)(p*16*VSTRW + j*8)*4u);
            #pragma unroll
            for (int nt = 0; nt < 4; nt++)
                mma_f16(oa[nt], a, bb[nt]);
        }
    }

    float i0 = 1.f / lr0;
    float i1 = 1.f / lr1;
    int r = q0 + row0 + g;
    #pragma unroll
    for (int nt = 0; nt < 4; nt++) {
        int col = h*32 + nt*8 + 2*t;
        *(__half2*)(out + ((size_t)b*N_ + r)*C_ + col) =
            __floats2half2_rn(oa[nt][0]*i0, oa[nt][1]*i0);
        *(__half2*)(out + ((size_t)b*N_ + r + 8)*C_ + col) =
            __floats2half2_rn(oa[nt][2]*i1, oa[nt][3]*i1);
    }
}

// ---------------------------------------------------------------------------
// Deformable gather: one warp per (b, n, head); V-table fp16, output fp16.
// ---------------------------------------------------------------------------
__global__ __launch_bounds__(128) void deform_kernel(
    const float* __restrict__ ref, const float* __restrict__ offaw,
    const __half* __restrict__ vp, __half* __restrict__ out)
{
    int u = (blockIdx.x << 2) + (threadIdx.x >> 5);
    int lane = threadIdx.x & 31;
    int h  = u & 7;
    int bn = u >> 3;
    int b  = bn >> 10;

    float rx = ref[(size_t)bn*2 + 0]*32.f - 0.5f;
    float ry = ref[(size_t)bn*2 + 1]*32.f - 0.5f;
    const float* offp = offaw + (size_t)bn*96 + h*8;
    const float* awp  = offaw + (size_t)bn*96 + 64 + h*4;

    float a0 = awp[0], a1 = awp[1], a2 = awp[2], a3 = awp[3];
    float mx = fmaxf(fmaxf(a0,a1), fmaxf(a2,a3));
    float e0 = __expf(a0-mx), e1 = __expf(a1-mx), e2 = __expf(a2-mx), e3 = __expf(a3-mx);
    float inv = 1.f/(e0+e1+e2+e3);
    float aw4[4] = {e0*inv, e1*inv, e2*inv, e3*inv};

    const __half* vb = vp + (size_t)b*N_*C_ + h*32 + lane;
    float acc = 0.f;
    #pragma unroll
    for (int p = 0; p < 4; p++) {
        float gx = rx + offp[p*2+0];
        float gy = ry + offp[p*2+1];
        float x0f = floorf(gx), y0f = floorf(gy);
        float lx = gx - x0f, ly = gy - y0f;
        int x0 = (int)x0f, y0 = (int)y0f;
        float s = 0.f;
        #pragma unroll
        for (int cy = 0; cy < 2; cy++) {
            int yi = y0 + cy;
            float wy = cy ? ly : (1.f - ly);
            bool vy = (yi >= 0) && (yi < 32);
            int yc = min(max(yi, 0), 31);
            #pragma unroll
            for (int cx = 0; cx < 2; cx++) {
                int xi = x0 + cx;
                float wx = cx ? lx : (1.f - lx);
                bool vx = (xi >= 0) && (xi < 32);
                int xc = min(max(xi, 0), 31);
                float val = (vx && vy)
                    ? __half2float(vb[(size_t)(yc*32 + xc)*C_]) : 0.f;
                s = fmaf(val, wx*wy, s);
            }
        }
        acc = fmaf(aw4[p], s, acc);
    }
    out[(size_t)bn*C_ + h*32 + lane] = __float2half_rn(acc);
}

// ---------------------------------------------------------------------------
// Launch
// ---------------------------------------------------------------------------
extern "C" void kernel_launch(void* const* d_in, const int* in_sizes, int n_in,
                              void* d_out, int out_size)
{
    const float* x       = (const float*)d_in[0];
    const float* ref     = (const float*)d_in[1];
    const float* value   = (const float*)d_in[2];
    const float* ln1w    = (const float*)d_in[3];
    const float* ln1b    = (const float*)d_in[4];
    const float* ln2w    = (const float*)d_in[5];
    const float* ln2b    = (const float*)d_in[6];
    const float* ln3w    = (const float*)d_in[7];
    const float* ln3b    = (const float*)d_in[8];
    const float* qkv_w   = (const float*)d_in[9];
    const float* proj_w  = (const float*)d_in[10];
    const float* proj_b  = (const float*)d_in[11];
    const float* off_w   = (const float*)d_in[12];
    const float* off_b   = (const float*)d_in[13];
    const float* aw_w    = (const float*)d_in[14];
    const float* aw_b    = (const float*)d_in[15];
    const float* vproj_w = (const float*)d_in[16];
    const float* vproj_b = (const float*)d_in[17];
    const float* oproj_w = (const float*)d_in[18];
    const float* oproj_b = (const float*)d_in[19];
    const float* fc1_w   = (const float*)d_in[20];
    const float* fc1_b   = (const float*)d_in[21];
    const float* fc2_w   = (const float*)d_in[22];
    const float* fc2_b   = (const float*)d_in[23];
    float* out = (float*)d_out;

    float  *x2, *offaw, *oab;
    __half *vph, *qkvh, *yh, *tmph, *h1h, *wh, *valh;
    cudaGetSymbolAddress((void**)&x2,    g_x2);
    cudaGetSymbolAddress((void**)&offaw, g_offaw);
    cudaGetSymbolAddress((void**)&oab,   g_oab);
    cudaGetSymbolAddress((void**)&vph,   g_vph);
    cudaGetSymbolAddress((void**)&qkvh,  g_qkvh);
    cudaGetSymbolAddress((void**)&yh,    g_yh);
    cudaGetSymbolAddress((void**)&tmph,  g_tmph);
    cudaGetSymbolAddress((void**)&h1h,   g_h1h);
    cudaGetSymbolAddress((void**)&wh,    g_wh);
    cudaGetSymbolAddress((void**)&valh,  g_valh);

    cudaFuncSetAttribute(flash_h,
        cudaFuncAttributeMaxDynamicSharedMemorySize, FSMEM);
    cudaFuncSetAttribute(gemm_h<0,0>,
        cudaFuncAttributeMaxDynamicSharedMemorySize, GSMEM);
    cudaFuncSetAttribute(gemm_h<1,0>,
        cudaFuncAttributeMaxDynamicSharedMemorySize, GSMEM);
    cudaFuncSetAttribute(gemm_h<0,1>,
        cudaFuncAttributeMaxDynamicSharedMemorySize, GSMEM);

    const __half* wq  = wh + WOFF_QKV;
    const __half* wp  = wh + WOFF_PROJ;
    const __half* woa = wh + WOFF_OFF;
    const __half* wv  = wh + WOFF_VPROJ;
    const __half* wop = wh + WOFF_OPROJ;
    const __half* w1  = wh + WOFF_FC1;
    const __half* w2  = wh + WOFF_FC2;

    // ---- fork side stream: weight prep + vproj chain ----
    cudaEventRecord(g_ss.evFork, 0);
    cudaStreamWaitEvent(g_ss.s1, g_ss.evFork, 0);

    round_weights_h<<<(WTOT/4 + 255)/256, 256, 0, g_ss.s1>>>(
        qkv_w, proj_w, off_w, aw_w, vproj_w, oproj_w, fc1_w, fc2_w, wh);
    concat_bias<<<1, 96, 0, g_ss.s1>>>(off_b, aw_b, oab);
    cudaEventRecord(g_ss.evW, g_ss.s1);

    round_buf_h<<<(M_*C_/4 + 255)/256, 256, 0, g_ss.s1>>>(value, valh, M_*C_/4);
    gemm_h<0,1><<<dim3(2,128), 256, GSMEM, g_ss.s1>>>(
        valh, wv, vproj_b, nullptr, vph, M_, 256, 256, 0);
    cudaEventRecord(g_ss.evV, g_ss.s1);

    // ---- main chain ----
    // x1 = x + attn(ln1(x))
    ln_kernel<<<M_/16, 256>>>(x, ln1w, ln1b, yh);
    cudaStreamWaitEvent(0, g_ss.evW, 0);   // weights + oab ready
    gemm_h<0,1><<<dim3(6,128), 256, GSMEM>>>(yh, wq, nullptr, nullptr, qkvh, M_, 768, 256, 0);
    flash_h<<<dim3(N_/FQT, NH_, B_), 256, FSMEM>>>(qkvh, tmph);
    gemm_h<0,0><<<dim3(2,128), 256, GSMEM>>>(tmph, wp, proj_b, x, x2, M_, 256, 256, 0);

    // x2 = x1 + deform(ln2(x1))
    ln_kernel<<<M_/16, 256>>>(x2, ln2w, ln2b, yh);
    gemm_h<1,0><<<dim3(1,128), 256, GSMEM>>>(yh, woa, oab, nullptr, offaw, M_, 96, 256, 0);
    cudaStreamWaitEvent(0, g_ss.evV, 0);   // vph ready
    deform_kernel<<<32768, 128>>>(ref, offaw, vph, tmph);
    gemm_h<0,0><<<dim3(2,128), 256, GSMEM>>>(tmph, wop, oproj_b, x2, x2, M_, 256, 256, 0);

    // out = x2 + fc2(gelu(fc1(ln3(x2))))
    ln_kernel<<<M_/16, 256>>>(x2, ln3w, ln3b, yh);
    gemm_h<0,1><<<dim3(8,128), 256, GSMEM>>>(yh, w1, fc1_b, nullptr, h1h, M_, 1024, 256, 1);
    gemm_h<0,0><<<dim3(2,128), 256, GSMEM>>>(h1h, w2, fc2_b, x2, out, M_, 256, 1024, 0);
}